// round 2
// baseline (speedup 1.0000x reference)
#include <cuda_runtime.h>
#include <cuda_bf16.h>
#include <math.h>

// ---------------- constants ----------------
#define Bn 128
// stage sizes
#define N1  8388608.0   // 128*256*256 per channel (conv1/bn1, s1, s2)
#define N2  524288.0    // 128*64*64
#define N3  131072.0    // 128*32*32
#define N4  32768.0     // 128*16*16
#define N5  32768.0

// bn stat offsets
#define S1CH 0   // 4 ch
#define SS1  8   // 1 ch
#define SS2  12  // 4 ch
#define S2CH 16  // 8 ch
#define S3   24  // 16 ch
#define S4   40  // 32 ch
#define S5   72  // 16 ch

// ---------------- scratch ----------------
__device__ float g_h1[33554432];   // (128,4,256,256) conv1 raw
__device__ float g_xg[33554432];   // gam x*att
__device__ float g_s1[8388608];    // (128,1,256,256)
__device__ float g_s2[33554432];   // (128,4,256,256)
__device__ float g_p1[8388608];    // (128,4,128,128)
__device__ float g_r2[4194304];    // (128,8,64,64)
__device__ float g_p2[1048576];    // (128,8,32,32)
__device__ float g_r3[2097152];    // (128,16,32,32)
__device__ float g_p3[524288];     // (128,16,16,16)
__device__ float g_r4[1048576];    // (128,32,16,16)
__device__ float g_r5[524288];     // (128,16,16,16)
__device__ float g_tok[524288];    // (128,256,16)
__device__ double g_sumA[128];
__device__ double g_sqA[128];

// ---------------- helpers ----------------
__device__ __forceinline__ float wred(float v){
    #pragma unroll
    for (int o=16;o>0;o>>=1) v += __shfl_down_sync(0xffffffffu, v, o);
    return v;
}
__device__ __forceinline__ void bn_scale(int off, double N, float& sc, float& sh){
    double m = g_sumA[off]/N;
    double v = g_sqA[off]/N - m*m;
    double s = 1.0/sqrt(v+1e-5);
    sc = (float)s; sh = (float)(-m*s);
}
__device__ __forceinline__ float sigm(float x){ return 1.f/(1.f+expf(-x)); }

__global__ void k_zero(){
    int t = threadIdx.x;
    if (t < 128){ g_sumA[t]=0.0; g_sqA[t]=0.0; }
}

// ---------------- conv1: 1->4, 5x5, s2, p2 + bn stats ----------------
__global__ void k_conv1(const float* __restrict__ x, const float* __restrict__ w,
                        const float* __restrict__ bias, float* __restrict__ out){
    __shared__ float t[35][36];
    __shared__ float ws[100];
    __shared__ float wb[4];
    __shared__ float ssum[4], ssq[4];
    int tid = threadIdx.y*16 + threadIdx.x;
    int b = blockIdx.z;
    if (tid < 100) ws[tid] = w[tid];
    if (tid < 4){ wb[tid] = bias[tid]; ssum[tid]=0.f; ssq[tid]=0.f; }
    int iy0 = blockIdx.y*32 - 2;
    int ix0 = blockIdx.x*32 - 2;
    const float* xb = x + (size_t)b*262144;
    for (int i = tid; i < 35*35; i += 256){
        int r = i/35, c = i%35;
        int iy = iy0 + r, ix = ix0 + c;
        float v = 0.f;
        if (iy>=0 && iy<512 && ix>=0 && ix<512) v = xb[iy*512+ix];
        t[r][c] = v;
    }
    __syncthreads();
    int ty=threadIdx.y, tx=threadIdx.x;
    float acc[4] = {wb[0],wb[1],wb[2],wb[3]};
    #pragma unroll
    for (int ky=0; ky<5; ky++)
        #pragma unroll
        for (int kx=0; kx<5; kx++){
            float v = t[2*ty+ky][2*tx+kx];
            #pragma unroll
            for (int c=0;c<4;c++) acc[c] += v*ws[c*25+ky*5+kx];
        }
    int oy = blockIdx.y*16+ty, ox = blockIdx.x*16+tx;
    size_t base = (size_t)b*262144 + (size_t)oy*256 + ox;
    #pragma unroll
    for (int c=0;c<4;c++) out[base + (size_t)c*65536] = acc[c];
    #pragma unroll
    for (int c=0;c<4;c++){
        float s = wred(acc[c]);
        float q = wred(acc[c]*acc[c]);
        if ((tid&31)==0){ atomicAdd(&ssum[c], s); atomicAdd(&ssq[c], q); }
    }
    __syncthreads();
    if (tid < 4){
        atomicAdd(&g_sumA[S1CH+tid], (double)ssum[tid]);
        atomicAdd(&g_sqA[S1CH+tid],  (double)ssq[tid]);
    }
}

// ---------------- gam channel attention: xg = relu(bn(h1)) * att ----------------
__global__ void k_xg(const float* __restrict__ h1, const float* __restrict__ caw1,
                     const float* __restrict__ cab1, const float* __restrict__ caw2,
                     const float* __restrict__ cab2, float* __restrict__ xg){
    __shared__ float sc[4], sh[4];
    int tid = threadIdx.x;
    if (tid < 4) bn_scale(S1CH+tid, N1, sc[tid], sh[tid]);
    __syncthreads();
    int idx = blockIdx.x*256 + tid;   // exact: 8388608 threads
    int b = idx >> 16; int p = idx & 65535;
    const float* hp = h1 + (size_t)b*262144 + p;
    float a[4];
    #pragma unroll
    for (int c=0;c<4;c++){ float v = hp[(size_t)c*65536]*sc[c]+sh[c]; a[c] = v>0.f?v:0.f; }
    float hid = cab1[0];
    #pragma unroll
    for (int c=0;c<4;c++) hid += a[c]*caw1[c];
    hid = hid>0.f?hid:0.f;
    float* op = xg + (size_t)b*262144 + p;
    #pragma unroll
    for (int c=0;c<4;c++) op[(size_t)c*65536] = a[c]*(hid*caw2[c]+cab2[c]);
}

// ---------------- s1 = conv7x7(edgepad(xg), sw1): 4->1 + stats ----------------
__global__ void k_s1(const float* __restrict__ xg, const float* __restrict__ w,
                     float* __restrict__ s1){
    __shared__ float t[4][22][22];
    __shared__ float ws[196];
    __shared__ float ssum, ssq;
    int tid = threadIdx.y*16+threadIdx.x;
    int b = blockIdx.z;
    if (tid<196) ws[tid]=w[tid];
    if (tid==0){ ssum=0.f; ssq=0.f; }
    int y0 = blockIdx.y*16-3, x0 = blockIdx.x*16-3;
    const float* xb = xg + (size_t)b*262144;
    for (int i=tid; i<4*484; i+=256){
        int c = i/484; int r = (i%484)/22; int cc = i%22;
        int sy = min(max(y0+r,0),255), sx = min(max(x0+cc,0),255);
        t[c][r][cc] = xb[(size_t)c*65536 + sy*256+sx];
    }
    __syncthreads();
    float acc = 0.f;
    #pragma unroll
    for (int c=0;c<4;c++)
        for (int ky=0;ky<7;ky++)
            #pragma unroll
            for (int kx=0;kx<7;kx++)
                acc += t[c][threadIdx.y+ky][threadIdx.x+kx]*ws[c*49+ky*7+kx];
    int oy = blockIdx.y*16+threadIdx.y, ox = blockIdx.x*16+threadIdx.x;
    s1[(size_t)b*65536 + oy*256+ox] = acc;
    float s = wred(acc), q = wred(acc*acc);
    if ((tid&31)==0){ atomicAdd(&ssum, s); atomicAdd(&ssq, q); }
    __syncthreads();
    if (tid==0){ atomicAdd(&g_sumA[SS1], (double)ssum); atomicAdd(&g_sqA[SS1], (double)ssq); }
}

// ---------------- s2 = conv7x7(edgepad(relu(bn(s1))), sw2): 1->4 + stats ----------------
__global__ void k_s2(const float* __restrict__ s1, const float* __restrict__ w,
                     float* __restrict__ s2){
    __shared__ float t[22][22];
    __shared__ float ws[196];
    __shared__ float sc1, sh1;
    __shared__ float ssum[4], ssq[4];
    int tid = threadIdx.y*16+threadIdx.x;
    int b = blockIdx.z;
    if (tid<196) ws[tid]=w[tid];
    if (tid==0) bn_scale(SS1, N1, sc1, sh1);
    if (tid<4){ ssum[tid]=0.f; ssq[tid]=0.f; }
    __syncthreads();
    int y0 = blockIdx.y*16-3, x0 = blockIdx.x*16-3;
    const float* sb = s1 + (size_t)b*65536;
    for (int i=tid; i<484; i+=256){
        int r = i/22, cc = i%22;
        int sy = min(max(y0+r,0),255), sx = min(max(x0+cc,0),255);
        float v = sb[sy*256+sx]*sc1+sh1;
        t[r][cc] = v>0.f?v:0.f;
    }
    __syncthreads();
    float acc[4] = {0.f,0.f,0.f,0.f};
    #pragma unroll
    for (int ky=0;ky<7;ky++)
        #pragma unroll
        for (int kx=0;kx<7;kx++){
            float v = t[threadIdx.y+ky][threadIdx.x+kx];
            #pragma unroll
            for (int c=0;c<4;c++) acc[c] += v*ws[c*49+ky*7+kx];
        }
    int oy = blockIdx.y*16+threadIdx.y, ox = blockIdx.x*16+threadIdx.x;
    size_t base = (size_t)b*262144 + (size_t)oy*256 + ox;
    #pragma unroll
    for (int c=0;c<4;c++) s2[base + (size_t)c*65536] = acc[c];
    #pragma unroll
    for (int c=0;c<4;c++){
        float s = wred(acc[c]), q = wred(acc[c]*acc[c]);
        if ((tid&31)==0){ atomicAdd(&ssum[c], s); atomicAdd(&ssq[c], q); }
    }
    __syncthreads();
    if (tid<4){
        atomicAdd(&g_sumA[SS2+tid], (double)ssum[tid]);
        atomicAdd(&g_sqA[SS2+tid],  (double)ssq[tid]);
    }
}

// ---------------- pool1 = maxpool2( xg * sigmoid(bn(s2)) ) ----------------
__global__ void k_pool1(const float* __restrict__ xg, const float* __restrict__ s2,
                        float* __restrict__ p1){
    __shared__ float sc[4], sh[4];
    int tid = threadIdx.x;
    if (tid<4) bn_scale(SS2+tid, N1, sc[tid], sh[tid]);
    __syncthreads();
    int idx = blockIdx.x*256 + tid;   // 8388608 exact
    int ox = idx & 127; int oy = (idx>>7)&127; int c = (idx>>14)&3; int b = idx>>16;
    size_t base = (size_t)b*262144 + (size_t)c*65536;
    float m = -1e30f;
    #pragma unroll
    for (int dy=0;dy<2;dy++)
        #pragma unroll
        for (int dx=0;dx<2;dx++){
            size_t o = base + (size_t)(2*oy+dy)*256 + (2*ox+dx);
            float sv = sigm(s2[o]*sc[c]+sh[c]);
            float v = xg[o]*sv;
            m = fmaxf(m, v);
        }
    p1[(size_t)b*65536 + (size_t)c*16384 + oy*128 + ox] = m;
}

// ---------------- conv2: 4->8, 3x3, s2, p1 + stats ----------------
__global__ void k_conv2(const float* __restrict__ in, const float* __restrict__ w,
                        const float* __restrict__ bias, float* __restrict__ out){
    __shared__ float t[4][33][33];
    __shared__ float ws[288];
    __shared__ float wb[8];
    __shared__ float ssum[8], ssq[8];
    int tid = threadIdx.y*16+threadIdx.x;
    int b = blockIdx.z;
    for (int i=tid;i<288;i+=256) ws[i]=w[i];   // FIXED: was if(tid<288) with 256 threads
    if (tid<8){ wb[tid]=bias[tid]; ssum[tid]=0.f; ssq[tid]=0.f; }
    int iy0 = blockIdx.y*32-1, ix0 = blockIdx.x*32-1;
    for (int i=tid; i<4*1089; i+=256){
        int c=i/1089; int r=(i%1089)/33; int cc=i%33;
        int iy=iy0+r, ix=ix0+cc;
        float v=0.f;
        if (iy>=0&&iy<128&&ix>=0&&ix<128)
            v = in[(size_t)b*65536 + (size_t)c*16384 + iy*128+ix];
        t[c][r][cc]=v;
    }
    __syncthreads();
    int ty=threadIdx.y, tx=threadIdx.x;
    float acc[8];
    #pragma unroll
    for (int oc=0;oc<8;oc++) acc[oc]=wb[oc];
    #pragma unroll
    for (int ci=0;ci<4;ci++)
        #pragma unroll
        for (int ky=0;ky<3;ky++)
            #pragma unroll
            for (int kx=0;kx<3;kx++){
                float v = t[ci][2*ty+ky][2*tx+kx];
                #pragma unroll
                for (int oc=0;oc<8;oc++) acc[oc]+=v*ws[oc*36+ci*9+ky*3+kx];
            }
    int oy = blockIdx.y*16+ty, ox = blockIdx.x*16+tx;
    #pragma unroll
    for (int oc=0;oc<8;oc++)
        out[(size_t)b*32768 + (size_t)oc*4096 + oy*64+ox] = acc[oc];
    #pragma unroll
    for (int oc=0;oc<8;oc++){
        float s=wred(acc[oc]), q=wred(acc[oc]*acc[oc]);
        if ((tid&31)==0){ atomicAdd(&ssum[oc],s); atomicAdd(&ssq[oc],q); }
    }
    __syncthreads();
    if (tid<8){
        atomicAdd(&g_sumA[S2CH+tid], (double)ssum[tid]);
        atomicAdd(&g_sqA[S2CH+tid],  (double)ssq[tid]);
    }
}

// ---------------- pool2 = maxpool2(relu(bn(r2))) ----------------
__global__ void k_pool2(const float* __restrict__ r2, float* __restrict__ p2){
    __shared__ float sc[8], sh[8];
    int tid=threadIdx.x;
    if (tid<8) bn_scale(S2CH+tid, N2, sc[tid], sh[tid]);
    __syncthreads();
    int idx = blockIdx.x*256+tid;   // 1048576 exact
    int ox=idx&31; int oy=(idx>>5)&31; int c=(idx>>10)&7; int b=idx>>13;
    size_t base = (size_t)b*32768 + (size_t)c*4096;
    float m=-1e30f;
    #pragma unroll
    for (int dy=0;dy<2;dy++)
        #pragma unroll
        for (int dx=0;dx<2;dx++){
            float v = r2[base + (size_t)(2*oy+dy)*64 + (2*ox+dx)]*sc[c]+sh[c];
            v = v>0.f?v:0.f;
            m = fmaxf(m,v);
        }
    p2[(size_t)b*8192 + (size_t)c*1024 + oy*32+ox] = m;
}

// ---------------- conv3: 8->16, 3x3, s1, p1 + stats ----------------
__global__ void k_conv3(const float* __restrict__ in, const float* __restrict__ w,
                        const float* __restrict__ bias, float* __restrict__ out){
    __shared__ float t[8][18][18];
    __shared__ float ws[1152];
    __shared__ float wb[16];
    __shared__ float ssum[16], ssq[16];
    int tid = threadIdx.y*16+threadIdx.x;
    int b = blockIdx.z;
    for (int i=tid;i<1152;i+=256) ws[i]=w[i];
    if (tid<16){ wb[tid]=bias[tid]; ssum[tid]=0.f; ssq[tid]=0.f; }
    int iy0 = blockIdx.y*16-1, ix0 = blockIdx.x*16-1;
    for (int i=tid;i<8*324;i+=256){
        int c=i/324; int r=(i%324)/18; int cc=i%18;
        int iy=iy0+r, ix=ix0+cc;
        float v=0.f;
        if (iy>=0&&iy<32&&ix>=0&&ix<32)
            v = in[(size_t)b*8192 + (size_t)c*1024 + iy*32+ix];
        t[c][r][cc]=v;
    }
    __syncthreads();
    int ty=threadIdx.y, tx=threadIdx.x;
    float acc[16];
    #pragma unroll
    for (int oc=0;oc<16;oc++) acc[oc]=wb[oc];
    #pragma unroll
    for (int ci=0;ci<8;ci++)
        #pragma unroll
        for (int ky=0;ky<3;ky++)
            #pragma unroll
            for (int kx=0;kx<3;kx++){
                float v=t[ci][ty+ky][tx+kx];
                #pragma unroll
                for (int oc=0;oc<16;oc++) acc[oc]+=v*ws[oc*72+ci*9+ky*3+kx];
            }
    int oy=blockIdx.y*16+ty, ox=blockIdx.x*16+tx;
    #pragma unroll
    for (int oc=0;oc<16;oc++)
        out[(size_t)b*16384 + (size_t)oc*1024 + oy*32+ox]=acc[oc];
    #pragma unroll
    for (int oc=0;oc<16;oc++){
        float s=wred(acc[oc]), q=wred(acc[oc]*acc[oc]);
        if ((tid&31)==0){ atomicAdd(&ssum[oc],s); atomicAdd(&ssq[oc],q); }
    }
    __syncthreads();
    if (tid<16){
        atomicAdd(&g_sumA[S3+tid], (double)ssum[tid]);
        atomicAdd(&g_sqA[S3+tid],  (double)ssq[tid]);
    }
}

// ---------------- pool3 = maxpool2(relu(bn(r3))) ----------------
__global__ void k_pool3(const float* __restrict__ r3, float* __restrict__ p3){
    __shared__ float sc[16], sh[16];
    int tid=threadIdx.x;
    if (tid<16) bn_scale(S3+tid, N3, sc[tid], sh[tid]);
    __syncthreads();
    int idx = blockIdx.x*256+tid;   // 524288 exact
    int ox=idx&15; int oy=(idx>>4)&15; int c=(idx>>8)&15; int b=idx>>12;
    size_t base=(size_t)b*16384 + (size_t)c*1024;
    float m=-1e30f;
    #pragma unroll
    for (int dy=0;dy<2;dy++)
        #pragma unroll
        for (int dx=0;dx<2;dx++){
            float v=r3[base + (size_t)(2*oy+dy)*32 + (2*ox+dx)]*sc[c]+sh[c];
            v=v>0.f?v:0.f;
            m=fmaxf(m,v);
        }
    p3[(size_t)b*4096 + (size_t)c*256 + oy*16+ox]=m;
}

// ---------------- conv4: 16->32, 3x3, s1, p1 + stats ----------------
__global__ void k_conv4(const float* __restrict__ in, const float* __restrict__ w,
                        const float* __restrict__ bias, float* __restrict__ out){
    __shared__ float t[16][18][18];
    __shared__ float ws[4608];
    __shared__ float wb[32];
    __shared__ float ssum[32], ssq[32];
    int tid = threadIdx.y*16+threadIdx.x;
    int b = blockIdx.x;
    for (int i=tid;i<4608;i+=256) ws[i]=w[i];
    if (tid<32){ wb[tid]=bias[tid]; ssum[tid]=0.f; ssq[tid]=0.f; }
    for (int i=tid;i<16*324;i+=256){
        int c=i/324; int r=(i%324)/18; int cc=i%18;
        int iy=r-1, ix=cc-1;
        float v=0.f;
        if (iy>=0&&iy<16&&ix>=0&&ix<16)
            v = in[(size_t)b*4096 + (size_t)c*256 + iy*16+ix];
        t[c][r][cc]=v;
    }
    __syncthreads();
    int ty=threadIdx.y, tx=threadIdx.x;
    float acc[32];
    #pragma unroll
    for (int oc=0;oc<32;oc++) acc[oc]=wb[oc];
    for (int ci=0;ci<16;ci++)
        #pragma unroll
        for (int ky=0;ky<3;ky++)
            #pragma unroll
            for (int kx=0;kx<3;kx++){
                float v=t[ci][ty+ky][tx+kx];
                #pragma unroll
                for (int oc=0;oc<32;oc++) acc[oc]+=v*ws[oc*144+ci*9+ky*3+kx];
            }
    #pragma unroll
    for (int oc=0;oc<32;oc++)
        out[(size_t)b*8192 + (size_t)oc*256 + ty*16+tx]=acc[oc];
    #pragma unroll
    for (int oc=0;oc<32;oc++){
        float s=wred(acc[oc]), q=wred(acc[oc]*acc[oc]);
        if ((tid&31)==0){ atomicAdd(&ssum[oc],s); atomicAdd(&ssq[oc],q); }
    }
    __syncthreads();
    if (tid<32){
        atomicAdd(&g_sumA[S4+tid], (double)ssum[tid]);
        atomicAdd(&g_sqA[S4+tid],  (double)ssq[tid]);
    }
}

// ---------------- conv5: 1x1, relu(bn(r4)) -> 16 + stats ----------------
__global__ void k_conv5(const float* __restrict__ r4, const float* __restrict__ w,
                        const float* __restrict__ bias, float* __restrict__ out){
    __shared__ float sc[32], sh[32];
    __shared__ float ws[512];
    __shared__ float wb[16];
    __shared__ float ssum[16], ssq[16];
    int tid=threadIdx.x;
    if (tid<32) bn_scale(S4+tid, N4, sc[tid], sh[tid]);
    for (int i=tid;i<512;i+=256) ws[i]=w[i];
    if (tid<16){ wb[tid]=bias[tid]; ssum[tid]=0.f; ssq[tid]=0.f; }
    __syncthreads();
    int idx = blockIdx.x*256+tid;   // 32768 exact
    int b = idx>>8; int p = idx&255;
    float a[32];
    #pragma unroll
    for (int ci=0;ci<32;ci++){
        float v = r4[(size_t)b*8192 + (size_t)ci*256 + p]*sc[ci]+sh[ci];
        a[ci]=v>0.f?v:0.f;
    }
    float accs[16];
    #pragma unroll
    for (int oc=0;oc<16;oc++){
        float acc=wb[oc];
        #pragma unroll
        for (int ci=0;ci<32;ci++) acc += a[ci]*ws[oc*32+ci];
        out[(size_t)b*4096 + (size_t)oc*256 + p]=acc;
        accs[oc]=acc;
    }
    #pragma unroll
    for (int oc=0;oc<16;oc++){
        float s=wred(accs[oc]), q=wred(accs[oc]*accs[oc]);
        if ((tid&31)==0){ atomicAdd(&ssum[oc],s); atomicAdd(&ssq[oc],q); }
    }
    __syncthreads();
    if (tid<16){
        atomicAdd(&g_sumA[S5+tid], (double)ssum[tid]);
        atomicAdd(&g_sqA[S5+tid],  (double)ssq[tid]);
    }
}

// ---------------- tok = relu(bn(r5)) transposed to (B,L,D) ----------------
__global__ void k_tok(const float* __restrict__ r5, float* __restrict__ tok){
    __shared__ float sc[16], sh[16];
    int tid=threadIdx.x;
    if (tid<16) bn_scale(S5+tid, N5, sc[tid], sh[tid]);
    __syncthreads();
    int idx = blockIdx.x*256+tid;   // 524288 exact
    int d = idx&15; int l=(idx>>4)&255; int b=idx>>12;
    float v = r5[(size_t)b*4096 + (size_t)d*256 + l]*sc[d]+sh[d];
    tok[idx] = v>0.f?v:0.f;
}

// ---------------- mamba layer (block per batch, everything in smem) ----------------
#define O_WIN 0
#define O_CW  1024
#define O_CB  1152
#define O_XP  1184
#define O_DTW 2240
#define O_DTB 2272
#define O_AE  2304
#define O_DD  2816
#define O_OW  2848
#define O_LNG 3360
#define O_LNB 3376
#define O_XI  3392
#define O_ZZ  11584
#define O_XC  19776
#define O_DL  27968
#define O_BM  36160
#define O_CM  40256
#define O_YY  44352
#define SM_FLOATS 52544

__global__ void k_mamba(float* __restrict__ tok,
    const float* __restrict__ lng, const float* __restrict__ lnb,
    const float* __restrict__ inw, const float* __restrict__ cw, const float* __restrict__ cb,
    const float* __restrict__ xpw, const float* __restrict__ dtw, const float* __restrict__ dtb,
    const float* __restrict__ alog, const float* __restrict__ dvec, const float* __restrict__ ow)
{
    extern __shared__ float sm[];
    int t = threadIdx.x; int b = blockIdx.x;
    for (int i=t;i<1024;i+=512) sm[O_WIN+i]=inw[i];
    for (int i=t;i<128;i+=512)  sm[O_CW+i]=cw[i];
    for (int i=t;i<1056;i+=512) sm[O_XP+i]=xpw[i];
    for (int i=t;i<512;i+=512){ sm[O_AE+i]=-expf(alog[i]); sm[O_OW+i]=ow[i]; }
    if (t<32){ sm[O_CB+t]=cb[t]; sm[O_DTW+t]=dtw[t]; sm[O_DTB+t]=dtb[t]; sm[O_DD+t]=dvec[t]; }
    if (t<16){ sm[O_LNG+t]=lng[t]; sm[O_LNB+t]=lnb[t]; }
    __syncthreads();

    // step 1: LN + in_proj
    if (t < 256){
        int l=t;
        float v[16];
        const float* tp = tok + ((size_t)b*4096 + (size_t)l*16);
        float mean=0.f;
        #pragma unroll
        for (int d=0;d<16;d++){ v[d]=tp[d]; mean+=v[d]; }
        mean *= 0.0625f;
        float var=0.f;
        #pragma unroll
        for (int d=0;d<16;d++){ float dd=v[d]-mean; var+=dd*dd; }
        var *= 0.0625f;
        float inv = rsqrtf(var+1e-5f);
        #pragma unroll
        for (int d=0;d<16;d++) v[d]=(v[d]-mean)*inv*sm[O_LNG+d]+sm[O_LNB+d];
        for (int j=0;j<64;j++){
            float a=0.f;
            #pragma unroll
            for (int d=0;d<16;d++) a += v[d]*sm[O_WIN+j*16+d];
            if (j<32) sm[O_XI+l*32+j]=a; else sm[O_ZZ+l*32+j-32]=a;
        }
    }
    __syncthreads();

    // step 2: depthwise causal conv + silu
    if (t < 256){
        int l=t;
        for (int d=0;d<32;d++){
            float a = sm[O_CB+d];
            #pragma unroll
            for (int k=0;k<4;k++){
                int ll=l-3+k;
                if (ll>=0) a += sm[O_CW+d*4+k]*sm[O_XI+ll*32+d];
            }
            sm[O_XC+l*32+d] = a/(1.f+expf(-a));
        }
    }
    __syncthreads();

    // step 3: x_proj (dt, B, C) + softplus(delta)
    if (t < 256){
        int l=t;
        float xcl[32];
        #pragma unroll
        for (int d=0;d<32;d++) xcl[d]=sm[O_XC+l*32+d];
        float dtv=0.f;
        #pragma unroll
        for (int d=0;d<32;d++) dtv += xcl[d]*sm[O_XP+d];
        for (int n=0;n<16;n++){
            float bb=0.f, cc=0.f;
            #pragma unroll
            for (int d=0;d<32;d++){
                bb += xcl[d]*sm[O_XP+(1+n)*32+d];
                cc += xcl[d]*sm[O_XP+(17+n)*32+d];
            }
            sm[O_BM+l*16+n]=bb; sm[O_CM+l*16+n]=cc;
        }
        for (int d=0;d<32;d++){
            float pre = dtv*sm[O_DTW+d]+sm[O_DTB+d];
            float sp = (pre>20.f)? pre : log1pf(expf(pre));
            sm[O_DL+l*32+d]=sp;
        }
    }
    __syncthreads();

    // step 4: selective scan, 512 chains (d,n)
    {
        int d = t>>4, n = t&15;
        float A  = sm[O_AE+d*16+n];
        float Dv = sm[O_DD+d];
        float h=0.f;
        for (int l=0;l<256;l++){
            float dl  = sm[O_DL+l*32+d];
            float xcv = sm[O_XC+l*32+d];
            float dA  = expf(dl*A);
            h = dA*h + dl*sm[O_BM+l*16+n]*xcv;
            float c = h*sm[O_CM+l*16+n];
            c += __shfl_xor_sync(0xffffffffu, c, 1);
            c += __shfl_xor_sync(0xffffffffu, c, 2);
            c += __shfl_xor_sync(0xffffffffu, c, 4);
            c += __shfl_xor_sync(0xffffffffu, c, 8);
            if (n==0) sm[O_YY+l*32+d] = c + xcv*Dv;
        }
    }
    __syncthreads();

    // step 5: gate + out_proj, residual add
    if (t < 256){
        int l=t;
        float yv[32];
        #pragma unroll
        for (int d=0;d<32;d++){
            float zv=sm[O_ZZ+l*32+d];
            yv[d]=sm[O_YY+l*32+d]*(zv/(1.f+expf(-zv)));
        }
        float* tp = tok + ((size_t)b*4096 + (size_t)l*16);
        #pragma unroll
        for (int j=0;j<16;j++){
            float a=0.f;
            #pragma unroll
            for (int d=0;d<32;d++) a += yv[d]*sm[O_OW+j*32+d];
            tp[j] += a;
        }
    }
}

// ---------------- head: mean-pool + linear + LN ----------------
__global__ void k_head(const float* __restrict__ tok, const float* __restrict__ pw,
                       const float* __restrict__ pb, const float* __restrict__ fg,
                       const float* __restrict__ fb, float* __restrict__ out){
    __shared__ float pooled[16];
    __shared__ float red[16];
    __shared__ float s_mean, s_inv;
    int t=threadIdx.x, b=blockIdx.x;
    if (t<16){
        float s=0.f;
        const float* tp = tok + (size_t)b*4096 + t;
        for (int l=0;l<256;l++) s += tp[l*16];
        pooled[t] = s*(1.f/256.f);
    }
    __syncthreads();
    float lg = pb[t];
    #pragma unroll
    for (int d=0;d<16;d++) lg += pooled[d]*pw[t*16+d];
    float s1v = wred(lg);
    float s2v = wred(lg*lg);
    int w = t>>5;
    if ((t&31)==0){ red[w]=s1v; red[8+w]=s2v; }
    __syncthreads();
    if (t==0){
        float a=0.f,q=0.f;
        for (int i=0;i<8;i++){a+=red[i]; q+=red[8+i];}
        float m=a*(1.f/256.f);
        float v=q*(1.f/256.f)-m*m;
        s_mean=m; s_inv=rsqrtf(v+1e-5f);
    }
    __syncthreads();
    out[b*256+t] = (lg-s_mean)*s_inv*fg[t]+fb[t];
}

// ---------------- launch ----------------
extern "C" void kernel_launch(void* const* d_in, const int* in_sizes, int n_in,
                              void* d_out, int out_size){
    const float* x    = (const float*)d_in[0];
    const float* c1w  = (const float*)d_in[1];
    const float* c1b  = (const float*)d_in[2];
    const float* caw1 = (const float*)d_in[3];
    const float* cab1 = (const float*)d_in[4];
    const float* caw2 = (const float*)d_in[5];
    const float* cab2 = (const float*)d_in[6];
    const float* sw1  = (const float*)d_in[7];
    const float* sw2  = (const float*)d_in[8];
    const float* c2w  = (const float*)d_in[9];
    const float* c2b  = (const float*)d_in[10];
    const float* c3w  = (const float*)d_in[11];
    const float* c3b  = (const float*)d_in[12];
    const float* c4w  = (const float*)d_in[13];
    const float* c4b  = (const float*)d_in[14];
    const float* c5w  = (const float*)d_in[15];
    const float* c5b  = (const float*)d_in[16];
    const float* mlng = (const float*)d_in[17];
    const float* mlnb = (const float*)d_in[18];
    const float* minw = (const float*)d_in[19];
    const float* mcw  = (const float*)d_in[20];
    const float* mcb  = (const float*)d_in[21];
    const float* mxp  = (const float*)d_in[22];
    const float* mdtw = (const float*)d_in[23];
    const float* mdtb = (const float*)d_in[24];
    const float* mal  = (const float*)d_in[25];
    const float* mD   = (const float*)d_in[26];
    const float* mow  = (const float*)d_in[27];
    const float* pw   = (const float*)d_in[28];
    const float* pb   = (const float*)d_in[29];
    const float* fg   = (const float*)d_in[30];
    const float* fb   = (const float*)d_in[31];
    float* out = (float*)d_out;

    float *h1, *xg, *s1, *s2, *p1, *r2, *p2, *r3, *p3, *r4, *r5, *tok;
    cudaGetSymbolAddress((void**)&h1, g_h1);
    cudaGetSymbolAddress((void**)&xg, g_xg);
    cudaGetSymbolAddress((void**)&s1, g_s1);
    cudaGetSymbolAddress((void**)&s2, g_s2);
    cudaGetSymbolAddress((void**)&p1, g_p1);
    cudaGetSymbolAddress((void**)&r2, g_r2);
    cudaGetSymbolAddress((void**)&p2, g_p2);
    cudaGetSymbolAddress((void**)&r3, g_r3);
    cudaGetSymbolAddress((void**)&p3, g_p3);
    cudaGetSymbolAddress((void**)&r4, g_r4);
    cudaGetSymbolAddress((void**)&r5, g_r5);
    cudaGetSymbolAddress((void**)&tok, g_tok);

    size_t smem_mamba = SM_FLOATS * sizeof(float);
    cudaFuncSetAttribute(k_mamba, cudaFuncAttributeMaxDynamicSharedMemorySize, (int)smem_mamba);

    k_zero<<<1,128>>>();
    k_conv1<<<dim3(16,16,128), dim3(16,16)>>>(x, c1w, c1b, h1);
    k_xg<<<32768,256>>>(h1, caw1, cab1, caw2, cab2, xg);
    k_s1<<<dim3(16,16,128), dim3(16,16)>>>(xg, sw1, s1);
    k_s2<<<dim3(16,16,128), dim3(16,16)>>>(s1, sw2, s2);
    k_pool1<<<32768,256>>>(xg, s2, p1);
    k_conv2<<<dim3(4,4,128), dim3(16,16)>>>(p1, c2w, c2b, r2);
    k_pool2<<<4096,256>>>(r2, p2);
    k_conv3<<<dim3(2,2,128), dim3(16,16)>>>(p2, c3w, c3b, r3);
    k_pool3<<<2048,256>>>(r3, p3);
    k_conv4<<<128, dim3(16,16)>>>(p3, c4w, c4b, r4);
    k_conv5<<<128,256>>>(r4, c5w, c5b, r5);
    k_tok<<<2048,256>>>(r5, tok);
    for (int layer=0; layer<2; layer++){
        k_mamba<<<128,512,smem_mamba>>>(tok,
            mlng+layer*16, mlnb+layer*16, minw+layer*1024,
            mcw+layer*128, mcb+layer*32, mxp+layer*1056,
            mdtw+layer*32, mdtb+layer*32, mal+layer*512,
            mD+layer*32, mow+layer*512);
    }
    k_head<<<128,256>>>(tok, pw, pb, fg, fb, out);
}

// round 3
// speedup vs baseline: 1.4111x; 1.4111x over previous
#include <cuda_runtime.h>
#include <cuda_bf16.h>
#include <math.h>

// ---------------- constants ----------------
#define N1  8388608.0   // 128*256*256 per channel
#define N2  524288.0    // 128*64*64
#define N3  131072.0    // 128*32*32
#define N4  32768.0     // 128*16*16
#define N5  32768.0

// bn stat offsets
#define S1CH 0   // 4 ch
#define SS1  8   // 1 ch
#define SS2  12  // 4 ch
#define S2CH 16  // 8 ch
#define S3   24  // 16 ch
#define S4   40  // 32 ch
#define S5   72  // 16 ch

// ---------------- scratch ----------------
__device__ float g_h1[33554432];   // (128,4,256,256) conv1 raw
__device__ float g_s1[8388608];    // (128,1,256,256) raw s1 conv
__device__ float g_p1[8388608];    // (128,4,128,128)
__device__ float g_r2[4194304];    // (128,8,64,64)
__device__ float g_p2[1048576];    // (128,8,32,32)
__device__ float g_r3[2097152];    // (128,16,32,32)
__device__ float g_p3[524288];     // (128,16,16,16)
__device__ float g_r4[1048576];    // (128,32,16,16)
__device__ float g_r5[524288];     // (128,16,16,16)
__device__ float g_tok[524288];    // (128,256,16)
__device__ double g_sumA[128];
__device__ double g_sqA[128];

// ---------------- helpers ----------------
__device__ __forceinline__ float wred(float v){
    #pragma unroll
    for (int o=16;o>0;o>>=1) v += __shfl_down_sync(0xffffffffu, v, o);
    return v;
}
__device__ __forceinline__ void bn_scale(int off, double N, float& sc, float& sh){
    double m = g_sumA[off]/N;
    double v = g_sqA[off]/N - m*m;
    double s = 1.0/sqrt(v+1e-5);
    sc = (float)s; sh = (float)(-m*s);
}
__device__ __forceinline__ float sigm(float x){ return 1.f/(1.f+expf(-x)); }

__global__ void k_zero(){
    int t = threadIdx.x;
    if (t < 128){ g_sumA[t]=0.0; g_sqA[t]=0.0; }
}

// ---------------- conv1: 1->4, 5x5, s2, p2, register-tiled 2x2 ----------------
// block 16x16, each thread 2x2 outputs x4ch -> 32x32 out tile. grid (8,8,128)
__global__ void k_conv1(const float* __restrict__ x, const float* __restrict__ w,
                        const float* __restrict__ bias, float* __restrict__ out){
    __shared__ float t[68][69];
    __shared__ float ws[100];
    __shared__ float wb[4];
    __shared__ float ssum[4], ssq[4];
    int tid = threadIdx.y*16 + threadIdx.x;
    int b = blockIdx.z;
    if (tid < 100) ws[tid] = w[tid];
    if (tid < 4){ wb[tid] = bias[tid]; ssum[tid]=0.f; ssq[tid]=0.f; }
    int oy0 = blockIdx.y*32, ox0 = blockIdx.x*32;
    int iy0 = 2*oy0 - 2, ix0 = 2*ox0 - 2;
    const float* xb = x + (size_t)b*262144;
    for (int i = tid; i < 68*68; i += 256){
        int r = i/68, c = i%68;
        int iy = iy0 + r, ix = ix0 + c;
        float v = 0.f;
        if (iy>=0 && iy<512 && ix>=0 && ix<512) v = xb[iy*512+ix];
        t[r][c] = v;
    }
    __syncthreads();
    int ty=threadIdx.y, tx=threadIdx.x;
    // 7x7 input window in registers
    float win[7][7];
    #pragma unroll
    for (int r=0;r<7;r++)
        #pragma unroll
        for (int c=0;c<7;c++) win[r][c] = t[4*ty+r][4*tx+c];
    #pragma unroll
    for (int oc=0; oc<4; oc++){
        float a00=wb[oc], a01=wb[oc], a10=wb[oc], a11=wb[oc];
        #pragma unroll
        for (int ky=0; ky<5; ky++)
            #pragma unroll
            for (int kx=0; kx<5; kx++){
                float wv = ws[oc*25+ky*5+kx];
                a00 += win[ky  ][kx  ]*wv;
                a01 += win[ky  ][kx+2]*wv;
                a10 += win[ky+2][kx  ]*wv;
                a11 += win[ky+2][kx+2]*wv;
            }
        size_t base = (size_t)b*262144 + (size_t)oc*65536;
        int oy = oy0 + 2*ty, ox = ox0 + 2*tx;
        *(float2*)&out[base + (size_t)oy*256 + ox]     = make_float2(a00,a01);
        *(float2*)&out[base + (size_t)(oy+1)*256 + ox] = make_float2(a10,a11);
        float s = a00+a01+a10+a11;
        float q = a00*a00+a01*a01+a10*a10+a11*a11;
        s = wred(s); q = wred(q);
        if ((tid&31)==0){ atomicAdd(&ssum[oc], s); atomicAdd(&ssq[oc], q); }
    }
    __syncthreads();
    if (tid < 4){
        atomicAdd(&g_sumA[S1CH+tid], (double)ssum[tid]);
        atomicAdd(&g_sqA[S1CH+tid],  (double)ssq[tid]);
    }
}

// ---------------- s1 fused: xg computed inline from h1, conv7x7 4->1, stats ----
// block 256 threads, each 4x4 outputs -> 64x64 tile. grid (4,4,128)
// dyn smem: xg tile 4 * 70*71 floats = 79520 B
__global__ void k_s1f(const float* __restrict__ h1, const float* __restrict__ w,
                      const float* __restrict__ caw1, const float* __restrict__ cab1,
                      const float* __restrict__ caw2, const float* __restrict__ cab2,
                      float* __restrict__ s1){
    extern __shared__ float xt[];
    __shared__ float wsm[196];
    __shared__ float sc[4], sh[4];
    __shared__ float a1w[4], a2w[4], a2b[4];
    __shared__ float a1b;
    __shared__ float ssum, ssq;
    int tid = threadIdx.x;
    int b = blockIdx.z;
    if (tid<196) wsm[tid]=w[tid];
    if (tid<4){ bn_scale(S1CH+tid, N1, sc[tid], sh[tid]);
                a1w[tid]=caw1[tid]; a2w[tid]=caw2[tid]; a2b[tid]=cab2[tid]; }
    if (tid==0){ a1b=cab1[0]; ssum=0.f; ssq=0.f; }
    __syncthreads();
    int y0 = blockIdx.y*64 - 3, x0 = blockIdx.x*64 - 3;
    const float* hb = h1 + (size_t)b*262144;
    for (int i=tid; i<4900; i+=256){
        int r=i/70, cc=i%70;
        int sy=min(max(y0+r,0),255), sx=min(max(x0+cc,0),255);
        int off = sy*256+sx;
        float a0 = fmaxf(hb[off         ]*sc[0]+sh[0], 0.f);
        float a1 = fmaxf(hb[off+  65536 ]*sc[1]+sh[1], 0.f);
        float a2 = fmaxf(hb[off+ 131072 ]*sc[2]+sh[2], 0.f);
        float a3 = fmaxf(hb[off+ 196608 ]*sc[3]+sh[3], 0.f);
        float hid = fmaxf(a1b + a0*a1w[0]+a1*a1w[1]+a2*a1w[2]+a3*a1w[3], 0.f);
        int p = r*71+cc;
        xt[p        ] = a0*(hid*a2w[0]+a2b[0]);
        xt[p+ 4970  ] = a1*(hid*a2w[1]+a2b[1]);
        xt[p+ 9940  ] = a2*(hid*a2w[2]+a2b[2]);
        xt[p+14910  ] = a3*(hid*a2w[3]+a2b[3]);
    }
    __syncthreads();
    int tyy=tid>>4, txx=tid&15;
    int r0=tyy*4, c0=txx*4;
    float acc[16];
    #pragma unroll
    for (int i=0;i<16;i++) acc[i]=0.f;
    for (int c=0;c<4;c++){
        float wr[49];
        #pragma unroll
        for (int k=0;k<49;k++) wr[k]=wsm[c*49+k];
        const float* tb = &xt[c*4970];
        #pragma unroll
        for (int r=0;r<10;r++){
            float rv[10];
            #pragma unroll
            for (int j=0;j<10;j++) rv[j]=tb[(r0+r)*71 + c0+j];
            #pragma unroll
            for (int dy=0;dy<4;dy++){
                int ky=r-dy;
                if (ky>=0 && ky<7){
                    #pragma unroll
                    for (int dx=0;dx<4;dx++){
                        float a=acc[dy*4+dx];
                        #pragma unroll
                        for (int kx=0;kx<7;kx++) a += rv[dx+kx]*wr[ky*7+kx];
                        acc[dy*4+dx]=a;
                    }
                }
            }
        }
    }
    int oy=blockIdx.y*64 + r0, ox=blockIdx.x*64 + c0;
    float s=0.f, q=0.f;
    #pragma unroll
    for (int dy=0;dy<4;dy++){
        float4 v = make_float4(acc[dy*4],acc[dy*4+1],acc[dy*4+2],acc[dy*4+3]);
        *(float4*)&s1[(size_t)b*65536 + (size_t)(oy+dy)*256 + ox] = v;
        s += v.x+v.y+v.z+v.w;
        q += v.x*v.x+v.y*v.y+v.z*v.z+v.w*v.w;
    }
    s=wred(s); q=wred(q);
    if ((tid&31)==0){ atomicAdd(&ssum,s); atomicAdd(&ssq,q); }
    __syncthreads();
    if (tid==0){ atomicAdd(&g_sumA[SS1],(double)ssum); atomicAdd(&g_sqA[SS1],(double)ssq); }
}

// ---------------- s2 stats-only: conv7x7 1->4 over bn-relu(s1), no output -----
// block 256 = 4 oc * 64 threads (8x8), each 4x4 -> out tile 32x32. grid (8,8,128)
__global__ void k_s2s(const float* __restrict__ s1, const float* __restrict__ w){
    __shared__ float t[38*39];
    __shared__ float wsm[196];
    __shared__ float sc1_, sh1_;
    __shared__ float ssum[4], ssq[4];
    int tid = threadIdx.x;
    int b = blockIdx.z;
    if (tid<196) wsm[tid]=w[tid];
    if (tid==0) bn_scale(SS1, N1, sc1_, sh1_);
    if (tid<4){ ssum[tid]=0.f; ssq[tid]=0.f; }
    __syncthreads();
    int y0 = blockIdx.y*32 - 3, x0 = blockIdx.x*32 - 3;
    const float* sb = s1 + (size_t)b*65536;
    for (int i=tid; i<1444; i+=256){
        int r=i/38, cc=i%38;
        int sy=min(max(y0+r,0),255), sx=min(max(x0+cc,0),255);
        t[r*39+cc] = fmaxf(sb[sy*256+sx]*sc1_+sh1_, 0.f);
    }
    __syncthreads();
    int oc = tid>>6, t64 = tid&63;
    int tyy = t64>>3, txx = t64&7;
    int r0=tyy*4, c0=txx*4;
    float wr[49];
    #pragma unroll
    for (int k=0;k<49;k++) wr[k]=wsm[oc*49+k];
    float acc[16];
    #pragma unroll
    for (int i=0;i<16;i++) acc[i]=0.f;
    #pragma unroll
    for (int r=0;r<10;r++){
        float rv[10];
        #pragma unroll
        for (int j=0;j<10;j++) rv[j]=t[(r0+r)*39 + c0+j];
        #pragma unroll
        for (int dy=0;dy<4;dy++){
            int ky=r-dy;
            if (ky>=0 && ky<7){
                #pragma unroll
                for (int dx=0;dx<4;dx++){
                    float a=acc[dy*4+dx];
                    #pragma unroll
                    for (int kx=0;kx<7;kx++) a += rv[dx+kx]*wr[ky*7+kx];
                    acc[dy*4+dx]=a;
                }
            }
        }
    }
    float s=0.f,q=0.f;
    #pragma unroll
    for (int i=0;i<16;i++){ s+=acc[i]; q+=acc[i]*acc[i]; }
    s=wred(s); q=wred(q);
    if ((tid&31)==0){ atomicAdd(&ssum[oc],s); atomicAdd(&ssq[oc],q); }
    __syncthreads();
    if (tid<4){
        atomicAdd(&g_sumA[SS2+tid],(double)ssum[tid]);
        atomicAdd(&g_sqA[SS2+tid], (double)ssq[tid]);
    }
}

// ---------------- pool1 fused: recompute xg (from h1) + s2 conv (from s1),
//                  gate with sigmoid(bn(s2)), maxpool2, write p1 ----------------
// block 256 threads, each 2x2 pooled x4ch. pooled tile 32x32. grid (4,4,128)
// dyn smem: s1t 70*71=4970 + xg 4*64*65=16640  -> 21610 floats = 86440 B
__global__ void k_pool1f(const float* __restrict__ h1, const float* __restrict__ s1,
                         const float* __restrict__ w2,
                         const float* __restrict__ caw1, const float* __restrict__ cab1,
                         const float* __restrict__ caw2, const float* __restrict__ cab2,
                         float* __restrict__ p1){
    extern __shared__ float sm[];
    float* s1t = sm;            // 70*71
    float* xgt = sm + 4970;     // 4 * 64*65
    __shared__ float wsm[196];
    __shared__ float scA[4], shA[4];
    __shared__ float sc2[4], sh2[4];
    __shared__ float a1w[4], a2w[4], a2b[4];
    __shared__ float sc1_, sh1_, a1b;
    int tid = threadIdx.x;
    int b = blockIdx.z;
    if (tid<196) wsm[tid]=w2[tid];
    if (tid<4){
        bn_scale(S1CH+tid, N1, scA[tid], shA[tid]);
        bn_scale(SS2+tid,  N1, sc2[tid], sh2[tid]);
        a1w[tid]=caw1[tid]; a2w[tid]=caw2[tid]; a2b[tid]=cab2[tid];
    }
    if (tid==0){ bn_scale(SS1, N1, sc1_, sh1_); a1b=cab1[0]; }
    __syncthreads();
    int Y0 = blockIdx.y*64, X0 = blockIdx.x*64;   // s2-pixel tile origin
    int y0 = Y0-3, x0 = X0-3;
    const float* sb = s1 + (size_t)b*65536;
    for (int i=tid; i<4900; i+=256){
        int r=i/70, cc=i%70;
        int sy=min(max(y0+r,0),255), sx=min(max(x0+cc,0),255);
        s1t[r*71+cc] = fmaxf(sb[sy*256+sx]*sc1_+sh1_, 0.f);
    }
    // xg for this thread's own 4x4 block (no halo needed)
    int tyy=tid>>4, txx=tid&15;
    int r0=tyy*4, c0=txx*4;
    const float* hb = h1 + (size_t)b*262144;
    #pragma unroll
    for (int i=0;i<4;i++){
        int gy=Y0+r0+i, gx=X0+c0;
        float ch0[4], ch1[4], ch2[4], ch3[4];
        *(float4*)ch0 = *(const float4*)&hb[(size_t)gy*256+gx];
        *(float4*)ch1 = *(const float4*)&hb[(size_t)gy*256+gx+ 65536];
        *(float4*)ch2 = *(const float4*)&hb[(size_t)gy*256+gx+131072];
        *(float4*)ch3 = *(const float4*)&hb[(size_t)gy*256+gx+196608];
        #pragma unroll
        for (int j=0;j<4;j++){
            float a0=fmaxf(ch0[j]*scA[0]+shA[0],0.f);
            float a1=fmaxf(ch1[j]*scA[1]+shA[1],0.f);
            float a2=fmaxf(ch2[j]*scA[2]+shA[2],0.f);
            float a3=fmaxf(ch3[j]*scA[3]+shA[3],0.f);
            float hid=fmaxf(a1b + a0*a1w[0]+a1*a1w[1]+a2*a1w[2]+a3*a1w[3],0.f);
            int p = (r0+i)*65 + (c0+j);
            xgt[p       ] = a0*(hid*a2w[0]+a2b[0]);
            xgt[p+ 4160 ] = a1*(hid*a2w[1]+a2b[1]);
            xgt[p+ 8320 ] = a2*(hid*a2w[2]+a2b[2]);
            xgt[p+12480 ] = a3*(hid*a2w[3]+a2b[3]);
        }
    }
    __syncthreads();
    for (int oc=0; oc<4; oc++){
        float wr[49];
        #pragma unroll
        for (int k=0;k<49;k++) wr[k]=wsm[oc*49+k];
        float acc[16];
        #pragma unroll
        for (int i=0;i<16;i++) acc[i]=0.f;
        #pragma unroll
        for (int r=0;r<10;r++){
            float rv[10];
            #pragma unroll
            for (int j=0;j<10;j++) rv[j]=s1t[(r0+r)*71 + c0+j];
            #pragma unroll
            for (int dy=0;dy<4;dy++){
                int ky=r-dy;
                if (ky>=0 && ky<7){
                    #pragma unroll
                    for (int dx=0;dx<4;dx++){
                        float a=acc[dy*4+dx];
                        #pragma unroll
                        for (int kx=0;kx<7;kx++) a += rv[dx+kx]*wr[ky*7+kx];
                        acc[dy*4+dx]=a;
                    }
                }
            }
        }
        // gate + maxpool 2x2 -> thread's 2x2 pooled outputs
        const float* xg_c = &xgt[oc*4160];
        #pragma unroll
        for (int dy=0;dy<2;dy++){
            float2 vv;
            #pragma unroll
            for (int dx=0;dx<2;dx++){
                float m=-1e30f;
                #pragma unroll
                for (int sy=0;sy<2;sy++)
                    #pragma unroll
                    for (int sx=0;sx<2;sx++){
                        int i=2*dy+sy, j=2*dx+sx;
                        float sv = sigm(acc[i*4+j]*sc2[oc]+sh2[oc]);
                        float xv = xg_c[(r0+i)*65 + c0+j];
                        m = fmaxf(m, xv*sv);
                    }
                if (dx==0) vv.x=m; else vv.y=m;
            }
            int py = blockIdx.y*32 + 2*tyy + dy;
            int px = blockIdx.x*32 + 2*txx;
            *(float2*)&p1[(size_t)b*65536 + (size_t)oc*16384 + (size_t)py*128 + px] = vv;
        }
    }
}

// ---------------- conv2: 4->8, 3x3, s2, p1 + stats ----------------
__global__ void k_conv2(const float* __restrict__ in, const float* __restrict__ w,
                        const float* __restrict__ bias, float* __restrict__ out){
    __shared__ float t[4][33][33];
    __shared__ float ws[288];
    __shared__ float wb[8];
    __shared__ float ssum[8], ssq[8];
    int tid = threadIdx.y*16+threadIdx.x;
    int b = blockIdx.z;
    for (int i=tid;i<288;i+=256) ws[i]=w[i];
    if (tid<8){ wb[tid]=bias[tid]; ssum[tid]=0.f; ssq[tid]=0.f; }
    int iy0 = blockIdx.y*32-1, ix0 = blockIdx.x*32-1;
    for (int i=tid; i<4*1089; i+=256){
        int c=i/1089; int r=(i%1089)/33; int cc=i%33;
        int iy=iy0+r, ix=ix0+cc;
        float v=0.f;
        if (iy>=0&&iy<128&&ix>=0&&ix<128)
            v = in[(size_t)b*65536 + (size_t)c*16384 + iy*128+ix];
        t[c][r][cc]=v;
    }
    __syncthreads();
    int ty=threadIdx.y, tx=threadIdx.x;
    float acc[8];
    #pragma unroll
    for (int oc=0;oc<8;oc++) acc[oc]=wb[oc];
    #pragma unroll
    for (int ci=0;ci<4;ci++)
        #pragma unroll
        for (int ky=0;ky<3;ky++)
            #pragma unroll
            for (int kx=0;kx<3;kx++){
                float v = t[ci][2*ty+ky][2*tx+kx];
                #pragma unroll
                for (int oc=0;oc<8;oc++) acc[oc]+=v*ws[oc*36+ci*9+ky*3+kx];
            }
    int oy = blockIdx.y*16+ty, ox = blockIdx.x*16+tx;
    #pragma unroll
    for (int oc=0;oc<8;oc++)
        out[(size_t)b*32768 + (size_t)oc*4096 + oy*64+ox] = acc[oc];
    #pragma unroll
    for (int oc=0;oc<8;oc++){
        float s=wred(acc[oc]), q=wred(acc[oc]*acc[oc]);
        if ((tid&31)==0){ atomicAdd(&ssum[oc],s); atomicAdd(&ssq[oc],q); }
    }
    __syncthreads();
    if (tid<8){
        atomicAdd(&g_sumA[S2CH+tid], (double)ssum[tid]);
        atomicAdd(&g_sqA[S2CH+tid],  (double)ssq[tid]);
    }
}

// ---------------- pool2 = maxpool2(relu(bn(r2))) ----------------
__global__ void k_pool2(const float* __restrict__ r2, float* __restrict__ p2){
    __shared__ float sc[8], sh[8];
    int tid=threadIdx.x;
    if (tid<8) bn_scale(S2CH+tid, N2, sc[tid], sh[tid]);
    __syncthreads();
    int idx = blockIdx.x*256+tid;
    int ox=idx&31; int oy=(idx>>5)&31; int c=(idx>>10)&7; int b=idx>>13;
    size_t base = (size_t)b*32768 + (size_t)c*4096;
    float m=-1e30f;
    #pragma unroll
    for (int dy=0;dy<2;dy++)
        #pragma unroll
        for (int dx=0;dx<2;dx++){
            float v = r2[base + (size_t)(2*oy+dy)*64 + (2*ox+dx)]*sc[c]+sh[c];
            v = v>0.f?v:0.f;
            m = fmaxf(m,v);
        }
    p2[(size_t)b*8192 + (size_t)c*1024 + oy*32+ox] = m;
}

// ---------------- conv3: 8->16, 3x3, s1, p1 + stats ----------------
__global__ void k_conv3(const float* __restrict__ in, const float* __restrict__ w,
                        const float* __restrict__ bias, float* __restrict__ out){
    __shared__ float t[8][18][18];
    __shared__ float ws[1152];
    __shared__ float wb[16];
    __shared__ float ssum[16], ssq[16];
    int tid = threadIdx.y*16+threadIdx.x;
    int b = blockIdx.z;
    for (int i=tid;i<1152;i+=256) ws[i]=w[i];
    if (tid<16){ wb[tid]=bias[tid]; ssum[tid]=0.f; ssq[tid]=0.f; }
    int iy0 = blockIdx.y*16-1, ix0 = blockIdx.x*16-1;
    for (int i=tid;i<8*324;i+=256){
        int c=i/324; int r=(i%324)/18; int cc=i%18;
        int iy=iy0+r, ix=ix0+cc;
        float v=0.f;
        if (iy>=0&&iy<32&&ix>=0&&ix<32)
            v = in[(size_t)b*8192 + (size_t)c*1024 + iy*32+ix];
        t[c][r][cc]=v;
    }
    __syncthreads();
    int ty=threadIdx.y, tx=threadIdx.x;
    float acc[16];
    #pragma unroll
    for (int oc=0;oc<16;oc++) acc[oc]=wb[oc];
    #pragma unroll
    for (int ci=0;ci<8;ci++)
        #pragma unroll
        for (int ky=0;ky<3;ky++)
            #pragma unroll
            for (int kx=0;kx<3;kx++){
                float v=t[ci][ty+ky][tx+kx];
                #pragma unroll
                for (int oc=0;oc<16;oc++) acc[oc]+=v*ws[oc*72+ci*9+ky*3+kx];
            }
    int oy=blockIdx.y*16+ty, ox=blockIdx.x*16+tx;
    #pragma unroll
    for (int oc=0;oc<16;oc++)
        out[(size_t)b*16384 + (size_t)oc*1024 + oy*32+ox]=acc[oc];
    #pragma unroll
    for (int oc=0;oc<16;oc++){
        float s=wred(acc[oc]), q=wred(acc[oc]*acc[oc]);
        if ((tid&31)==0){ atomicAdd(&ssum[oc],s); atomicAdd(&ssq[oc],q); }
    }
    __syncthreads();
    if (tid<16){
        atomicAdd(&g_sumA[S3+tid], (double)ssum[tid]);
        atomicAdd(&g_sqA[S3+tid],  (double)ssq[tid]);
    }
}

// ---------------- pool3 = maxpool2(relu(bn(r3))) ----------------
__global__ void k_pool3(const float* __restrict__ r3, float* __restrict__ p3){
    __shared__ float sc[16], sh[16];
    int tid=threadIdx.x;
    if (tid<16) bn_scale(S3+tid, N3, sc[tid], sh[tid]);
    __syncthreads();
    int idx = blockIdx.x*256+tid;
    int ox=idx&15; int oy=(idx>>4)&15; int c=(idx>>8)&15; int b=idx>>12;
    size_t base=(size_t)b*16384 + (size_t)c*1024;
    float m=-1e30f;
    #pragma unroll
    for (int dy=0;dy<2;dy++)
        #pragma unroll
        for (int dx=0;dx<2;dx++){
            float v=r3[base + (size_t)(2*oy+dy)*32 + (2*ox+dx)]*sc[c]+sh[c];
            v=v>0.f?v:0.f;
            m=fmaxf(m,v);
        }
    p3[(size_t)b*4096 + (size_t)c*256 + oy*16+ox]=m;
}

// ---------------- conv4: 16->32, 3x3, s1, p1 + stats ----------------
__global__ void k_conv4(const float* __restrict__ in, const float* __restrict__ w,
                        const float* __restrict__ bias, float* __restrict__ out){
    __shared__ float t[16][18][18];
    __shared__ float ws[4608];
    __shared__ float wb[32];
    __shared__ float ssum[32], ssq[32];
    int tid = threadIdx.y*16+threadIdx.x;
    int b = blockIdx.x;
    for (int i=tid;i<4608;i+=256) ws[i]=w[i];
    if (tid<32){ wb[tid]=bias[tid]; ssum[tid]=0.f; ssq[tid]=0.f; }
    for (int i=tid;i<16*324;i+=256){
        int c=i/324; int r=(i%324)/18; int cc=i%18;
        int iy=r-1, ix=cc-1;
        float v=0.f;
        if (iy>=0&&iy<16&&ix>=0&&ix<16)
            v = in[(size_t)b*4096 + (size_t)c*256 + iy*16+ix];
        t[c][r][cc]=v;
    }
    __syncthreads();
    int ty=threadIdx.y, tx=threadIdx.x;
    float acc[32];
    #pragma unroll
    for (int oc=0;oc<32;oc++) acc[oc]=wb[oc];
    for (int ci=0;ci<16;ci++)
        #pragma unroll
        for (int ky=0;ky<3;ky++)
            #pragma unroll
            for (int kx=0;kx<3;kx++){
                float v=t[ci][ty+ky][tx+kx];
                #pragma unroll
                for (int oc=0;oc<32;oc++) acc[oc]+=v*ws[oc*144+ci*9+ky*3+kx];
            }
    #pragma unroll
    for (int oc=0;oc<32;oc++)
        out[(size_t)b*8192 + (size_t)oc*256 + ty*16+tx]=acc[oc];
    #pragma unroll
    for (int oc=0;oc<32;oc++){
        float s=wred(acc[oc]), q=wred(acc[oc]*acc[oc]);
        if ((tid&31)==0){ atomicAdd(&ssum[oc],s); atomicAdd(&ssq[oc],q); }
    }
    __syncthreads();
    if (tid<32){
        atomicAdd(&g_sumA[S4+tid], (double)ssum[tid]);
        atomicAdd(&g_sqA[S4+tid],  (double)ssq[tid]);
    }
}

// ---------------- conv5: 1x1, relu(bn(r4)) -> 16 + stats ----------------
__global__ void k_conv5(const float* __restrict__ r4, const float* __restrict__ w,
                        const float* __restrict__ bias, float* __restrict__ out){
    __shared__ float sc[32], sh[32];
    __shared__ float ws[512];
    __shared__ float wb[16];
    __shared__ float ssum[16], ssq[16];
    int tid=threadIdx.x;
    if (tid<32) bn_scale(S4+tid, N4, sc[tid], sh[tid]);
    for (int i=tid;i<512;i+=256) ws[i]=w[i];
    if (tid<16){ wb[tid]=bias[tid]; ssum[tid]=0.f; ssq[tid]=0.f; }
    __syncthreads();
    int idx = blockIdx.x*256+tid;
    int b = idx>>8; int p = idx&255;
    float a[32];
    #pragma unroll
    for (int ci=0;ci<32;ci++){
        float v = r4[(size_t)b*8192 + (size_t)ci*256 + p]*sc[ci]+sh[ci];
        a[ci]=v>0.f?v:0.f;
    }
    float accs[16];
    #pragma unroll
    for (int oc=0;oc<16;oc++){
        float acc=wb[oc];
        #pragma unroll
        for (int ci=0;ci<32;ci++) acc += a[ci]*ws[oc*32+ci];
        out[(size_t)b*4096 + (size_t)oc*256 + p]=acc;
        accs[oc]=acc;
    }
    #pragma unroll
    for (int oc=0;oc<16;oc++){
        float s=wred(accs[oc]), q=wred(accs[oc]*accs[oc]);
        if ((tid&31)==0){ atomicAdd(&ssum[oc],s); atomicAdd(&ssq[oc],q); }
    }
    __syncthreads();
    if (tid<16){
        atomicAdd(&g_sumA[S5+tid], (double)ssum[tid]);
        atomicAdd(&g_sqA[S5+tid],  (double)ssq[tid]);
    }
}

// ---------------- tok = relu(bn(r5)) transposed to (B,L,D) ----------------
__global__ void k_tok(const float* __restrict__ r5, float* __restrict__ tok){
    __shared__ float sc[16], sh[16];
    int tid=threadIdx.x;
    if (tid<16) bn_scale(S5+tid, N5, sc[tid], sh[tid]);
    __syncthreads();
    int idx = blockIdx.x*256+tid;
    int d = idx&15; int l=(idx>>4)&255; int b=idx>>12;
    float v = r5[(size_t)b*4096 + (size_t)d*256 + l]*sc[d]+sh[d];
    tok[idx] = v>0.f?v:0.f;
}

// ---------------- mamba layer (block per batch, everything in smem) ----------------
#define O_WIN 0
#define O_CW  1024
#define O_CB  1152
#define O_XP  1184
#define O_DTW 2240
#define O_DTB 2272
#define O_AE  2304
#define O_DD  2816
#define O_OW  2848
#define O_LNG 3360
#define O_LNB 3376
#define O_XI  3392
#define O_ZZ  11584
#define O_XC  19776
#define O_DL  27968
#define O_BM  36160
#define O_CM  40256
#define O_YY  44352
#define SM_FLOATS 52544

__global__ void k_mamba(float* __restrict__ tok,
    const float* __restrict__ lng, const float* __restrict__ lnb,
    const float* __restrict__ inw, const float* __restrict__ cw, const float* __restrict__ cb,
    const float* __restrict__ xpw, const float* __restrict__ dtw, const float* __restrict__ dtb,
    const float* __restrict__ alog, const float* __restrict__ dvec, const float* __restrict__ ow)
{
    extern __shared__ float sm[];
    int t = threadIdx.x; int b = blockIdx.x;
    for (int i=t;i<1024;i+=512) sm[O_WIN+i]=inw[i];
    for (int i=t;i<128;i+=512)  sm[O_CW+i]=cw[i];
    for (int i=t;i<1056;i+=512) sm[O_XP+i]=xpw[i];
    for (int i=t;i<512;i+=512){ sm[O_AE+i]=-expf(alog[i]); sm[O_OW+i]=ow[i]; }
    if (t<32){ sm[O_CB+t]=cb[t]; sm[O_DTW+t]=dtw[t]; sm[O_DTB+t]=dtb[t]; sm[O_DD+t]=dvec[t]; }
    if (t<16){ sm[O_LNG+t]=lng[t]; sm[O_LNB+t]=lnb[t]; }
    __syncthreads();

    if (t < 256){
        int l=t;
        float v[16];
        const float* tp = tok + ((size_t)b*4096 + (size_t)l*16);
        float mean=0.f;
        #pragma unroll
        for (int d=0;d<16;d++){ v[d]=tp[d]; mean+=v[d]; }
        mean *= 0.0625f;
        float var=0.f;
        #pragma unroll
        for (int d=0;d<16;d++){ float dd=v[d]-mean; var+=dd*dd; }
        var *= 0.0625f;
        float inv = rsqrtf(var+1e-5f);
        #pragma unroll
        for (int d=0;d<16;d++) v[d]=(v[d]-mean)*inv*sm[O_LNG+d]+sm[O_LNB+d];
        for (int j=0;j<64;j++){
            float a=0.f;
            #pragma unroll
            for (int d=0;d<16;d++) a += v[d]*sm[O_WIN+j*16+d];
            if (j<32) sm[O_XI+l*32+j]=a; else sm[O_ZZ+l*32+j-32]=a;
        }
    }
    __syncthreads();

    if (t < 256){
        int l=t;
        for (int d=0;d<32;d++){
            float a = sm[O_CB+d];
            #pragma unroll
            for (int k=0;k<4;k++){
                int ll=l-3+k;
                if (ll>=0) a += sm[O_CW+d*4+k]*sm[O_XI+ll*32+d];
            }
            sm[O_XC+l*32+d] = a/(1.f+expf(-a));
        }
    }
    __syncthreads();

    if (t < 256){
        int l=t;
        float xcl[32];
        #pragma unroll
        for (int d=0;d<32;d++) xcl[d]=sm[O_XC+l*32+d];
        float dtv=0.f;
        #pragma unroll
        for (int d=0;d<32;d++) dtv += xcl[d]*sm[O_XP+d];
        for (int n=0;n<16;n++){
            float bb=0.f, cc=0.f;
            #pragma unroll
            for (int d=0;d<32;d++){
                bb += xcl[d]*sm[O_XP+(1+n)*32+d];
                cc += xcl[d]*sm[O_XP+(17+n)*32+d];
            }
            sm[O_BM+l*16+n]=bb; sm[O_CM+l*16+n]=cc;
        }
        for (int d=0;d<32;d++){
            float pre = dtv*sm[O_DTW+d]+sm[O_DTB+d];
            float sp = (pre>20.f)? pre : log1pf(expf(pre));
            sm[O_DL+l*32+d]=sp;
        }
    }
    __syncthreads();

    {
        int d = t>>4, n = t&15;
        float A  = sm[O_AE+d*16+n];
        float Dv = sm[O_DD+d];
        float h=0.f;
        for (int l=0;l<256;l++){
            float dl  = sm[O_DL+l*32+d];
            float xcv = sm[O_XC+l*32+d];
            float dA  = expf(dl*A);
            h = dA*h + dl*sm[O_BM+l*16+n]*xcv;
            float c = h*sm[O_CM+l*16+n];
            c += __shfl_xor_sync(0xffffffffu, c, 1);
            c += __shfl_xor_sync(0xffffffffu, c, 2);
            c += __shfl_xor_sync(0xffffffffu, c, 4);
            c += __shfl_xor_sync(0xffffffffu, c, 8);
            if (n==0) sm[O_YY+l*32+d] = c + xcv*Dv;
        }
    }
    __syncthreads();

    if (t < 256){
        int l=t;
        float yv[32];
        #pragma unroll
        for (int d=0;d<32;d++){
            float zv=sm[O_ZZ+l*32+d];
            yv[d]=sm[O_YY+l*32+d]*(zv/(1.f+expf(-zv)));
        }
        float* tp = tok + ((size_t)b*4096 + (size_t)l*16);
        #pragma unroll
        for (int j=0;j<16;j++){
            float a=0.f;
            #pragma unroll
            for (int d=0;d<32;d++) a += yv[d]*sm[O_OW+j*32+d];
            tp[j] += a;
        }
    }
}

// ---------------- head: mean-pool + linear + LN ----------------
__global__ void k_head(const float* __restrict__ tok, const float* __restrict__ pw,
                       const float* __restrict__ pb, const float* __restrict__ fg,
                       const float* __restrict__ fb, float* __restrict__ out){
    __shared__ float pooled[16];
    __shared__ float red[16];
    __shared__ float s_mean, s_inv;
    int t=threadIdx.x, b=blockIdx.x;
    if (t<16){
        float s=0.f;
        const float* tp = tok + (size_t)b*4096 + t;
        for (int l=0;l<256;l++) s += tp[l*16];
        pooled[t] = s*(1.f/256.f);
    }
    __syncthreads();
    float lg = pb[t];
    #pragma unroll
    for (int d=0;d<16;d++) lg += pooled[d]*pw[t*16+d];
    float s1v = wred(lg);
    float s2v = wred(lg*lg);
    int w = t>>5;
    if ((t&31)==0){ red[w]=s1v; red[8+w]=s2v; }
    __syncthreads();
    if (t==0){
        float a=0.f,q=0.f;
        for (int i=0;i<8;i++){a+=red[i]; q+=red[8+i];}
        float m=a*(1.f/256.f);
        float v=q*(1.f/256.f)-m*m;
        s_mean=m; s_inv=rsqrtf(v+1e-5f);
    }
    __syncthreads();
    out[b*256+t] = (lg-s_mean)*s_inv*fg[t]+fb[t];
}

// ---------------- launch ----------------
extern "C" void kernel_launch(void* const* d_in, const int* in_sizes, int n_in,
                              void* d_out, int out_size){
    const float* x    = (const float*)d_in[0];
    const float* c1w  = (const float*)d_in[1];
    const float* c1b  = (const float*)d_in[2];
    const float* caw1 = (const float*)d_in[3];
    const float* cab1 = (const float*)d_in[4];
    const float* caw2 = (const float*)d_in[5];
    const float* cab2 = (const float*)d_in[6];
    const float* sw1  = (const float*)d_in[7];
    const float* sw2  = (const float*)d_in[8];
    const float* c2w  = (const float*)d_in[9];
    const float* c2b  = (const float*)d_in[10];
    const float* c3w  = (const float*)d_in[11];
    const float* c3b  = (const float*)d_in[12];
    const float* c4w  = (const float*)d_in[13];
    const float* c4b  = (const float*)d_in[14];
    const float* c5w  = (const float*)d_in[15];
    const float* c5b  = (const float*)d_in[16];
    const float* mlng = (const float*)d_in[17];
    const float* mlnb = (const float*)d_in[18];
    const float* minw = (const float*)d_in[19];
    const float* mcw  = (const float*)d_in[20];
    const float* mcb  = (const float*)d_in[21];
    const float* mxp  = (const float*)d_in[22];
    const float* mdtw = (const float*)d_in[23];
    const float* mdtb = (const float*)d_in[24];
    const float* mal  = (const float*)d_in[25];
    const float* mD   = (const float*)d_in[26];
    const float* mow  = (const float*)d_in[27];
    const float* pw   = (const float*)d_in[28];
    const float* pb   = (const float*)d_in[29];
    const float* fg   = (const float*)d_in[30];
    const float* fb   = (const float*)d_in[31];
    float* out = (float*)d_out;

    float *h1, *s1, *p1, *r2, *p2, *r3, *p3, *r4, *r5, *tok;
    cudaGetSymbolAddress((void**)&h1, g_h1);
    cudaGetSymbolAddress((void**)&s1, g_s1);
    cudaGetSymbolAddress((void**)&p1, g_p1);
    cudaGetSymbolAddress((void**)&r2, g_r2);
    cudaGetSymbolAddress((void**)&p2, g_p2);
    cudaGetSymbolAddress((void**)&r3, g_r3);
    cudaGetSymbolAddress((void**)&p3, g_p3);
    cudaGetSymbolAddress((void**)&r4, g_r4);
    cudaGetSymbolAddress((void**)&r5, g_r5);
    cudaGetSymbolAddress((void**)&tok, g_tok);

    size_t smem_mamba = SM_FLOATS * sizeof(float);
    cudaFuncSetAttribute(k_mamba, cudaFuncAttributeMaxDynamicSharedMemorySize, (int)smem_mamba);
    size_t smem_s1f = 4*4970*sizeof(float);           // 79520
    cudaFuncSetAttribute(k_s1f, cudaFuncAttributeMaxDynamicSharedMemorySize, (int)smem_s1f);
    size_t smem_p1f = (4970 + 4*4160)*sizeof(float);  // 86440
    cudaFuncSetAttribute(k_pool1f, cudaFuncAttributeMaxDynamicSharedMemorySize, (int)smem_p1f);

    k_zero<<<1,128>>>();
    k_conv1<<<dim3(8,8,128), dim3(16,16)>>>(x, c1w, c1b, h1);
    k_s1f<<<dim3(4,4,128), 256, smem_s1f>>>(h1, sw1, caw1, cab1, caw2, cab2, s1);
    k_s2s<<<dim3(8,8,128), 256>>>(s1, sw2);
    k_pool1f<<<dim3(4,4,128), 256, smem_p1f>>>(h1, s1, sw2, caw1, cab1, caw2, cab2, p1);
    k_conv2<<<dim3(4,4,128), dim3(16,16)>>>(p1, c2w, c2b, r2);
    k_pool2<<<4096,256>>>(r2, p2);
    k_conv3<<<dim3(2,2,128), dim3(16,16)>>>(p2, c3w, c3b, r3);
    k_pool3<<<2048,256>>>(r3, p3);
    k_conv4<<<128, dim3(16,16)>>>(p3, c4w, c4b, r4);
    k_conv5<<<128,256>>>(r4, c5w, c5b, r5);
    k_tok<<<2048,256>>>(r5, tok);
    for (int layer=0; layer<2; layer++){
        k_mamba<<<128,512,smem_mamba>>>(tok,
            mlng+layer*16, mlnb+layer*16, minw+layer*1024,
            mcw+layer*128, mcb+layer*32, mxp+layer*1056,
            mdtw+layer*32, mdtb+layer*32, mal+layer*512,
            mD+layer*32, mow+layer*512);
    }
    k_head<<<128,256>>>(tok, pw, pb, fg, fb, out);
}

// round 4
// speedup vs baseline: 1.7528x; 1.2422x over previous
#include <cuda_runtime.h>
#include <cuda_bf16.h>
#include <math.h>

// ---------------- constants ----------------
#define N1  8388608.0   // 128*256*256 per channel
#define N2  524288.0    // 128*64*64
#define N3  131072.0    // 128*32*32
#define N4  32768.0     // 128*16*16
#define N5  32768.0

// bn stat offsets
#define S1CH 0   // 4 ch
#define SS1  8   // 1 ch
#define SS2  12  // 4 ch
#define S2CH 16  // 8 ch
#define S3   24  // 16 ch
#define S4   40  // 32 ch
#define S5   72  // 16 ch

// ---------------- scratch ----------------
__device__ float g_h1[33554432];   // (128,4,256,256) conv1 raw
__device__ float g_s2[33554432];   // (128,4,256,256) raw s2 conv
__device__ float g_s1[8388608];    // (128,1,256,256) raw s1 conv
__device__ float g_p1[8388608];    // (128,4,128,128)
__device__ float g_r2[4194304];    // (128,8,64,64)
__device__ float g_p2[1048576];    // (128,8,32,32)
__device__ float g_r3[2097152];    // (128,16,32,32)
__device__ float g_p3[524288];     // (128,16,16,16)
__device__ float g_r4[1048576];    // (128,32,16,16)
__device__ float g_r5[524288];     // (128,16,16,16)
__device__ float g_tok[524288];    // (128,256,16)
__device__ double g_sumA[128];
__device__ double g_sqA[128];

// ---------------- helpers ----------------
__device__ __forceinline__ float wred(float v){
    #pragma unroll
    for (int o=16;o>0;o>>=1) v += __shfl_down_sync(0xffffffffu, v, o);
    return v;
}
__device__ __forceinline__ void bn_scale(int off, double N, float& sc, float& sh){
    double m = g_sumA[off]/N;
    double v = g_sqA[off]/N - m*m;
    double s = 1.0/sqrt(v+1e-5);
    sc = (float)s; sh = (float)(-m*s);
}
__device__ __forceinline__ float sigm(float x){
    return __fdividef(1.f, 1.f + __expf(-x));
}

__global__ void k_zero(){
    int t = threadIdx.x;
    if (t < 128){ g_sumA[t]=0.0; g_sqA[t]=0.0; }
}

// ---------------- conv1: 1->4, 5x5, s2, p2, register-tiled 2x2 ----------------
__global__ void k_conv1(const float* __restrict__ x, const float* __restrict__ w,
                        const float* __restrict__ bias, float* __restrict__ out){
    __shared__ float t[68][69];
    __shared__ float ws[100];
    __shared__ float wb[4];
    __shared__ float ssum[4], ssq[4];
    int tid = threadIdx.y*16 + threadIdx.x;
    int b = blockIdx.z;
    if (tid < 100) ws[tid] = w[tid];
    if (tid < 4){ wb[tid] = bias[tid]; ssum[tid]=0.f; ssq[tid]=0.f; }
    int oy0 = blockIdx.y*32, ox0 = blockIdx.x*32;
    int iy0 = 2*oy0 - 2, ix0 = 2*ox0 - 2;
    const float* xb = x + (size_t)b*262144;
    for (int i = tid; i < 68*68; i += 256){
        int r = i/68, c = i%68;
        int iy = iy0 + r, ix = ix0 + c;
        float v = 0.f;
        if (iy>=0 && iy<512 && ix>=0 && ix<512) v = xb[iy*512+ix];
        t[r][c] = v;
    }
    __syncthreads();
    int ty=threadIdx.y, tx=threadIdx.x;
    float win[7][7];
    #pragma unroll
    for (int r=0;r<7;r++)
        #pragma unroll
        for (int c=0;c<7;c++) win[r][c] = t[4*ty+r][4*tx+c];
    #pragma unroll
    for (int oc=0; oc<4; oc++){
        float a00=wb[oc], a01=wb[oc], a10=wb[oc], a11=wb[oc];
        #pragma unroll
        for (int ky=0; ky<5; ky++)
            #pragma unroll
            for (int kx=0; kx<5; kx++){
                float wv = ws[oc*25+ky*5+kx];
                a00 += win[ky  ][kx  ]*wv;
                a01 += win[ky  ][kx+2]*wv;
                a10 += win[ky+2][kx  ]*wv;
                a11 += win[ky+2][kx+2]*wv;
            }
        size_t base = (size_t)b*262144 + (size_t)oc*65536;
        int oy = oy0 + 2*ty, ox = ox0 + 2*tx;
        *(float2*)&out[base + (size_t)oy*256 + ox]     = make_float2(a00,a01);
        *(float2*)&out[base + (size_t)(oy+1)*256 + ox] = make_float2(a10,a11);
        float s = a00+a01+a10+a11;
        float q = a00*a00+a01*a01+a10*a10+a11*a11;
        s = wred(s); q = wred(q);
        if ((tid&31)==0){ atomicAdd(&ssum[oc], s); atomicAdd(&ssq[oc], q); }
    }
    __syncthreads();
    if (tid < 4){
        atomicAdd(&g_sumA[S1CH+tid], (double)ssum[tid]);
        atomicAdd(&g_sqA[S1CH+tid],  (double)ssq[tid]);
    }
}

// ---------------- s1 fused: xg inline from h1, conv7x7 4->1, stats ----------
__global__ void k_s1f(const float* __restrict__ h1, const float* __restrict__ w,
                      const float* __restrict__ caw1, const float* __restrict__ cab1,
                      const float* __restrict__ caw2, const float* __restrict__ cab2,
                      float* __restrict__ s1){
    extern __shared__ float xt[];
    __shared__ float wsm[196];
    __shared__ float sc[4], sh[4];
    __shared__ float a1w[4], a2w[4], a2b[4];
    __shared__ float a1b;
    __shared__ float ssum, ssq;
    int tid = threadIdx.x;
    int b = blockIdx.z;
    if (tid<196) wsm[tid]=w[tid];
    if (tid<4){ bn_scale(S1CH+tid, N1, sc[tid], sh[tid]);
                a1w[tid]=caw1[tid]; a2w[tid]=caw2[tid]; a2b[tid]=cab2[tid]; }
    if (tid==0){ a1b=cab1[0]; ssum=0.f; ssq=0.f; }
    __syncthreads();
    int y0 = blockIdx.y*64 - 3, x0 = blockIdx.x*64 - 3;
    const float* hb = h1 + (size_t)b*262144;
    for (int i=tid; i<4900; i+=256){
        int r=i/70, cc=i%70;
        int sy=min(max(y0+r,0),255), sx=min(max(x0+cc,0),255);
        int off = sy*256+sx;
        float a0 = fmaxf(hb[off         ]*sc[0]+sh[0], 0.f);
        float a1 = fmaxf(hb[off+  65536 ]*sc[1]+sh[1], 0.f);
        float a2 = fmaxf(hb[off+ 131072 ]*sc[2]+sh[2], 0.f);
        float a3 = fmaxf(hb[off+ 196608 ]*sc[3]+sh[3], 0.f);
        float hid = fmaxf(a1b + a0*a1w[0]+a1*a1w[1]+a2*a1w[2]+a3*a1w[3], 0.f);
        int p = r*71+cc;
        xt[p        ] = a0*(hid*a2w[0]+a2b[0]);
        xt[p+ 4970  ] = a1*(hid*a2w[1]+a2b[1]);
        xt[p+ 9940  ] = a2*(hid*a2w[2]+a2b[2]);
        xt[p+14910  ] = a3*(hid*a2w[3]+a2b[3]);
    }
    __syncthreads();
    int tyy=tid>>4, txx=tid&15;
    int r0=tyy*4, c0=txx*4;
    float acc[16];
    #pragma unroll
    for (int i=0;i<16;i++) acc[i]=0.f;
    for (int c=0;c<4;c++){
        float wr[49];
        #pragma unroll
        for (int k=0;k<49;k++) wr[k]=wsm[c*49+k];
        const float* tb = &xt[c*4970];
        #pragma unroll
        for (int r=0;r<10;r++){
            float rv[10];
            #pragma unroll
            for (int j=0;j<10;j++) rv[j]=tb[(r0+r)*71 + c0+j];
            #pragma unroll
            for (int dy=0;dy<4;dy++){
                int ky=r-dy;
                if (ky>=0 && ky<7){
                    #pragma unroll
                    for (int dx=0;dx<4;dx++){
                        float a=acc[dy*4+dx];
                        #pragma unroll
                        for (int kx=0;kx<7;kx++) a += rv[dx+kx]*wr[ky*7+kx];
                        acc[dy*4+dx]=a;
                    }
                }
            }
        }
    }
    int oy=blockIdx.y*64 + r0, ox=blockIdx.x*64 + c0;
    float s=0.f, q=0.f;
    #pragma unroll
    for (int dy=0;dy<4;dy++){
        float4 v = make_float4(acc[dy*4],acc[dy*4+1],acc[dy*4+2],acc[dy*4+3]);
        *(float4*)&s1[(size_t)b*65536 + (size_t)(oy+dy)*256 + ox] = v;
        s += v.x+v.y+v.z+v.w;
        q += v.x*v.x+v.y*v.y+v.z*v.z+v.w*v.w;
    }
    s=wred(s); q=wred(q);
    if ((tid&31)==0){ atomicAdd(&ssum,s); atomicAdd(&ssq,q); }
    __syncthreads();
    if (tid==0){ atomicAdd(&g_sumA[SS1],(double)ssum); atomicAdd(&g_sqA[SS1],(double)ssq); }
}

// ---------------- s2w: conv7x7 1->4 over bn-relu(s1), stats + WRITE raw s2 ----
// block 256 = 4 oc * 64 threads (8x8), each 4x4 -> out tile 32x32. grid (8,8,128)
__global__ void k_s2w(const float* __restrict__ s1, const float* __restrict__ w,
                      float* __restrict__ s2){
    __shared__ float t[38*39];
    __shared__ float wsm[196];
    __shared__ float sc1_, sh1_;
    __shared__ float ssum[4], ssq[4];
    int tid = threadIdx.x;
    int b = blockIdx.z;
    if (tid<196) wsm[tid]=w[tid];
    if (tid==0) bn_scale(SS1, N1, sc1_, sh1_);
    if (tid<4){ ssum[tid]=0.f; ssq[tid]=0.f; }
    __syncthreads();
    int y0 = blockIdx.y*32 - 3, x0 = blockIdx.x*32 - 3;
    const float* sb = s1 + (size_t)b*65536;
    for (int i=tid; i<1444; i+=256){
        int r=i/38, cc=i%38;
        int sy=min(max(y0+r,0),255), sx=min(max(x0+cc,0),255);
        t[r*39+cc] = fmaxf(sb[sy*256+sx]*sc1_+sh1_, 0.f);
    }
    __syncthreads();
    int oc = tid>>6, t64 = tid&63;
    int tyy = t64>>3, txx = t64&7;
    int r0=tyy*4, c0=txx*4;
    float wr[49];
    #pragma unroll
    for (int k=0;k<49;k++) wr[k]=wsm[oc*49+k];
    float acc[16];
    #pragma unroll
    for (int i=0;i<16;i++) acc[i]=0.f;
    #pragma unroll
    for (int r=0;r<10;r++){
        float rv[10];
        #pragma unroll
        for (int j=0;j<10;j++) rv[j]=t[(r0+r)*39 + c0+j];
        #pragma unroll
        for (int dy=0;dy<4;dy++){
            int ky=r-dy;
            if (ky>=0 && ky<7){
                #pragma unroll
                for (int dx=0;dx<4;dx++){
                    float a=acc[dy*4+dx];
                    #pragma unroll
                    for (int kx=0;kx<7;kx++) a += rv[dx+kx]*wr[ky*7+kx];
                    acc[dy*4+dx]=a;
                }
            }
        }
    }
    // write raw s2 + stats
    int oy = blockIdx.y*32 + r0, ox = blockIdx.x*32 + c0;
    size_t base = (size_t)b*262144 + (size_t)oc*65536;
    float s=0.f,q=0.f;
    #pragma unroll
    for (int dy=0;dy<4;dy++){
        float4 v = make_float4(acc[dy*4],acc[dy*4+1],acc[dy*4+2],acc[dy*4+3]);
        *(float4*)&s2[base + (size_t)(oy+dy)*256 + ox] = v;
        s += v.x+v.y+v.z+v.w;
        q += v.x*v.x+v.y*v.y+v.z*v.z+v.w*v.w;
    }
    s=wred(s); q=wred(q);
    if ((tid&31)==0){ atomicAdd(&ssum[oc],s); atomicAdd(&ssq[oc],q); }
    __syncthreads();
    if (tid<4){
        atomicAdd(&g_sumA[SS2+tid],(double)ssum[tid]);
        atomicAdd(&g_sqA[SS2+tid], (double)ssq[tid]);
    }
}

// ---------------- pool1e: streaming xg recompute + sigmoid(bn(s2)) gate + maxpool
// one thread per pooled (b,oy,ox), handles all 4 channels. 2.1M threads.
__global__ void k_pool1e(const float* __restrict__ h1, const float* __restrict__ s2,
                         const float* __restrict__ caw1, const float* __restrict__ cab1,
                         const float* __restrict__ caw2, const float* __restrict__ cab2,
                         float* __restrict__ p1){
    __shared__ float scA[4], shA[4], sc2[4], sh2[4];
    __shared__ float a1w[4], a2w[4], a2b[4];
    __shared__ float a1b;
    int tid = threadIdx.x;
    if (tid<4){
        bn_scale(S1CH+tid, N1, scA[tid], shA[tid]);
        bn_scale(SS2+tid,  N1, sc2[tid], sh2[tid]);
        a1w[tid]=caw1[tid]; a2w[tid]=caw2[tid]; a2b[tid]=cab2[tid];
    }
    if (tid==0) a1b=cab1[0];
    __syncthreads();
    int idx = blockIdx.x*256 + tid;   // 2097152 exact
    int ox = idx & 127; int oy = (idx>>7)&127; int b = idx>>14;
    size_t pix = (size_t)b*262144 + (size_t)(2*oy)*256 + 2*ox;
    float m[4] = {-1e30f,-1e30f,-1e30f,-1e30f};
    #pragma unroll
    for (int dy=0;dy<2;dy++){
        size_t rowo = pix + (size_t)dy*256;
        float2 h[4], g[4];
        #pragma unroll
        for (int c=0;c<4;c++){
            h[c] = *(const float2*)&h1[rowo + (size_t)c*65536];
            g[c] = *(const float2*)&s2[rowo + (size_t)c*65536];
        }
        #pragma unroll
        for (int dx=0;dx<2;dx++){
            float a[4];
            #pragma unroll
            for (int c=0;c<4;c++){
                float hv = dx? h[c].y : h[c].x;
                a[c] = fmaxf(hv*scA[c]+shA[c], 0.f);
            }
            float hid = fmaxf(a1b + a[0]*a1w[0]+a[1]*a1w[1]+a[2]*a1w[2]+a[3]*a1w[3], 0.f);
            #pragma unroll
            for (int c=0;c<4;c++){
                float gv = dx? g[c].y : g[c].x;
                float sv = sigm(gv*sc2[c]+sh2[c]);
                float xv = a[c]*(hid*a2w[c]+a2b[c]);
                m[c] = fmaxf(m[c], xv*sv);
            }
        }
    }
    size_t ob = (size_t)b*65536 + (size_t)oy*128 + ox;
    #pragma unroll
    for (int c=0;c<4;c++) p1[ob + (size_t)c*16384] = m[c];
}

// ---------------- conv2: 4->8, 3x3, s2, p1 + stats ----------------
__global__ void k_conv2(const float* __restrict__ in, const float* __restrict__ w,
                        const float* __restrict__ bias, float* __restrict__ out){
    __shared__ float t[4][33][33];
    __shared__ float ws[288];
    __shared__ float wb[8];
    __shared__ float ssum[8], ssq[8];
    int tid = threadIdx.y*16+threadIdx.x;
    int b = blockIdx.z;
    for (int i=tid;i<288;i+=256) ws[i]=w[i];
    if (tid<8){ wb[tid]=bias[tid]; ssum[tid]=0.f; ssq[tid]=0.f; }
    int iy0 = blockIdx.y*32-1, ix0 = blockIdx.x*32-1;
    for (int i=tid; i<4*1089; i+=256){
        int c=i/1089; int r=(i%1089)/33; int cc=i%33;
        int iy=iy0+r, ix=ix0+cc;
        float v=0.f;
        if (iy>=0&&iy<128&&ix>=0&&ix<128)
            v = in[(size_t)b*65536 + (size_t)c*16384 + iy*128+ix];
        t[c][r][cc]=v;
    }
    __syncthreads();
    int ty=threadIdx.y, tx=threadIdx.x;
    float acc[8];
    #pragma unroll
    for (int oc=0;oc<8;oc++) acc[oc]=wb[oc];
    #pragma unroll
    for (int ci=0;ci<4;ci++)
        #pragma unroll
        for (int ky=0;ky<3;ky++)
            #pragma unroll
            for (int kx=0;kx<3;kx++){
                float v = t[ci][2*ty+ky][2*tx+kx];
                #pragma unroll
                for (int oc=0;oc<8;oc++) acc[oc]+=v*ws[oc*36+ci*9+ky*3+kx];
            }
    int oy = blockIdx.y*16+ty, ox = blockIdx.x*16+tx;
    #pragma unroll
    for (int oc=0;oc<8;oc++)
        out[(size_t)b*32768 + (size_t)oc*4096 + oy*64+ox] = acc[oc];
    #pragma unroll
    for (int oc=0;oc<8;oc++){
        float s=wred(acc[oc]), q=wred(acc[oc]*acc[oc]);
        if ((tid&31)==0){ atomicAdd(&ssum[oc],s); atomicAdd(&ssq[oc],q); }
    }
    __syncthreads();
    if (tid<8){
        atomicAdd(&g_sumA[S2CH+tid], (double)ssum[tid]);
        atomicAdd(&g_sqA[S2CH+tid],  (double)ssq[tid]);
    }
}

// ---------------- pool2 = maxpool2(relu(bn(r2))) ----------------
__global__ void k_pool2(const float* __restrict__ r2, float* __restrict__ p2){
    __shared__ float sc[8], sh[8];
    int tid=threadIdx.x;
    if (tid<8) bn_scale(S2CH+tid, N2, sc[tid], sh[tid]);
    __syncthreads();
    int idx = blockIdx.x*256+tid;
    int ox=idx&31; int oy=(idx>>5)&31; int c=(idx>>10)&7; int b=idx>>13;
    size_t base = (size_t)b*32768 + (size_t)c*4096;
    float m=-1e30f;
    #pragma unroll
    for (int dy=0;dy<2;dy++)
        #pragma unroll
        for (int dx=0;dx<2;dx++){
            float v = r2[base + (size_t)(2*oy+dy)*64 + (2*ox+dx)]*sc[c]+sh[c];
            v = v>0.f?v:0.f;
            m = fmaxf(m,v);
        }
    p2[(size_t)b*8192 + (size_t)c*1024 + oy*32+ox] = m;
}

// ---------------- conv3: 8->16, 3x3, s1, p1 + stats ----------------
__global__ void k_conv3(const float* __restrict__ in, const float* __restrict__ w,
                        const float* __restrict__ bias, float* __restrict__ out){
    __shared__ float t[8][18][18];
    __shared__ float ws[1152];
    __shared__ float wb[16];
    __shared__ float ssum[16], ssq[16];
    int tid = threadIdx.y*16+threadIdx.x;
    int b = blockIdx.z;
    for (int i=tid;i<1152;i+=256) ws[i]=w[i];
    if (tid<16){ wb[tid]=bias[tid]; ssum[tid]=0.f; ssq[tid]=0.f; }
    int iy0 = blockIdx.y*16-1, ix0 = blockIdx.x*16-1;
    for (int i=tid;i<8*324;i+=256){
        int c=i/324; int r=(i%324)/18; int cc=i%18;
        int iy=iy0+r, ix=ix0+cc;
        float v=0.f;
        if (iy>=0&&iy<32&&ix>=0&&ix<32)
            v = in[(size_t)b*8192 + (size_t)c*1024 + iy*32+ix];
        t[c][r][cc]=v;
    }
    __syncthreads();
    int ty=threadIdx.y, tx=threadIdx.x;
    float acc[16];
    #pragma unroll
    for (int oc=0;oc<16;oc++) acc[oc]=wb[oc];
    #pragma unroll
    for (int ci=0;ci<8;ci++)
        #pragma unroll
        for (int ky=0;ky<3;ky++)
            #pragma unroll
            for (int kx=0;kx<3;kx++){
                float v=t[ci][ty+ky][tx+kx];
                #pragma unroll
                for (int oc=0;oc<16;oc++) acc[oc]+=v*ws[oc*72+ci*9+ky*3+kx];
            }
    int oy=blockIdx.y*16+ty, ox=blockIdx.x*16+tx;
    #pragma unroll
    for (int oc=0;oc<16;oc++)
        out[(size_t)b*16384 + (size_t)oc*1024 + oy*32+ox]=acc[oc];
    #pragma unroll
    for (int oc=0;oc<16;oc++){
        float s=wred(acc[oc]), q=wred(acc[oc]*acc[oc]);
        if ((tid&31)==0){ atomicAdd(&ssum[oc],s); atomicAdd(&ssq[oc],q); }
    }
    __syncthreads();
    if (tid<16){
        atomicAdd(&g_sumA[S3+tid], (double)ssum[tid]);
        atomicAdd(&g_sqA[S3+tid],  (double)ssq[tid]);
    }
}

// ---------------- pool3 = maxpool2(relu(bn(r3))) ----------------
__global__ void k_pool3(const float* __restrict__ r3, float* __restrict__ p3){
    __shared__ float sc[16], sh[16];
    int tid=threadIdx.x;
    if (tid<16) bn_scale(S3+tid, N3, sc[tid], sh[tid]);
    __syncthreads();
    int idx = blockIdx.x*256+tid;
    int ox=idx&15; int oy=(idx>>4)&15; int c=(idx>>8)&15; int b=idx>>12;
    size_t base=(size_t)b*16384 + (size_t)c*1024;
    float m=-1e30f;
    #pragma unroll
    for (int dy=0;dy<2;dy++)
        #pragma unroll
        for (int dx=0;dx<2;dx++){
            float v=r3[base + (size_t)(2*oy+dy)*32 + (2*ox+dx)]*sc[c]+sh[c];
            v=v>0.f?v:0.f;
            m=fmaxf(m,v);
        }
    p3[(size_t)b*4096 + (size_t)c*256 + oy*16+ox]=m;
}

// ---------------- conv4: 16->32, 3x3, s1, p1 + stats ----------------
__global__ void k_conv4(const float* __restrict__ in, const float* __restrict__ w,
                        const float* __restrict__ bias, float* __restrict__ out){
    __shared__ float t[16][18][18];
    __shared__ float ws[4608];
    __shared__ float wb[32];
    __shared__ float ssum[32], ssq[32];
    int tid = threadIdx.y*16+threadIdx.x;
    int b = blockIdx.x;
    for (int i=tid;i<4608;i+=256) ws[i]=w[i];
    if (tid<32){ wb[tid]=bias[tid]; ssum[tid]=0.f; ssq[tid]=0.f; }
    for (int i=tid;i<16*324;i+=256){
        int c=i/324; int r=(i%324)/18; int cc=i%18;
        int iy=r-1, ix=cc-1;
        float v=0.f;
        if (iy>=0&&iy<16&&ix>=0&&ix<16)
            v = in[(size_t)b*4096 + (size_t)c*256 + iy*16+ix];
        t[c][r][cc]=v;
    }
    __syncthreads();
    int ty=threadIdx.y, tx=threadIdx.x;
    float acc[32];
    #pragma unroll
    for (int oc=0;oc<32;oc++) acc[oc]=wb[oc];
    for (int ci=0;ci<16;ci++)
        #pragma unroll
        for (int ky=0;ky<3;ky++)
            #pragma unroll
            for (int kx=0;kx<3;kx++){
                float v=t[ci][ty+ky][tx+kx];
                #pragma unroll
                for (int oc=0;oc<32;oc++) acc[oc]+=v*ws[oc*144+ci*9+ky*3+kx];
            }
    #pragma unroll
    for (int oc=0;oc<32;oc++)
        out[(size_t)b*8192 + (size_t)oc*256 + ty*16+tx]=acc[oc];
    #pragma unroll
    for (int oc=0;oc<32;oc++){
        float s=wred(acc[oc]), q=wred(acc[oc]*acc[oc]);
        if ((tid&31)==0){ atomicAdd(&ssum[oc],s); atomicAdd(&ssq[oc],q); }
    }
    __syncthreads();
    if (tid<32){
        atomicAdd(&g_sumA[S4+tid], (double)ssum[tid]);
        atomicAdd(&g_sqA[S4+tid],  (double)ssq[tid]);
    }
}

// ---------------- conv5: 1x1, relu(bn(r4)) -> 16 + stats ----------------
__global__ void k_conv5(const float* __restrict__ r4, const float* __restrict__ w,
                        const float* __restrict__ bias, float* __restrict__ out){
    __shared__ float sc[32], sh[32];
    __shared__ float ws[512];
    __shared__ float wb[16];
    __shared__ float ssum[16], ssq[16];
    int tid=threadIdx.x;
    if (tid<32) bn_scale(S4+tid, N4, sc[tid], sh[tid]);
    for (int i=tid;i<512;i+=256) ws[i]=w[i];
    if (tid<16){ wb[tid]=bias[tid]; ssum[tid]=0.f; ssq[tid]=0.f; }
    __syncthreads();
    int idx = blockIdx.x*256+tid;
    int b = idx>>8; int p = idx&255;
    float a[32];
    #pragma unroll
    for (int ci=0;ci<32;ci++){
        float v = r4[(size_t)b*8192 + (size_t)ci*256 + p]*sc[ci]+sh[ci];
        a[ci]=v>0.f?v:0.f;
    }
    float accs[16];
    #pragma unroll
    for (int oc=0;oc<16;oc++){
        float acc=wb[oc];
        #pragma unroll
        for (int ci=0;ci<32;ci++) acc += a[ci]*ws[oc*32+ci];
        out[(size_t)b*4096 + (size_t)oc*256 + p]=acc;
        accs[oc]=acc;
    }
    #pragma unroll
    for (int oc=0;oc<16;oc++){
        float s=wred(accs[oc]), q=wred(accs[oc]*accs[oc]);
        if ((tid&31)==0){ atomicAdd(&ssum[oc],s); atomicAdd(&ssq[oc],q); }
    }
    __syncthreads();
    if (tid<16){
        atomicAdd(&g_sumA[S5+tid], (double)ssum[tid]);
        atomicAdd(&g_sqA[S5+tid],  (double)ssq[tid]);
    }
}

// ---------------- tok = relu(bn(r5)) transposed to (B,L,D) ----------------
__global__ void k_tok(const float* __restrict__ r5, float* __restrict__ tok){
    __shared__ float sc[16], sh[16];
    int tid=threadIdx.x;
    if (tid<16) bn_scale(S5+tid, N5, sc[tid], sh[tid]);
    __syncthreads();
    int idx = blockIdx.x*256+tid;
    int d = idx&15; int l=(idx>>4)&255; int b=idx>>12;
    float v = r5[(size_t)b*4096 + (size_t)d*256 + l]*sc[d]+sh[d];
    tok[idx] = v>0.f?v:0.f;
}

// ---------------- mamba layer ----------------
#define O_WIN 0
#define O_CW  1024
#define O_CB  1152
#define O_XP  1184
#define O_DTW 2240
#define O_DTB 2272
#define O_AE  2304
#define O_DD  2816
#define O_OW  2848
#define O_LNG 3360
#define O_LNB 3376
#define O_XI  3392
#define O_ZZ  11584
#define O_XC  19776
#define O_DL  27968
#define O_BM  36160
#define O_CM  40256
#define O_YY  44352
#define SM_FLOATS 52544

__global__ void k_mamba(float* __restrict__ tok,
    const float* __restrict__ lng, const float* __restrict__ lnb,
    const float* __restrict__ inw, const float* __restrict__ cw, const float* __restrict__ cb,
    const float* __restrict__ xpw, const float* __restrict__ dtw, const float* __restrict__ dtb,
    const float* __restrict__ alog, const float* __restrict__ dvec, const float* __restrict__ ow)
{
    extern __shared__ float sm[];
    int t = threadIdx.x; int b = blockIdx.x;
    for (int i=t;i<1024;i+=512) sm[O_WIN+i]=inw[i];
    for (int i=t;i<128;i+=512)  sm[O_CW+i]=cw[i];
    for (int i=t;i<1056;i+=512) sm[O_XP+i]=xpw[i];
    for (int i=t;i<512;i+=512){ sm[O_AE+i]=-expf(alog[i]); sm[O_OW+i]=ow[i]; }
    if (t<32){ sm[O_CB+t]=cb[t]; sm[O_DTW+t]=dtw[t]; sm[O_DTB+t]=dtb[t]; sm[O_DD+t]=dvec[t]; }
    if (t<16){ sm[O_LNG+t]=lng[t]; sm[O_LNB+t]=lnb[t]; }
    __syncthreads();

    // step 1: LN + in_proj
    if (t < 256){
        int l=t;
        float v[16];
        const float* tp = tok + ((size_t)b*4096 + (size_t)l*16);
        float mean=0.f;
        #pragma unroll
        for (int d=0;d<16;d++){ v[d]=tp[d]; mean+=v[d]; }
        mean *= 0.0625f;
        float var=0.f;
        #pragma unroll
        for (int d=0;d<16;d++){ float dd=v[d]-mean; var+=dd*dd; }
        var *= 0.0625f;
        float inv = rsqrtf(var+1e-5f);
        #pragma unroll
        for (int d=0;d<16;d++) v[d]=(v[d]-mean)*inv*sm[O_LNG+d]+sm[O_LNB+d];
        for (int j=0;j<64;j++){
            float a=0.f;
            #pragma unroll
            for (int d=0;d<16;d++) a += v[d]*sm[O_WIN+j*16+d];
            if (j<32) sm[O_XI+l*32+j]=a; else sm[O_ZZ+l*32+j-32]=a;
        }
    }
    __syncthreads();

    // step 2: depthwise causal conv + silu
    if (t < 256){
        int l=t;
        for (int d=0;d<32;d++){
            float a = sm[O_CB+d];
            #pragma unroll
            for (int k=0;k<4;k++){
                int ll=l-3+k;
                if (ll>=0) a += sm[O_CW+d*4+k]*sm[O_XI+ll*32+d];
            }
            sm[O_XC+l*32+d] = a*__fdividef(1.f, 1.f+__expf(-a));
        }
    }
    __syncthreads();

    // step 3: x_proj (dt,B,C) + softplus(delta)
    if (t < 256){
        int l=t;
        float xcl[32];
        #pragma unroll
        for (int d=0;d<32;d++) xcl[d]=sm[O_XC+l*32+d];
        float dtv=0.f;
        #pragma unroll
        for (int d=0;d<32;d++) dtv += xcl[d]*sm[O_XP+d];
        for (int n=0;n<16;n++){
            float bb=0.f, cc=0.f;
            #pragma unroll
            for (int d=0;d<32;d++){
                bb += xcl[d]*sm[O_XP+(1+n)*32+d];
                cc += xcl[d]*sm[O_XP+(17+n)*32+d];
            }
            sm[O_BM+l*16+n]=bb; sm[O_CM+l*16+n]=cc;
        }
        for (int d=0;d<32;d++){
            float pre = dtv*sm[O_DTW+d]+sm[O_DTB+d];
            float sp = (pre>20.f)? pre : log1pf(__expf(pre));
            sm[O_DL+l*32+d]=sp;
        }
    }
    __syncthreads();

    // step 4: selective scan, chunked (8) with deferred shuffle reduction
    {
        int d = t>>4, n = t&15;
        float A  = sm[O_AE+d*16+n];
        float Dv = sm[O_DD+d];
        float h=0.f;
        for (int l0=0;l0<256;l0+=8){
            float cbuf[8];
            #pragma unroll
            for (int j=0;j<8;j++){
                int l=l0+j;
                float dl  = sm[O_DL+l*32+d];
                float xcv = sm[O_XC+l*32+d];
                float dA  = __expf(dl*A);
                h = dA*h + dl*sm[O_BM+l*16+n]*xcv;
                cbuf[j] = h*sm[O_CM+l*16+n];
            }
            #pragma unroll
            for (int j=0;j<8;j++){
                float c=cbuf[j];
                c += __shfl_xor_sync(0xffffffffu, c, 1);
                c += __shfl_xor_sync(0xffffffffu, c, 2);
                c += __shfl_xor_sync(0xffffffffu, c, 4);
                c += __shfl_xor_sync(0xffffffffu, c, 8);
                cbuf[j]=c;
            }
            if (n==0){
                #pragma unroll
                for (int j=0;j<8;j++){
                    int l=l0+j;
                    sm[O_YY+l*32+d] = cbuf[j] + sm[O_XC+l*32+d]*Dv;
                }
            }
        }
    }
    __syncthreads();

    // step 5: gate + out_proj, residual add
    if (t < 256){
        int l=t;
        float yv[32];
        #pragma unroll
        for (int d=0;d<32;d++){
            float zv=sm[O_ZZ+l*32+d];
            yv[d]=sm[O_YY+l*32+d]*(zv*__fdividef(1.f,1.f+__expf(-zv)));
        }
        float* tp = tok + ((size_t)b*4096 + (size_t)l*16);
        #pragma unroll
        for (int j=0;j<16;j++){
            float a=0.f;
            #pragma unroll
            for (int d=0;d<32;d++) a += yv[d]*sm[O_OW+j*32+d];
            tp[j] += a;
        }
    }
}

// ---------------- head: mean-pool + linear + LN ----------------
__global__ void k_head(const float* __restrict__ tok, const float* __restrict__ pw,
                       const float* __restrict__ pb, const float* __restrict__ fg,
                       const float* __restrict__ fb, float* __restrict__ out){
    __shared__ float pooled[16];
    __shared__ float red[16];
    __shared__ float s_mean, s_inv;
    int t=threadIdx.x, b=blockIdx.x;
    if (t<16){
        float s=0.f;
        const float* tp = tok + (size_t)b*4096 + t;
        for (int l=0;l<256;l++) s += tp[l*16];
        pooled[t] = s*(1.f/256.f);
    }
    __syncthreads();
    float lg = pb[t];
    #pragma unroll
    for (int d=0;d<16;d++) lg += pooled[d]*pw[t*16+d];
    float s1v = wred(lg);
    float s2v = wred(lg*lg);
    int w = t>>5;
    if ((t&31)==0){ red[w]=s1v; red[8+w]=s2v; }
    __syncthreads();
    if (t==0){
        float a=0.f,q=0.f;
        for (int i=0;i<8;i++){a+=red[i]; q+=red[8+i];}
        float m=a*(1.f/256.f);
        float v=q*(1.f/256.f)-m*m;
        s_mean=m; s_inv=rsqrtf(v+1e-5f);
    }
    __syncthreads();
    out[b*256+t] = (lg-s_mean)*s_inv*fg[t]+fb[t];
}

// ---------------- launch ----------------
extern "C" void kernel_launch(void* const* d_in, const int* in_sizes, int n_in,
                              void* d_out, int out_size){
    const float* x    = (const float*)d_in[0];
    const float* c1w  = (const float*)d_in[1];
    const float* c1b  = (const float*)d_in[2];
    const float* caw1 = (const float*)d_in[3];
    const float* cab1 = (const float*)d_in[4];
    const float* caw2 = (const float*)d_in[5];
    const float* cab2 = (const float*)d_in[6];
    const float* sw1  = (const float*)d_in[7];
    const float* sw2  = (const float*)d_in[8];
    const float* c2w  = (const float*)d_in[9];
    const float* c2b  = (const float*)d_in[10];
    const float* c3w  = (const float*)d_in[11];
    const float* c3b  = (const float*)d_in[12];
    const float* c4w  = (const float*)d_in[13];
    const float* c4b  = (const float*)d_in[14];
    const float* c5w  = (const float*)d_in[15];
    const float* c5b  = (const float*)d_in[16];
    const float* mlng = (const float*)d_in[17];
    const float* mlnb = (const float*)d_in[18];
    const float* minw = (const float*)d_in[19];
    const float* mcw  = (const float*)d_in[20];
    const float* mcb  = (const float*)d_in[21];
    const float* mxp  = (const float*)d_in[22];
    const float* mdtw = (const float*)d_in[23];
    const float* mdtb = (const float*)d_in[24];
    const float* mal  = (const float*)d_in[25];
    const float* mD   = (const float*)d_in[26];
    const float* mow  = (const float*)d_in[27];
    const float* pw   = (const float*)d_in[28];
    const float* pb   = (const float*)d_in[29];
    const float* fg   = (const float*)d_in[30];
    const float* fb   = (const float*)d_in[31];
    float* out = (float*)d_out;

    float *h1, *s1, *s2, *p1, *r2, *p2, *r3, *p3, *r4, *r5, *tok;
    cudaGetSymbolAddress((void**)&h1, g_h1);
    cudaGetSymbolAddress((void**)&s1, g_s1);
    cudaGetSymbolAddress((void**)&s2, g_s2);
    cudaGetSymbolAddress((void**)&p1, g_p1);
    cudaGetSymbolAddress((void**)&r2, g_r2);
    cudaGetSymbolAddress((void**)&p2, g_p2);
    cudaGetSymbolAddress((void**)&r3, g_r3);
    cudaGetSymbolAddress((void**)&p3, g_p3);
    cudaGetSymbolAddress((void**)&r4, g_r4);
    cudaGetSymbolAddress((void**)&r5, g_r5);
    cudaGetSymbolAddress((void**)&tok, g_tok);

    size_t smem_mamba = SM_FLOATS * sizeof(float);
    cudaFuncSetAttribute(k_mamba, cudaFuncAttributeMaxDynamicSharedMemorySize, (int)smem_mamba);
    size_t smem_s1f = 4*4970*sizeof(float);           // 79520
    cudaFuncSetAttribute(k_s1f, cudaFuncAttributeMaxDynamicSharedMemorySize, (int)smem_s1f);

    k_zero<<<1,128>>>();
    k_conv1<<<dim3(8,8,128), dim3(16,16)>>>(x, c1w, c1b, h1);
    k_s1f<<<dim3(4,4,128), 256, smem_s1f>>>(h1, sw1, caw1, cab1, caw2, cab2, s1);
    k_s2w<<<dim3(8,8,128), 256>>>(s1, sw2, s2);
    k_pool1e<<<8192,256>>>(h1, s2, caw1, cab1, caw2, cab2, p1);
    k_conv2<<<dim3(4,4,128), dim3(16,16)>>>(p1, c2w, c2b, r2);
    k_pool2<<<4096,256>>>(r2, p2);
    k_conv3<<<dim3(2,2,128), dim3(16,16)>>>(p2, c3w, c3b, r3);
    k_pool3<<<2048,256>>>(r3, p3);
    k_conv4<<<128, dim3(16,16)>>>(p3, c4w, c4b, r4);
    k_conv5<<<128,256>>>(r4, c5w, c5b, r5);
    k_tok<<<2048,256>>>(r5, tok);
    for (int layer=0; layer<2; layer++){
        k_mamba<<<128,512,smem_mamba>>>(tok,
            mlng+layer*16, mlnb+layer*16, minw+layer*1024,
            mcw+layer*128, mcb+layer*32, mxp+layer*1056,
            mdtw+layer*32, mdtb+layer*32, mal+layer*512,
            mD+layer*32, mow+layer*512);
    }
    k_head<<<128,256>>>(tok, pw, pb, fg, fb, out);
}

// round 5
// speedup vs baseline: 1.7947x; 1.0239x over previous
#include <cuda_runtime.h>
#include <cuda_bf16.h>
#include <math.h>

// ---------------- constants ----------------
#define N1  8388608.0   // 128*256*256 per channel
#define N2  524288.0    // 128*64*64
#define N3  131072.0    // 128*32*32
#define N4  32768.0     // 128*16*16
#define N5  32768.0

// bn stat offsets
#define S1CH 0   // 4 ch
#define SS1  8   // 1 ch
#define SS2  12  // 4 ch
#define S2CH 16  // 8 ch
#define S3   24  // 16 ch
#define S4   40  // 32 ch
#define S5   72  // 16 ch

// ---------------- scratch ----------------
__device__ float g_h1[33554432];   // (128,4,256,256) conv1 raw
__device__ float g_s2[33554432];   // (128,4,256,256) raw s2 conv
__device__ float g_s1[8388608];    // (128,1,256,256) raw s1 conv
__device__ float g_p1[8388608];    // (128,4,128,128)
__device__ float g_r2[4194304];    // (128,8,64,64)
__device__ float g_p2[1048576];    // (128,8,32,32)
__device__ float g_r3[2097152];    // (128,16,32,32)
__device__ float g_p3[524288];     // (128,16,16,16)
__device__ float g_r4[1048576];    // (128,32,16,16)
__device__ float g_r5[524288];     // (128,16,16,16)
__device__ float g_tok[524288];    // (128,256,16)
__device__ double g_sumA[128];
__device__ double g_sqA[128];

// ---------------- helpers ----------------
__device__ __forceinline__ float wred(float v){
    #pragma unroll
    for (int o=16;o>0;o>>=1) v += __shfl_down_sync(0xffffffffu, v, o);
    return v;
}
__device__ __forceinline__ void bn_scale(int off, double N, float& sc, float& sh){
    double m = g_sumA[off]/N;
    double v = g_sqA[off]/N - m*m;
    double s = 1.0/sqrt(v+1e-5);
    sc = (float)s; sh = (float)(-m*s);
}
__device__ __forceinline__ float sigm(float x){
    return __fdividef(1.f, 1.f + __expf(-x));
}

__global__ void k_zero(){
    int t = threadIdx.x;
    if (t < 128){ g_sumA[t]=0.0; g_sqA[t]=0.0; }
}

// ---------------- conv1: 1->4, 5x5, s2, p2, register-tiled 2x2 ----------------
__global__ void k_conv1(const float* __restrict__ x, const float* __restrict__ w,
                        const float* __restrict__ bias, float* __restrict__ out){
    __shared__ float t[68][69];
    __shared__ float ws[100];
    __shared__ float wb[4];
    __shared__ float ssum[4], ssq[4];
    int tid = threadIdx.y*16 + threadIdx.x;
    int b = blockIdx.z;
    if (tid < 100) ws[tid] = w[tid];
    if (tid < 4){ wb[tid] = bias[tid]; ssum[tid]=0.f; ssq[tid]=0.f; }
    int oy0 = blockIdx.y*32, ox0 = blockIdx.x*32;
    int iy0 = 2*oy0 - 2, ix0 = 2*ox0 - 2;
    const float* xb = x + (size_t)b*262144;
    for (int i = tid; i < 68*68; i += 256){
        int r = i/68, c = i%68;
        int iy = iy0 + r, ix = ix0 + c;
        float v = 0.f;
        if (iy>=0 && iy<512 && ix>=0 && ix<512) v = xb[iy*512+ix];
        t[r][c] = v;
    }
    __syncthreads();
    int ty=threadIdx.y, tx=threadIdx.x;
    float win[7][7];
    #pragma unroll
    for (int r=0;r<7;r++)
        #pragma unroll
        for (int c=0;c<7;c++) win[r][c] = t[4*ty+r][4*tx+c];
    #pragma unroll
    for (int oc=0; oc<4; oc++){
        float a00=wb[oc], a01=wb[oc], a10=wb[oc], a11=wb[oc];
        #pragma unroll
        for (int ky=0; ky<5; ky++)
            #pragma unroll
            for (int kx=0; kx<5; kx++){
                float wv = ws[oc*25+ky*5+kx];
                a00 += win[ky  ][kx  ]*wv;
                a01 += win[ky  ][kx+2]*wv;
                a10 += win[ky+2][kx  ]*wv;
                a11 += win[ky+2][kx+2]*wv;
            }
        size_t base = (size_t)b*262144 + (size_t)oc*65536;
        int oy = oy0 + 2*ty, ox = ox0 + 2*tx;
        *(float2*)&out[base + (size_t)oy*256 + ox]     = make_float2(a00,a01);
        *(float2*)&out[base + (size_t)(oy+1)*256 + ox] = make_float2(a10,a11);
        float s = a00+a01+a10+a11;
        float q = a00*a00+a01*a01+a10*a10+a11*a11;
        s = wred(s); q = wred(q);
        if ((tid&31)==0){ atomicAdd(&ssum[oc], s); atomicAdd(&ssq[oc], q); }
    }
    __syncthreads();
    if (tid < 4){
        atomicAdd(&g_sumA[S1CH+tid], (double)ssum[tid]);
        atomicAdd(&g_sqA[S1CH+tid],  (double)ssq[tid]);
    }
}

// ---------------- s1 fused: xg inline from h1 (channel-sequential smem),
//                  conv7x7 4->1, stats. smem = 70*71 floats per pass ---------
__global__ void __launch_bounds__(256) k_s1f(
                      const float* __restrict__ h1, const float* __restrict__ w,
                      const float* __restrict__ caw1, const float* __restrict__ cab1,
                      const float* __restrict__ caw2, const float* __restrict__ cab2,
                      float* __restrict__ s1){
    extern __shared__ float xt[];   // 70*71 = 4970 floats
    __shared__ float wsm[196];
    __shared__ float sc[4], sh[4];
    __shared__ float a1w[4], a2w[4], a2b[4];
    __shared__ float a1b;
    __shared__ float ssum, ssq;
    int tid = threadIdx.x;
    int b = blockIdx.z;
    if (tid<196) wsm[tid]=w[tid];
    if (tid<4){ bn_scale(S1CH+tid, N1, sc[tid], sh[tid]);
                a1w[tid]=caw1[tid]; a2w[tid]=caw2[tid]; a2b[tid]=cab2[tid]; }
    if (tid==0){ a1b=cab1[0]; ssum=0.f; ssq=0.f; }
    __syncthreads();
    int y0 = blockIdx.y*64 - 3, x0 = blockIdx.x*64 - 3;
    const float* hb = h1 + (size_t)b*262144;
    int tyy=tid>>4, txx=tid&15;
    int r0=tyy*4, c0=txx*4;
    float acc[16];
    #pragma unroll
    for (int i=0;i<16;i++) acc[i]=0.f;
    #pragma unroll
    for (int c=0;c<4;c++){
        if (c) __syncthreads();   // previous pass's conv reads done
        for (int i=tid; i<4900; i+=256){
            int r=i/70, cc=i%70;
            int sy=min(max(y0+r,0),255), sx=min(max(x0+cc,0),255);
            int off = sy*256+sx;
            float a0 = fmaxf(hb[off         ]*sc[0]+sh[0], 0.f);
            float a1 = fmaxf(hb[off+  65536 ]*sc[1]+sh[1], 0.f);
            float a2 = fmaxf(hb[off+ 131072 ]*sc[2]+sh[2], 0.f);
            float a3 = fmaxf(hb[off+ 196608 ]*sc[3]+sh[3], 0.f);
            float hid = fmaxf(a1b + a0*a1w[0]+a1*a1w[1]+a2*a1w[2]+a3*a1w[3], 0.f);
            float ac = (c==0)?a0:(c==1)?a1:(c==2)?a2:a3;
            xt[r*71+cc] = ac*(hid*a2w[c]+a2b[c]);
        }
        __syncthreads();
        float wr[49];
        #pragma unroll
        for (int k=0;k<49;k++) wr[k]=wsm[c*49+k];
        #pragma unroll
        for (int r=0;r<10;r++){
            float rv[10];
            #pragma unroll
            for (int j=0;j<10;j++) rv[j]=xt[(r0+r)*71 + c0+j];
            #pragma unroll
            for (int dy=0;dy<4;dy++){
                int ky=r-dy;
                if (ky>=0 && ky<7){
                    #pragma unroll
                    for (int dx=0;dx<4;dx++){
                        float a=acc[dy*4+dx];
                        #pragma unroll
                        for (int kx=0;kx<7;kx++) a += rv[dx+kx]*wr[ky*7+kx];
                        acc[dy*4+dx]=a;
                    }
                }
            }
        }
    }
    int oy=blockIdx.y*64 + r0, ox=blockIdx.x*64 + c0;
    float s=0.f, q=0.f;
    #pragma unroll
    for (int dy=0;dy<4;dy++){
        float4 v = make_float4(acc[dy*4],acc[dy*4+1],acc[dy*4+2],acc[dy*4+3]);
        *(float4*)&s1[(size_t)b*65536 + (size_t)(oy+dy)*256 + ox] = v;
        s += v.x+v.y+v.z+v.w;
        q += v.x*v.x+v.y*v.y+v.z*v.z+v.w*v.w;
    }
    s=wred(s); q=wred(q);
    if ((tid&31)==0){ atomicAdd(&ssum,s); atomicAdd(&ssq,q); }
    __syncthreads();
    if (tid==0){ atomicAdd(&g_sumA[SS1],(double)ssum); atomicAdd(&g_sqA[SS1],(double)ssq); }
}

// ---------------- s2w: conv7x7 1->4 over bn-relu(s1), stats + WRITE raw s2 ----
__global__ void k_s2w(const float* __restrict__ s1, const float* __restrict__ w,
                      float* __restrict__ s2){
    __shared__ float t[38*39];
    __shared__ float wsm[196];
    __shared__ float sc1_, sh1_;
    __shared__ float ssum[4], ssq[4];
    int tid = threadIdx.x;
    int b = blockIdx.z;
    if (tid<196) wsm[tid]=w[tid];
    if (tid==0) bn_scale(SS1, N1, sc1_, sh1_);
    if (tid<4){ ssum[tid]=0.f; ssq[tid]=0.f; }
    __syncthreads();
    int y0 = blockIdx.y*32 - 3, x0 = blockIdx.x*32 - 3;
    const float* sb = s1 + (size_t)b*65536;
    for (int i=tid; i<1444; i+=256){
        int r=i/38, cc=i%38;
        int sy=min(max(y0+r,0),255), sx=min(max(x0+cc,0),255);
        t[r*39+cc] = fmaxf(sb[sy*256+sx]*sc1_+sh1_, 0.f);
    }
    __syncthreads();
    int oc = tid>>6, t64 = tid&63;
    int tyy = t64>>3, txx = t64&7;
    int r0=tyy*4, c0=txx*4;
    float wr[49];
    #pragma unroll
    for (int k=0;k<49;k++) wr[k]=wsm[oc*49+k];
    float acc[16];
    #pragma unroll
    for (int i=0;i<16;i++) acc[i]=0.f;
    #pragma unroll
    for (int r=0;r<10;r++){
        float rv[10];
        #pragma unroll
        for (int j=0;j<10;j++) rv[j]=t[(r0+r)*39 + c0+j];
        #pragma unroll
        for (int dy=0;dy<4;dy++){
            int ky=r-dy;
            if (ky>=0 && ky<7){
                #pragma unroll
                for (int dx=0;dx<4;dx++){
                    float a=acc[dy*4+dx];
                    #pragma unroll
                    for (int kx=0;kx<7;kx++) a += rv[dx+kx]*wr[ky*7+kx];
                    acc[dy*4+dx]=a;
                }
            }
        }
    }
    int oy = blockIdx.y*32 + r0, ox = blockIdx.x*32 + c0;
    size_t base = (size_t)b*262144 + (size_t)oc*65536;
    float s=0.f,q=0.f;
    #pragma unroll
    for (int dy=0;dy<4;dy++){
        float4 v = make_float4(acc[dy*4],acc[dy*4+1],acc[dy*4+2],acc[dy*4+3]);
        *(float4*)&s2[base + (size_t)(oy+dy)*256 + ox] = v;
        s += v.x+v.y+v.z+v.w;
        q += v.x*v.x+v.y*v.y+v.z*v.z+v.w*v.w;
    }
    s=wred(s); q=wred(q);
    if ((tid&31)==0){ atomicAdd(&ssum[oc],s); atomicAdd(&ssq[oc],q); }
    __syncthreads();
    if (tid<4){
        atomicAdd(&g_sumA[SS2+tid],(double)ssum[tid]);
        atomicAdd(&g_sqA[SS2+tid], (double)ssq[tid]);
    }
}

// ---------------- pool1v: streaming xg + sigmoid(bn(s2)) gate + maxpool,
// float4 loads. one thread = 2 pooled x, 4 channels. 1M threads.
__global__ void k_pool1v(const float* __restrict__ h1, const float* __restrict__ s2,
                         const float* __restrict__ caw1, const float* __restrict__ cab1,
                         const float* __restrict__ caw2, const float* __restrict__ cab2,
                         float* __restrict__ p1){
    __shared__ float scA[4], shA[4], sc2[4], sh2[4];
    __shared__ float a1w[4], a2w[4], a2b[4];
    __shared__ float a1b;
    int tid = threadIdx.x;
    if (tid<4){
        bn_scale(S1CH+tid, N1, scA[tid], shA[tid]);
        bn_scale(SS2+tid,  N1, sc2[tid], sh2[tid]);
        a1w[tid]=caw1[tid]; a2w[tid]=caw2[tid]; a2b[tid]=cab2[tid];
    }
    if (tid==0) a1b=cab1[0];
    __syncthreads();
    int idx = blockIdx.x*256 + tid;   // 1048576 exact
    int xp2 = idx & 63;               // pooled-x pair: pooled x = 2*xp2
    int oy  = (idx>>6) & 127;
    int b   = idx>>13;
    size_t rowbase = (size_t)b*262144 + (size_t)(2*oy)*256 + 4*xp2;
    float m[4][2];
    #pragma unroll
    for (int c=0;c<4;c++){ m[c][0]=-1e30f; m[c][1]=-1e30f; }
    #pragma unroll
    for (int dy=0;dy<2;dy++){
        size_t ro = rowbase + (size_t)dy*256;
        float4 h[4], g[4];
        #pragma unroll
        for (int c=0;c<4;c++){
            h[c] = *(const float4*)&h1[ro + (size_t)c*65536];
            g[c] = *(const float4*)&s2[ro + (size_t)c*65536];
        }
        #pragma unroll
        for (int j=0;j<4;j++){
            float a[4], gv[4];
            #pragma unroll
            for (int c=0;c<4;c++){
                float hv = (j==0)?h[c].x:(j==1)?h[c].y:(j==2)?h[c].z:h[c].w;
                gv[c]    = (j==0)?g[c].x:(j==1)?g[c].y:(j==2)?g[c].z:g[c].w;
                a[c] = fmaxf(hv*scA[c]+shA[c], 0.f);
            }
            float hid = fmaxf(a1b + a[0]*a1w[0]+a[1]*a1w[1]+a[2]*a1w[2]+a[3]*a1w[3], 0.f);
            int half = j>>1;
            #pragma unroll
            for (int c=0;c<4;c++){
                float sv = sigm(gv[c]*sc2[c]+sh2[c]);
                float xv = a[c]*(hid*a2w[c]+a2b[c]);
                m[c][half] = fmaxf(m[c][half], xv*sv);
            }
        }
    }
    size_t ob = (size_t)b*65536 + (size_t)oy*128 + 2*xp2;
    #pragma unroll
    for (int c=0;c<4;c++)
        *(float2*)&p1[ob + (size_t)c*16384] = make_float2(m[c][0], m[c][1]);
}

// ---------------- conv2: 4->8, 3x3, s2, p1 + stats ----------------
__global__ void k_conv2(const float* __restrict__ in, const float* __restrict__ w,
                        const float* __restrict__ bias, float* __restrict__ out){
    __shared__ float t[4][33][33];
    __shared__ float ws[288];
    __shared__ float wb[8];
    __shared__ float ssum[8], ssq[8];
    int tid = threadIdx.y*16+threadIdx.x;
    int b = blockIdx.z;
    for (int i=tid;i<288;i+=256) ws[i]=w[i];
    if (tid<8){ wb[tid]=bias[tid]; ssum[tid]=0.f; ssq[tid]=0.f; }
    int iy0 = blockIdx.y*32-1, ix0 = blockIdx.x*32-1;
    for (int i=tid; i<4*1089; i+=256){
        int c=i/1089; int r=(i%1089)/33; int cc=i%33;
        int iy=iy0+r, ix=ix0+cc;
        float v=0.f;
        if (iy>=0&&iy<128&&ix>=0&&ix<128)
            v = in[(size_t)b*65536 + (size_t)c*16384 + iy*128+ix];
        t[c][r][cc]=v;
    }
    __syncthreads();
    int ty=threadIdx.y, tx=threadIdx.x;
    float acc[8];
    #pragma unroll
    for (int oc=0;oc<8;oc++) acc[oc]=wb[oc];
    #pragma unroll
    for (int ci=0;ci<4;ci++)
        #pragma unroll
        for (int ky=0;ky<3;ky++)
            #pragma unroll
            for (int kx=0;kx<3;kx++){
                float v = t[ci][2*ty+ky][2*tx+kx];
                #pragma unroll
                for (int oc=0;oc<8;oc++) acc[oc]+=v*ws[oc*36+ci*9+ky*3+kx];
            }
    int oy = blockIdx.y*16+ty, ox = blockIdx.x*16+tx;
    #pragma unroll
    for (int oc=0;oc<8;oc++)
        out[(size_t)b*32768 + (size_t)oc*4096 + oy*64+ox] = acc[oc];
    #pragma unroll
    for (int oc=0;oc<8;oc++){
        float s=wred(acc[oc]), q=wred(acc[oc]*acc[oc]);
        if ((tid&31)==0){ atomicAdd(&ssum[oc],s); atomicAdd(&ssq[oc],q); }
    }
    __syncthreads();
    if (tid<8){
        atomicAdd(&g_sumA[S2CH+tid], (double)ssum[tid]);
        atomicAdd(&g_sqA[S2CH+tid],  (double)ssq[tid]);
    }
}

// ---------------- pool2 = maxpool2(relu(bn(r2))) ----------------
__global__ void k_pool2(const float* __restrict__ r2, float* __restrict__ p2){
    __shared__ float sc[8], sh[8];
    int tid=threadIdx.x;
    if (tid<8) bn_scale(S2CH+tid, N2, sc[tid], sh[tid]);
    __syncthreads();
    int idx = blockIdx.x*256+tid;
    int ox=idx&31; int oy=(idx>>5)&31; int c=(idx>>10)&7; int b=idx>>13;
    size_t base = (size_t)b*32768 + (size_t)c*4096;
    float m=-1e30f;
    #pragma unroll
    for (int dy=0;dy<2;dy++)
        #pragma unroll
        for (int dx=0;dx<2;dx++){
            float v = r2[base + (size_t)(2*oy+dy)*64 + (2*ox+dx)]*sc[c]+sh[c];
            v = v>0.f?v:0.f;
            m = fmaxf(m,v);
        }
    p2[(size_t)b*8192 + (size_t)c*1024 + oy*32+ox] = m;
}

// ---------------- conv3: 8->16, 3x3, s1, p1 + stats ----------------
__global__ void k_conv3(const float* __restrict__ in, const float* __restrict__ w,
                        const float* __restrict__ bias, float* __restrict__ out){
    __shared__ float t[8][18][18];
    __shared__ float ws[1152];
    __shared__ float wb[16];
    __shared__ float ssum[16], ssq[16];
    int tid = threadIdx.y*16+threadIdx.x;
    int b = blockIdx.z;
    for (int i=tid;i<1152;i+=256) ws[i]=w[i];
    if (tid<16){ wb[tid]=bias[tid]; ssum[tid]=0.f; ssq[tid]=0.f; }
    int iy0 = blockIdx.y*16-1, ix0 = blockIdx.x*16-1;
    for (int i=tid;i<8*324;i+=256){
        int c=i/324; int r=(i%324)/18; int cc=i%18;
        int iy=iy0+r, ix=ix0+cc;
        float v=0.f;
        if (iy>=0&&iy<32&&ix>=0&&ix<32)
            v = in[(size_t)b*8192 + (size_t)c*1024 + iy*32+ix];
        t[c][r][cc]=v;
    }
    __syncthreads();
    int ty=threadIdx.y, tx=threadIdx.x;
    float acc[16];
    #pragma unroll
    for (int oc=0;oc<16;oc++) acc[oc]=wb[oc];
    #pragma unroll
    for (int ci=0;ci<8;ci++)
        #pragma unroll
        for (int ky=0;ky<3;ky++)
            #pragma unroll
            for (int kx=0;kx<3;kx++){
                float v=t[ci][ty+ky][tx+kx];
                #pragma unroll
                for (int oc=0;oc<16;oc++) acc[oc]+=v*ws[oc*72+ci*9+ky*3+kx];
            }
    int oy=blockIdx.y*16+ty, ox=blockIdx.x*16+tx;
    #pragma unroll
    for (int oc=0;oc<16;oc++)
        out[(size_t)b*16384 + (size_t)oc*1024 + oy*32+ox]=acc[oc];
    #pragma unroll
    for (int oc=0;oc<16;oc++){
        float s=wred(acc[oc]), q=wred(acc[oc]*acc[oc]);
        if ((tid&31)==0){ atomicAdd(&ssum[oc],s); atomicAdd(&ssq[oc],q); }
    }
    __syncthreads();
    if (tid<16){
        atomicAdd(&g_sumA[S3+tid], (double)ssum[tid]);
        atomicAdd(&g_sqA[S3+tid],  (double)ssq[tid]);
    }
}

// ---------------- pool3 = maxpool2(relu(bn(r3))) ----------------
__global__ void k_pool3(const float* __restrict__ r3, float* __restrict__ p3){
    __shared__ float sc[16], sh[16];
    int tid=threadIdx.x;
    if (tid<16) bn_scale(S3+tid, N3, sc[tid], sh[tid]);
    __syncthreads();
    int idx = blockIdx.x*256+tid;
    int ox=idx&15; int oy=(idx>>4)&15; int c=(idx>>8)&15; int b=idx>>12;
    size_t base=(size_t)b*16384 + (size_t)c*1024;
    float m=-1e30f;
    #pragma unroll
    for (int dy=0;dy<2;dy++)
        #pragma unroll
        for (int dx=0;dx<2;dx++){
            float v=r3[base + (size_t)(2*oy+dy)*32 + (2*ox+dx)]*sc[c]+sh[c];
            v=v>0.f?v:0.f;
            m=fmaxf(m,v);
        }
    p3[(size_t)b*4096 + (size_t)c*256 + oy*16+ox]=m;
}

// ---------------- conv4: 16->32, 3x3, s1, p1 + stats (split 2 oc-halves) -----
__global__ void k_conv4(const float* __restrict__ in, const float* __restrict__ w,
                        const float* __restrict__ bias, float* __restrict__ out){
    __shared__ float t[16][18][18];
    __shared__ float ws[2304];
    __shared__ float wb[16];
    __shared__ float ssum[16], ssq[16];
    int tid = threadIdx.y*16+threadIdx.x;
    int b = blockIdx.x;
    int ocb = blockIdx.y*16;   // 0 or 16
    for (int i=tid;i<2304;i+=256) ws[i]=w[ocb*144+i];
    if (tid<16){ wb[tid]=bias[ocb+tid]; ssum[tid]=0.f; ssq[tid]=0.f; }
    for (int i=tid;i<16*324;i+=256){
        int c=i/324; int r=(i%324)/18; int cc=i%18;
        int iy=r-1, ix=cc-1;
        float v=0.f;
        if (iy>=0&&iy<16&&ix>=0&&ix<16)
            v = in[(size_t)b*4096 + (size_t)c*256 + iy*16+ix];
        t[c][r][cc]=v;
    }
    __syncthreads();
    int ty=threadIdx.y, tx=threadIdx.x;
    float acc[16];
    #pragma unroll
    for (int oc=0;oc<16;oc++) acc[oc]=wb[oc];
    #pragma unroll
    for (int ci=0;ci<16;ci++)
        #pragma unroll
        for (int ky=0;ky<3;ky++)
            #pragma unroll
            for (int kx=0;kx<3;kx++){
                float v=t[ci][ty+ky][tx+kx];
                #pragma unroll
                for (int oc=0;oc<16;oc++) acc[oc]+=v*ws[oc*144+ci*9+ky*3+kx];
            }
    #pragma unroll
    for (int oc=0;oc<16;oc++)
        out[(size_t)b*8192 + (size_t)(ocb+oc)*256 + ty*16+tx]=acc[oc];
    #pragma unroll
    for (int oc=0;oc<16;oc++){
        float s=wred(acc[oc]), q=wred(acc[oc]*acc[oc]);
        if ((tid&31)==0){ atomicAdd(&ssum[oc],s); atomicAdd(&ssq[oc],q); }
    }
    __syncthreads();
    if (tid<16){
        atomicAdd(&g_sumA[S4+ocb+tid], (double)ssum[tid]);
        atomicAdd(&g_sqA[S4+ocb+tid],  (double)ssq[tid]);
    }
}

// ---------------- conv5: 1x1, relu(bn(r4)) -> 16 + stats ----------------
__global__ void k_conv5(const float* __restrict__ r4, const float* __restrict__ w,
                        const float* __restrict__ bias, float* __restrict__ out){
    __shared__ float sc[32], sh[32];
    __shared__ float ws[512];
    __shared__ float wb[16];
    __shared__ float ssum[16], ssq[16];
    int tid=threadIdx.x;
    if (tid<32) bn_scale(S4+tid, N4, sc[tid], sh[tid]);
    for (int i=tid;i<512;i+=256) ws[i]=w[i];
    if (tid<16){ wb[tid]=bias[tid]; ssum[tid]=0.f; ssq[tid]=0.f; }
    __syncthreads();
    int idx = blockIdx.x*256+tid;
    int b = idx>>8; int p = idx&255;
    float a[32];
    #pragma unroll
    for (int ci=0;ci<32;ci++){
        float v = r4[(size_t)b*8192 + (size_t)ci*256 + p]*sc[ci]+sh[ci];
        a[ci]=v>0.f?v:0.f;
    }
    float accs[16];
    #pragma unroll
    for (int oc=0;oc<16;oc++){
        float acc=wb[oc];
        #pragma unroll
        for (int ci=0;ci<32;ci++) acc += a[ci]*ws[oc*32+ci];
        out[(size_t)b*4096 + (size_t)oc*256 + p]=acc;
        accs[oc]=acc;
    }
    #pragma unroll
    for (int oc=0;oc<16;oc++){
        float s=wred(accs[oc]), q=wred(accs[oc]*accs[oc]);
        if ((tid&31)==0){ atomicAdd(&ssum[oc],s); atomicAdd(&ssq[oc],q); }
    }
    __syncthreads();
    if (tid<16){
        atomicAdd(&g_sumA[S5+tid], (double)ssum[tid]);
        atomicAdd(&g_sqA[S5+tid],  (double)ssq[tid]);
    }
}

// ---------------- tok = relu(bn(r5)) transposed to (B,L,D) ----------------
__global__ void k_tok(const float* __restrict__ r5, float* __restrict__ tok){
    __shared__ float sc[16], sh[16];
    int tid=threadIdx.x;
    if (tid<16) bn_scale(S5+tid, N5, sc[tid], sh[tid]);
    __syncthreads();
    int idx = blockIdx.x*256+tid;
    int d = idx&15; int l=(idx>>4)&255; int b=idx>>12;
    float v = r5[(size_t)b*4096 + (size_t)d*256 + l]*sc[d]+sh[d];
    tok[idx] = v>0.f?v:0.f;
}

// ---------------- mamba layer ----------------
#define O_WIN 0
#define O_CW  1024
#define O_CB  1152
#define O_XP  1184
#define O_DTW 2240
#define O_DTB 2272
#define O_AE  2304
#define O_DD  2816
#define O_OW  2848
#define O_LNG 3360
#define O_LNB 3376
#define O_XI  3392
#define O_ZZ  11584
#define O_XC  19776
#define O_DL  27968
#define O_BM  36160
#define O_CM  40256
#define O_YY  44352
#define SM_FLOATS 52544

__global__ void k_mamba(float* __restrict__ tok,
    const float* __restrict__ lng, const float* __restrict__ lnb,
    const float* __restrict__ inw, const float* __restrict__ cw, const float* __restrict__ cb,
    const float* __restrict__ xpw, const float* __restrict__ dtw, const float* __restrict__ dtb,
    const float* __restrict__ alog, const float* __restrict__ dvec, const float* __restrict__ ow)
{
    extern __shared__ float sm[];
    int t = threadIdx.x; int b = blockIdx.x;
    for (int i=t;i<1024;i+=512) sm[O_WIN+i]=inw[i];
    for (int i=t;i<128;i+=512)  sm[O_CW+i]=cw[i];
    for (int i=t;i<1056;i+=512) sm[O_XP+i]=xpw[i];
    for (int i=t;i<512;i+=512){ sm[O_AE+i]=-expf(alog[i]); sm[O_OW+i]=ow[i]; }
    if (t<32){ sm[O_CB+t]=cb[t]; sm[O_DTW+t]=dtw[t]; sm[O_DTB+t]=dtb[t]; sm[O_DD+t]=dvec[t]; }
    if (t<16){ sm[O_LNG+t]=lng[t]; sm[O_LNB+t]=lnb[t]; }
    __syncthreads();

    // step 1: LN + in_proj (all 512 threads: half 0 -> xi, half 1 -> z)
    {
        int l = t & 255;
        int half = t >> 8;
        float v[16];
        const float* tp = tok + ((size_t)b*4096 + (size_t)l*16);
        float mean=0.f;
        #pragma unroll
        for (int d=0;d<16;d++){ v[d]=tp[d]; mean+=v[d]; }
        mean *= 0.0625f;
        float var=0.f;
        #pragma unroll
        for (int d=0;d<16;d++){ float dd=v[d]-mean; var+=dd*dd; }
        var *= 0.0625f;
        float inv = rsqrtf(var+1e-5f);
        #pragma unroll
        for (int d=0;d<16;d++) v[d]=(v[d]-mean)*inv*sm[O_LNG+d]+sm[O_LNB+d];
        int j0 = half*32;
        float* dst = (half==0) ? &sm[O_XI+l*32] : &sm[O_ZZ+l*32];
        for (int jj=0;jj<32;jj++){
            float a=0.f;
            #pragma unroll
            for (int d=0;d<16;d++) a += v[d]*sm[O_WIN+(j0+jj)*16+d];
            dst[jj]=a;
        }
    }
    __syncthreads();

    // step 2: depthwise causal conv + silu (half the threads, 2 l per... keep 256)
    if (t < 256){
        int l=t;
        for (int d=0;d<32;d++){
            float a = sm[O_CB+d];
            #pragma unroll
            for (int k=0;k<4;k++){
                int ll=l-3+k;
                if (ll>=0) a += sm[O_CW+d*4+k]*sm[O_XI+ll*32+d];
            }
            sm[O_XC+l*32+d] = a*__fdividef(1.f, 1.f+__expf(-a));
        }
    }
    __syncthreads();

    // step 3: x_proj (half 0: dt + B + delta; half 1: C)
    {
        int l = t & 255;
        int half = t >> 8;
        float xcl[32];
        #pragma unroll
        for (int d=0;d<32;d++) xcl[d]=sm[O_XC+l*32+d];
        if (half==0){
            float dtv=0.f;
            #pragma unroll
            for (int d=0;d<32;d++) dtv += xcl[d]*sm[O_XP+d];
            for (int n=0;n<16;n++){
                float bb=0.f;
                #pragma unroll
                for (int d=0;d<32;d++) bb += xcl[d]*sm[O_XP+(1+n)*32+d];
                sm[O_BM+l*16+n]=bb;
            }
            for (int d=0;d<32;d++){
                float pre = dtv*sm[O_DTW+d]+sm[O_DTB+d];
                float sp = (pre>20.f)? pre : log1pf(__expf(pre));
                sm[O_DL+l*32+d]=sp;
            }
        } else {
            for (int n=0;n<16;n++){
                float cc=0.f;
                #pragma unroll
                for (int d=0;d<32;d++) cc += xcl[d]*sm[O_XP+(17+n)*32+d];
                sm[O_CM+l*16+n]=cc;
            }
        }
    }
    __syncthreads();

    // step 4: selective scan, chunked (8) with deferred shuffle reduction
    {
        int d = t>>4, n = t&15;
        float A  = sm[O_AE+d*16+n];
        float Dv = sm[O_DD+d];
        float h=0.f;
        for (int l0=0;l0<256;l0+=8){
            float cbuf[8];
            #pragma unroll
            for (int j=0;j<8;j++){
                int l=l0+j;
                float dl  = sm[O_DL+l*32+d];
                float xcv = sm[O_XC+l*32+d];
                float dA  = __expf(dl*A);
                h = dA*h + dl*sm[O_BM+l*16+n]*xcv;
                cbuf[j] = h*sm[O_CM+l*16+n];
            }
            #pragma unroll
            for (int j=0;j<8;j++){
                float c=cbuf[j];
                c += __shfl_xor_sync(0xffffffffu, c, 1);
                c += __shfl_xor_sync(0xffffffffu, c, 2);
                c += __shfl_xor_sync(0xffffffffu, c, 4);
                c += __shfl_xor_sync(0xffffffffu, c, 8);
                cbuf[j]=c;
            }
            if (n==0){
                #pragma unroll
                for (int j=0;j<8;j++){
                    int l=l0+j;
                    sm[O_YY+l*32+d] = cbuf[j] + sm[O_XC+l*32+d]*Dv;
                }
            }
        }
    }
    __syncthreads();

    // step 5: gate + out_proj, residual add (all 512: half j-split)
    {
        int l = t & 255;
        int half = t >> 8;
        float yv[32];
        #pragma unroll
        for (int d=0;d<32;d++){
            float zv=sm[O_ZZ+l*32+d];
            yv[d]=sm[O_YY+l*32+d]*(zv*__fdividef(1.f,1.f+__expf(-zv)));
        }
        float* tp = tok + ((size_t)b*4096 + (size_t)l*16);
        int j0 = half*8;
        #pragma unroll
        for (int jj=0;jj<8;jj++){
            float a=0.f;
            #pragma unroll
            for (int d=0;d<32;d++) a += yv[d]*sm[O_OW+(j0+jj)*32+d];
            tp[j0+jj] += a;
        }
    }
}

// ---------------- head: mean-pool + linear + LN ----------------
__global__ void k_head(const float* __restrict__ tok, const float* __restrict__ pw,
                       const float* __restrict__ pb, const float* __restrict__ fg,
                       const float* __restrict__ fb, float* __restrict__ out){
    __shared__ float pooled[16];
    __shared__ float red[16];
    __shared__ float s_mean, s_inv;
    int t=threadIdx.x, b=blockIdx.x;
    if (t<16){
        float s=0.f;
        const float* tp = tok + (size_t)b*4096 + t;
        for (int l=0;l<256;l++) s += tp[l*16];
        pooled[t] = s*(1.f/256.f);
    }
    __syncthreads();
    float lg = pb[t];
    #pragma unroll
    for (int d=0;d<16;d++) lg += pooled[d]*pw[t*16+d];
    float s1v = wred(lg);
    float s2v = wred(lg*lg);
    int w = t>>5;
    if ((t&31)==0){ red[w]=s1v; red[8+w]=s2v; }
    __syncthreads();
    if (t==0){
        float a=0.f,q=0.f;
        for (int i=0;i<8;i++){a+=red[i]; q+=red[8+i];}
        float m=a*(1.f/256.f);
        float v=q*(1.f/256.f)-m*m;
        s_mean=m; s_inv=rsqrtf(v+1e-5f);
    }
    __syncthreads();
    out[b*256+t] = (lg-s_mean)*s_inv*fg[t]+fb[t];
}

// ---------------- launch ----------------
extern "C" void kernel_launch(void* const* d_in, const int* in_sizes, int n_in,
                              void* d_out, int out_size){
    const float* x    = (const float*)d_in[0];
    const float* c1w  = (const float*)d_in[1];
    const float* c1b  = (const float*)d_in[2];
    const float* caw1 = (const float*)d_in[3];
    const float* cab1 = (const float*)d_in[4];
    const float* caw2 = (const float*)d_in[5];
    const float* cab2 = (const float*)d_in[6];
    const float* sw1  = (const float*)d_in[7];
    const float* sw2  = (const float*)d_in[8];
    const float* c2w  = (const float*)d_in[9];
    const float* c2b  = (const float*)d_in[10];
    const float* c3w  = (const float*)d_in[11];
    const float* c3b  = (const float*)d_in[12];
    const float* c4w  = (const float*)d_in[13];
    const float* c4b  = (const float*)d_in[14];
    const float* c5w  = (const float*)d_in[15];
    const float* c5b  = (const float*)d_in[16];
    const float* mlng = (const float*)d_in[17];
    const float* mlnb = (const float*)d_in[18];
    const float* minw = (const float*)d_in[19];
    const float* mcw  = (const float*)d_in[20];
    const float* mcb  = (const float*)d_in[21];
    const float* mxp  = (const float*)d_in[22];
    const float* mdtw = (const float*)d_in[23];
    const float* mdtb = (const float*)d_in[24];
    const float* mal  = (const float*)d_in[25];
    const float* mD   = (const float*)d_in[26];
    const float* mow  = (const float*)d_in[27];
    const float* pw   = (const float*)d_in[28];
    const float* pb   = (const float*)d_in[29];
    const float* fg   = (const float*)d_in[30];
    const float* fb   = (const float*)d_in[31];
    float* out = (float*)d_out;

    float *h1, *s1, *s2, *p1, *r2, *p2, *r3, *p3, *r4, *r5, *tok;
    cudaGetSymbolAddress((void**)&h1, g_h1);
    cudaGetSymbolAddress((void**)&s1, g_s1);
    cudaGetSymbolAddress((void**)&s2, g_s2);
    cudaGetSymbolAddress((void**)&p1, g_p1);
    cudaGetSymbolAddress((void**)&r2, g_r2);
    cudaGetSymbolAddress((void**)&p2, g_p2);
    cudaGetSymbolAddress((void**)&r3, g_r3);
    cudaGetSymbolAddress((void**)&p3, g_p3);
    cudaGetSymbolAddress((void**)&r4, g_r4);
    cudaGetSymbolAddress((void**)&r5, g_r5);
    cudaGetSymbolAddress((void**)&tok, g_tok);

    size_t smem_mamba = SM_FLOATS * sizeof(float);
    cudaFuncSetAttribute(k_mamba, cudaFuncAttributeMaxDynamicSharedMemorySize, (int)smem_mamba);
    size_t smem_s1f = 4970*sizeof(float);   // 19880 B, one channel tile
    cudaFuncSetAttribute(k_s1f, cudaFuncAttributeMaxDynamicSharedMemorySize, (int)smem_s1f);

    k_zero<<<1,128>>>();
    k_conv1<<<dim3(8,8,128), dim3(16,16)>>>(x, c1w, c1b, h1);
    k_s1f<<<dim3(4,4,128), 256, smem_s1f>>>(h1, sw1, caw1, cab1, caw2, cab2, s1);
    k_s2w<<<dim3(8,8,128), 256>>>(s1, sw2, s2);
    k_pool1v<<<4096,256>>>(h1, s2, caw1, cab1, caw2, cab2, p1);
    k_conv2<<<dim3(4,4,128), dim3(16,16)>>>(p1, c2w, c2b, r2);
    k_pool2<<<4096,256>>>(r2, p2);
    k_conv3<<<dim3(2,2,128), dim3(16,16)>>>(p2, c3w, c3b, r3);
    k_pool3<<<2048,256>>>(r3, p3);
    k_conv4<<<dim3(128,2), dim3(16,16)>>>(p3, c4w, c4b, r4);
    k_conv5<<<128,256>>>(r4, c5w, c5b, r5);
    k_tok<<<2048,256>>>(r5, tok);
    for (int layer=0; layer<2; layer++){
        k_mamba<<<128,512,smem_mamba>>>(tok,
            mlng+layer*16, mlnb+layer*16, minw+layer*1024,
            mcw+layer*128, mcb+layer*32, mxp+layer*1056,
            mdtw+layer*32, mdtb+layer*32, mal+layer*512,
            mD+layer*32, mow+layer*512);
    }
    k_head<<<128,256>>>(tok, pw, pb, fg, fb, out);
}

// round 6
// speedup vs baseline: 1.9284x; 1.0745x over previous
#include <cuda_runtime.h>
#include <cuda_bf16.h>
#include <math.h>

// ---------------- constants ----------------
#define N1  8388608.0   // 128*256*256 per channel
#define N2  524288.0    // 128*64*64
#define N3  131072.0    // 128*32*32
#define N4  32768.0     // 128*16*16
#define N5  32768.0

// bn stat offsets
#define S1CH 0   // 4 ch
#define SS1  8   // 1 ch
#define SS2  12  // 4 ch
#define S2CH 16  // 8 ch
#define S3   24  // 16 ch
#define S4   40  // 32 ch
#define S5   72  // 16 ch

// ---------------- scratch ----------------
__device__ float g_h1[33554432];   // (128,4,256,256) conv1 raw
__device__ float g_s2[33554432];   // (128,4,256,256) raw s2 conv
__device__ float g_s1[8388608];    // (128,1,256,256) raw s1 conv
__device__ float g_p1[8388608];    // (128,4,128,128)
__device__ float g_r2[4194304];    // (128,8,64,64)
__device__ float g_p2[1048576];    // (128,8,32,32)
__device__ float g_r3[2097152];    // (128,16,32,32)
__device__ float g_p3[524288];     // (128,16,16,16)
__device__ float g_r4[1048576];    // (128,32,16,16)
__device__ float g_r5[524288];     // (128,16,16,16)
__device__ float g_tok[524288];    // (128,256,16)
__device__ double g_sumA[128];
__device__ double g_sqA[128];

// ---------------- helpers ----------------
__device__ __forceinline__ float wred(float v){
    #pragma unroll
    for (int o=16;o>0;o>>=1) v += __shfl_down_sync(0xffffffffu, v, o);
    return v;
}
__device__ __forceinline__ void bn_scale(int off, double N, float& sc, float& sh){
    double m = g_sumA[off]/N;
    double v = g_sqA[off]/N - m*m;
    double s = 1.0/sqrt(v+1e-5);
    sc = (float)s; sh = (float)(-m*s);
}
__device__ __forceinline__ float sigm(float x){
    return __fdividef(1.f, 1.f + __expf(-x));
}

__global__ void k_zero(){
    int t = threadIdx.x;
    if (t < 128){ g_sumA[t]=0.0; g_sqA[t]=0.0; }
}

// ---------------- conv1: 1->4, 5x5, s2, p2 ----------------
// block (32,8): thread computes 1 row x 4 cols x 4 oc. out tile 8x128.
// grid (2, 32, 128). smem tile 19 x 260.
__global__ void __launch_bounds__(256) k_conv1(
                        const float* __restrict__ x, const float* __restrict__ w,
                        const float* __restrict__ bias, float* __restrict__ out){
    __shared__ float t[19][260];
    __shared__ float ws[100];
    __shared__ float wb[4];
    __shared__ float ssum[4], ssq[4];
    int tx = threadIdx.x, ty = threadIdx.y;
    int tid = ty*32 + tx;
    int b = blockIdx.z;
    if (tid < 100) ws[tid] = w[tid];
    if (tid < 4){ wb[tid] = bias[tid]; ssum[tid]=0.f; ssq[tid]=0.f; }
    int oy0 = blockIdx.y*8, ox0 = blockIdx.x*128;
    int iy0 = 2*oy0 - 2, ix0 = 2*ox0 - 2;
    const float* xb = x + (size_t)b*262144;
    // load 19 x 259 input tile
    for (int i = tid; i < 19*259; i += 256){
        int r = i/259, c = i%259;
        int iy = iy0 + r, ix = ix0 + c;
        float v = 0.f;
        if (iy>=0 && iy<512 && ix>=0 && ix<512) v = xb[iy*512+ix];
        t[r][c] = v;
    }
    __syncthreads();
    float acc[16];
    #pragma unroll
    for (int oc=0;oc<4;oc++)
        #pragma unroll
        for (int dx=0;dx<4;dx++) acc[oc*4+dx] = wb[oc];
    int colb = 8*tx;   // local input col base for dx=0,kx=0
    #pragma unroll
    for (int ky=0; ky<5; ky++){
        float rv[11];
        const float* row = &t[2*ty+ky][colb];
        #pragma unroll
        for (int j=0;j<11;j++) rv[j] = row[j];
        #pragma unroll
        for (int oc=0;oc<4;oc++){
            #pragma unroll
            for (int kx=0;kx<5;kx++){
                float wv = ws[oc*25+ky*5+kx];
                #pragma unroll
                for (int dx=0;dx<4;dx++)
                    acc[oc*4+dx] += rv[2*dx+kx]*wv;
            }
        }
    }
    int oy = oy0 + ty, ox = ox0 + 4*tx;
    #pragma unroll
    for (int oc=0;oc<4;oc++){
        float4 v = make_float4(acc[oc*4],acc[oc*4+1],acc[oc*4+2],acc[oc*4+3]);
        *(float4*)&out[(size_t)b*262144 + (size_t)oc*65536 + (size_t)oy*256 + ox] = v;
        float s = v.x+v.y+v.z+v.w;
        float q = v.x*v.x+v.y*v.y+v.z*v.z+v.w*v.w;
        s = wred(s); q = wred(q);
        if ((tid&31)==0){ atomicAdd(&ssum[oc], s); atomicAdd(&ssq[oc], q); }
    }
    __syncthreads();
    if (tid < 4){
        atomicAdd(&g_sumA[S1CH+tid], (double)ssum[tid]);
        atomicAdd(&g_sqA[S1CH+tid],  (double)ssq[tid]);
    }
}

// ---------------- s1 fused: xg inline from h1 (2 channels per pass),
//                  conv7x7 4->1, stats. smem = 2*70*71 floats ---------
__global__ void __launch_bounds__(256) k_s1f(
                      const float* __restrict__ h1, const float* __restrict__ w,
                      const float* __restrict__ caw1, const float* __restrict__ cab1,
                      const float* __restrict__ caw2, const float* __restrict__ cab2,
                      float* __restrict__ s1){
    extern __shared__ float xt[];   // 2 * 4970 floats
    __shared__ float wsm[196];
    __shared__ float sc[4], sh[4];
    __shared__ float a1w[4], a2w[4], a2b[4];
    __shared__ float a1b;
    __shared__ float ssum, ssq;
    int tid = threadIdx.x;
    int b = blockIdx.z;
    if (tid<196) wsm[tid]=w[tid];
    if (tid<4){ bn_scale(S1CH+tid, N1, sc[tid], sh[tid]);
                a1w[tid]=caw1[tid]; a2w[tid]=caw2[tid]; a2b[tid]=cab2[tid]; }
    if (tid==0){ a1b=cab1[0]; ssum=0.f; ssq=0.f; }
    __syncthreads();
    int y0 = blockIdx.y*64 - 3, x0 = blockIdx.x*64 - 3;
    const float* hb = h1 + (size_t)b*262144;
    int tyy=tid>>4, txx=tid&15;
    int r0=tyy*4, c0=txx*4;
    float acc[16];
    #pragma unroll
    for (int i=0;i<16;i++) acc[i]=0.f;
    #pragma unroll
    for (int pass=0; pass<2; pass++){
        if (pass) __syncthreads();   // prior pass conv reads done
        int cA = 2*pass, cB = 2*pass+1;
        for (int i=tid; i<4900; i+=256){
            int r=i/70, cc=i%70;
            int sy=min(max(y0+r,0),255), sx=min(max(x0+cc,0),255);
            int off = sy*256+sx;
            float a0 = fmaxf(hb[off         ]*sc[0]+sh[0], 0.f);
            float a1 = fmaxf(hb[off+  65536 ]*sc[1]+sh[1], 0.f);
            float a2 = fmaxf(hb[off+ 131072 ]*sc[2]+sh[2], 0.f);
            float a3 = fmaxf(hb[off+ 196608 ]*sc[3]+sh[3], 0.f);
            float hid = fmaxf(a1b + a0*a1w[0]+a1*a1w[1]+a2*a1w[2]+a3*a1w[3], 0.f);
            float aA = (cA==0)?a0:a2;
            float aB = (cA==0)?a1:a3;
            int p = r*71+cc;
            xt[p       ] = aA*(hid*a2w[cA]+a2b[cA]);
            xt[p+4970  ] = aB*(hid*a2w[cB]+a2b[cB]);
        }
        __syncthreads();
        #pragma unroll
        for (int half=0; half<2; half++){
            int c = 2*pass + half;
            float wr[49];
            #pragma unroll
            for (int k=0;k<49;k++) wr[k]=wsm[c*49+k];
            const float* tb = &xt[half*4970];
            #pragma unroll
            for (int r=0;r<10;r++){
                float rv[10];
                #pragma unroll
                for (int j=0;j<10;j++) rv[j]=tb[(r0+r)*71 + c0+j];
                #pragma unroll
                for (int dy=0;dy<4;dy++){
                    int ky=r-dy;
                    if (ky>=0 && ky<7){
                        #pragma unroll
                        for (int dx=0;dx<4;dx++){
                            float a=acc[dy*4+dx];
                            #pragma unroll
                            for (int kx=0;kx<7;kx++) a += rv[dx+kx]*wr[ky*7+kx];
                            acc[dy*4+dx]=a;
                        }
                    }
                }
            }
        }
    }
    int oy=blockIdx.y*64 + r0, ox=blockIdx.x*64 + c0;
    float s=0.f, q=0.f;
    #pragma unroll
    for (int dy=0;dy<4;dy++){
        float4 v = make_float4(acc[dy*4],acc[dy*4+1],acc[dy*4+2],acc[dy*4+3]);
        *(float4*)&s1[(size_t)b*65536 + (size_t)(oy+dy)*256 + ox] = v;
        s += v.x+v.y+v.z+v.w;
        q += v.x*v.x+v.y*v.y+v.z*v.z+v.w*v.w;
    }
    s=wred(s); q=wred(q);
    if ((tid&31)==0){ atomicAdd(&ssum,s); atomicAdd(&ssq,q); }
    __syncthreads();
    if (tid==0){ atomicAdd(&g_sumA[SS1],(double)ssum); atomicAdd(&g_sqA[SS1],(double)ssq); }
}

// ---------------- s2w: conv7x7 1->4 over bn-relu(s1), stats + WRITE raw s2 ----
__global__ void k_s2w(const float* __restrict__ s1, const float* __restrict__ w,
                      float* __restrict__ s2){
    __shared__ float t[38*39];
    __shared__ float wsm[196];
    __shared__ float sc1_, sh1_;
    __shared__ float ssum[4], ssq[4];
    int tid = threadIdx.x;
    int b = blockIdx.z;
    if (tid<196) wsm[tid]=w[tid];
    if (tid==0) bn_scale(SS1, N1, sc1_, sh1_);
    if (tid<4){ ssum[tid]=0.f; ssq[tid]=0.f; }
    __syncthreads();
    int y0 = blockIdx.y*32 - 3, x0 = blockIdx.x*32 - 3;
    const float* sb = s1 + (size_t)b*65536;
    for (int i=tid; i<1444; i+=256){
        int r=i/38, cc=i%38;
        int sy=min(max(y0+r,0),255), sx=min(max(x0+cc,0),255);
        t[r*39+cc] = fmaxf(sb[sy*256+sx]*sc1_+sh1_, 0.f);
    }
    __syncthreads();
    int oc = tid>>6, t64 = tid&63;
    int tyy = t64>>3, txx = t64&7;
    int r0=tyy*4, c0=txx*4;
    float wr[49];
    #pragma unroll
    for (int k=0;k<49;k++) wr[k]=wsm[oc*49+k];
    float acc[16];
    #pragma unroll
    for (int i=0;i<16;i++) acc[i]=0.f;
    #pragma unroll
    for (int r=0;r<10;r++){
        float rv[10];
        #pragma unroll
        for (int j=0;j<10;j++) rv[j]=t[(r0+r)*39 + c0+j];
        #pragma unroll
        for (int dy=0;dy<4;dy++){
            int ky=r-dy;
            if (ky>=0 && ky<7){
                #pragma unroll
                for (int dx=0;dx<4;dx++){
                    float a=acc[dy*4+dx];
                    #pragma unroll
                    for (int kx=0;kx<7;kx++) a += rv[dx+kx]*wr[ky*7+kx];
                    acc[dy*4+dx]=a;
                }
            }
        }
    }
    int oy = blockIdx.y*32 + r0, ox = blockIdx.x*32 + c0;
    size_t base = (size_t)b*262144 + (size_t)oc*65536;
    float s=0.f,q=0.f;
    #pragma unroll
    for (int dy=0;dy<4;dy++){
        float4 v = make_float4(acc[dy*4],acc[dy*4+1],acc[dy*4+2],acc[dy*4+3]);
        *(float4*)&s2[base + (size_t)(oy+dy)*256 + ox] = v;
        s += v.x+v.y+v.z+v.w;
        q += v.x*v.x+v.y*v.y+v.z*v.z+v.w*v.w;
    }
    s=wred(s); q=wred(q);
    if ((tid&31)==0){ atomicAdd(&ssum[oc],s); atomicAdd(&ssq[oc],q); }
    __syncthreads();
    if (tid<4){
        atomicAdd(&g_sumA[SS2+tid],(double)ssum[tid]);
        atomicAdd(&g_sqA[SS2+tid], (double)ssq[tid]);
    }
}

// ---------------- pool1v: streaming xg + sigmoid(bn(s2)) gate + maxpool ------
__global__ void k_pool1v(const float* __restrict__ h1, const float* __restrict__ s2,
                         const float* __restrict__ caw1, const float* __restrict__ cab1,
                         const float* __restrict__ caw2, const float* __restrict__ cab2,
                         float* __restrict__ p1){
    __shared__ float scA[4], shA[4], sc2[4], sh2[4];
    __shared__ float a1w[4], a2w[4], a2b[4];
    __shared__ float a1b;
    int tid = threadIdx.x;
    if (tid<4){
        bn_scale(S1CH+tid, N1, scA[tid], shA[tid]);
        bn_scale(SS2+tid,  N1, sc2[tid], sh2[tid]);
        a1w[tid]=caw1[tid]; a2w[tid]=caw2[tid]; a2b[tid]=cab2[tid];
    }
    if (tid==0) a1b=cab1[0];
    __syncthreads();
    int idx = blockIdx.x*256 + tid;   // 1048576 exact
    int xp2 = idx & 63;
    int oy  = (idx>>6) & 127;
    int b   = idx>>13;
    size_t rowbase = (size_t)b*262144 + (size_t)(2*oy)*256 + 4*xp2;
    float m[4][2];
    #pragma unroll
    for (int c=0;c<4;c++){ m[c][0]=-1e30f; m[c][1]=-1e30f; }
    #pragma unroll
    for (int dy=0;dy<2;dy++){
        size_t ro = rowbase + (size_t)dy*256;
        float4 h[4], g[4];
        #pragma unroll
        for (int c=0;c<4;c++){
            h[c] = *(const float4*)&h1[ro + (size_t)c*65536];
            g[c] = *(const float4*)&s2[ro + (size_t)c*65536];
        }
        #pragma unroll
        for (int j=0;j<4;j++){
            float a[4], gv[4];
            #pragma unroll
            for (int c=0;c<4;c++){
                float hv = (j==0)?h[c].x:(j==1)?h[c].y:(j==2)?h[c].z:h[c].w;
                gv[c]    = (j==0)?g[c].x:(j==1)?g[c].y:(j==2)?g[c].z:g[c].w;
                a[c] = fmaxf(hv*scA[c]+shA[c], 0.f);
            }
            float hid = fmaxf(a1b + a[0]*a1w[0]+a[1]*a1w[1]+a[2]*a1w[2]+a[3]*a1w[3], 0.f);
            int half = j>>1;
            #pragma unroll
            for (int c=0;c<4;c++){
                float sv = sigm(gv[c]*sc2[c]+sh2[c]);
                float xv = a[c]*(hid*a2w[c]+a2b[c]);
                m[c][half] = fmaxf(m[c][half], xv*sv);
            }
        }
    }
    size_t ob = (size_t)b*65536 + (size_t)oy*128 + 2*xp2;
    #pragma unroll
    for (int c=0;c<4;c++)
        *(float2*)&p1[ob + (size_t)c*16384] = make_float2(m[c][0], m[c][1]);
}

// ---------------- conv2: 4->8, 3x3, s2, p1 + stats ----------------
__global__ void k_conv2(const float* __restrict__ in, const float* __restrict__ w,
                        const float* __restrict__ bias, float* __restrict__ out){
    __shared__ float t[4][33][33];
    __shared__ float ws[288];
    __shared__ float wb[8];
    __shared__ float ssum[8], ssq[8];
    int tid = threadIdx.y*16+threadIdx.x;
    int b = blockIdx.z;
    for (int i=tid;i<288;i+=256) ws[i]=w[i];
    if (tid<8){ wb[tid]=bias[tid]; ssum[tid]=0.f; ssq[tid]=0.f; }
    int iy0 = blockIdx.y*32-1, ix0 = blockIdx.x*32-1;
    for (int i=tid; i<4*1089; i+=256){
        int c=i/1089; int r=(i%1089)/33; int cc=i%33;
        int iy=iy0+r, ix=ix0+cc;
        float v=0.f;
        if (iy>=0&&iy<128&&ix>=0&&ix<128)
            v = in[(size_t)b*65536 + (size_t)c*16384 + iy*128+ix];
        t[c][r][cc]=v;
    }
    __syncthreads();
    int ty=threadIdx.y, tx=threadIdx.x;
    float acc[8];
    #pragma unroll
    for (int oc=0;oc<8;oc++) acc[oc]=wb[oc];
    #pragma unroll
    for (int ci=0;ci<4;ci++)
        #pragma unroll
        for (int ky=0;ky<3;ky++)
            #pragma unroll
            for (int kx=0;kx<3;kx++){
                float v = t[ci][2*ty+ky][2*tx+kx];
                #pragma unroll
                for (int oc=0;oc<8;oc++) acc[oc]+=v*ws[oc*36+ci*9+ky*3+kx];
            }
    int oy = blockIdx.y*16+ty, ox = blockIdx.x*16+tx;
    #pragma unroll
    for (int oc=0;oc<8;oc++)
        out[(size_t)b*32768 + (size_t)oc*4096 + oy*64+ox] = acc[oc];
    #pragma unroll
    for (int oc=0;oc<8;oc++){
        float s=wred(acc[oc]), q=wred(acc[oc]*acc[oc]);
        if ((tid&31)==0){ atomicAdd(&ssum[oc],s); atomicAdd(&ssq[oc],q); }
    }
    __syncthreads();
    if (tid<8){
        atomicAdd(&g_sumA[S2CH+tid], (double)ssum[tid]);
        atomicAdd(&g_sqA[S2CH+tid],  (double)ssq[tid]);
    }
}

// ---------------- pool2 = maxpool2(relu(bn(r2))) ----------------
__global__ void k_pool2(const float* __restrict__ r2, float* __restrict__ p2){
    __shared__ float sc[8], sh[8];
    int tid=threadIdx.x;
    if (tid<8) bn_scale(S2CH+tid, N2, sc[tid], sh[tid]);
    __syncthreads();
    int idx = blockIdx.x*256+tid;
    int ox=idx&31; int oy=(idx>>5)&31; int c=(idx>>10)&7; int b=idx>>13;
    size_t base = (size_t)b*32768 + (size_t)c*4096;
    float m=-1e30f;
    #pragma unroll
    for (int dy=0;dy<2;dy++)
        #pragma unroll
        for (int dx=0;dx<2;dx++){
            float v = r2[base + (size_t)(2*oy+dy)*64 + (2*ox+dx)]*sc[c]+sh[c];
            v = v>0.f?v:0.f;
            m = fmaxf(m,v);
        }
    p2[(size_t)b*8192 + (size_t)c*1024 + oy*32+ox] = m;
}

// ---------------- conv3: 8->16, 3x3, s1, p1 + stats ----------------
__global__ void k_conv3(const float* __restrict__ in, const float* __restrict__ w,
                        const float* __restrict__ bias, float* __restrict__ out){
    __shared__ float t[8][18][18];
    __shared__ float ws[1152];
    __shared__ float wb[16];
    __shared__ float ssum[16], ssq[16];
    int tid = threadIdx.y*16+threadIdx.x;
    int b = blockIdx.z;
    for (int i=tid;i<1152;i+=256) ws[i]=w[i];
    if (tid<16){ wb[tid]=bias[tid]; ssum[tid]=0.f; ssq[tid]=0.f; }
    int iy0 = blockIdx.y*16-1, ix0 = blockIdx.x*16-1;
    for (int i=tid;i<8*324;i+=256){
        int c=i/324; int r=(i%324)/18; int cc=i%18;
        int iy=iy0+r, ix=ix0+cc;
        float v=0.f;
        if (iy>=0&&iy<32&&ix>=0&&ix<32)
            v = in[(size_t)b*8192 + (size_t)c*1024 + iy*32+ix];
        t[c][r][cc]=v;
    }
    __syncthreads();
    int ty=threadIdx.y, tx=threadIdx.x;
    float acc[16];
    #pragma unroll
    for (int oc=0;oc<16;oc++) acc[oc]=wb[oc];
    #pragma unroll
    for (int ci=0;ci<8;ci++)
        #pragma unroll
        for (int ky=0;ky<3;ky++)
            #pragma unroll
            for (int kx=0;kx<3;kx++){
                float v=t[ci][ty+ky][tx+kx];
                #pragma unroll
                for (int oc=0;oc<16;oc++) acc[oc]+=v*ws[oc*72+ci*9+ky*3+kx];
            }
    int oy=blockIdx.y*16+ty, ox=blockIdx.x*16+tx;
    #pragma unroll
    for (int oc=0;oc<16;oc++)
        out[(size_t)b*16384 + (size_t)oc*1024 + oy*32+ox]=acc[oc];
    #pragma unroll
    for (int oc=0;oc<16;oc++){
        float s=wred(acc[oc]), q=wred(acc[oc]*acc[oc]);
        if ((tid&31)==0){ atomicAdd(&ssum[oc],s); atomicAdd(&ssq[oc],q); }
    }
    __syncthreads();
    if (tid<16){
        atomicAdd(&g_sumA[S3+tid], (double)ssum[tid]);
        atomicAdd(&g_sqA[S3+tid],  (double)ssq[tid]);
    }
}

// ---------------- pool3 = maxpool2(relu(bn(r3))) ----------------
__global__ void k_pool3(const float* __restrict__ r3, float* __restrict__ p3){
    __shared__ float sc[16], sh[16];
    int tid=threadIdx.x;
    if (tid<16) bn_scale(S3+tid, N3, sc[tid], sh[tid]);
    __syncthreads();
    int idx = blockIdx.x*256+tid;
    int ox=idx&15; int oy=(idx>>4)&15; int c=(idx>>8)&15; int b=idx>>12;
    size_t base=(size_t)b*16384 + (size_t)c*1024;
    float m=-1e30f;
    #pragma unroll
    for (int dy=0;dy<2;dy++)
        #pragma unroll
        for (int dx=0;dx<2;dx++){
            float v=r3[base + (size_t)(2*oy+dy)*32 + (2*ox+dx)]*sc[c]+sh[c];
            v=v>0.f?v:0.f;
            m=fmaxf(m,v);
        }
    p3[(size_t)b*4096 + (size_t)c*256 + oy*16+ox]=m;
}

// ---------------- conv4: 16->32, 3x3, s1, p1 + stats (split 2 oc-halves) -----
__global__ void k_conv4(const float* __restrict__ in, const float* __restrict__ w,
                        const float* __restrict__ bias, float* __restrict__ out){
    __shared__ float t[16][18][18];
    __shared__ float ws[2304];
    __shared__ float wb[16];
    __shared__ float ssum[16], ssq[16];
    int tid = threadIdx.y*16+threadIdx.x;
    int b = blockIdx.x;
    int ocb = blockIdx.y*16;
    for (int i=tid;i<2304;i+=256) ws[i]=w[ocb*144+i];
    if (tid<16){ wb[tid]=bias[ocb+tid]; ssum[tid]=0.f; ssq[tid]=0.f; }
    for (int i=tid;i<16*324;i+=256){
        int c=i/324; int r=(i%324)/18; int cc=i%18;
        int iy=r-1, ix=cc-1;
        float v=0.f;
        if (iy>=0&&iy<16&&ix>=0&&ix<16)
            v = in[(size_t)b*4096 + (size_t)c*256 + iy*16+ix];
        t[c][r][cc]=v;
    }
    __syncthreads();
    int ty=threadIdx.y, tx=threadIdx.x;
    float acc[16];
    #pragma unroll
    for (int oc=0;oc<16;oc++) acc[oc]=wb[oc];
    #pragma unroll
    for (int ci=0;ci<16;ci++)
        #pragma unroll
        for (int ky=0;ky<3;ky++)
            #pragma unroll
            for (int kx=0;kx<3;kx++){
                float v=t[ci][ty+ky][tx+kx];
                #pragma unroll
                for (int oc=0;oc<16;oc++) acc[oc]+=v*ws[oc*144+ci*9+ky*3+kx];
            }
    #pragma unroll
    for (int oc=0;oc<16;oc++)
        out[(size_t)b*8192 + (size_t)(ocb+oc)*256 + ty*16+tx]=acc[oc];
    #pragma unroll
    for (int oc=0;oc<16;oc++){
        float s=wred(acc[oc]), q=wred(acc[oc]*acc[oc]);
        if ((tid&31)==0){ atomicAdd(&ssum[oc],s); atomicAdd(&ssq[oc],q); }
    }
    __syncthreads();
    if (tid<16){
        atomicAdd(&g_sumA[S4+ocb+tid], (double)ssum[tid]);
        atomicAdd(&g_sqA[S4+ocb+tid],  (double)ssq[tid]);
    }
}

// ---------------- conv5: 1x1, relu(bn(r4)) -> 16 + stats ----------------
__global__ void k_conv5(const float* __restrict__ r4, const float* __restrict__ w,
                        const float* __restrict__ bias, float* __restrict__ out){
    __shared__ float sc[32], sh[32];
    __shared__ float ws[512];
    __shared__ float wb[16];
    __shared__ float ssum[16], ssq[16];
    int tid=threadIdx.x;
    if (tid<32) bn_scale(S4+tid, N4, sc[tid], sh[tid]);
    for (int i=tid;i<512;i+=256) ws[i]=w[i];
    if (tid<16){ wb[tid]=bias[tid]; ssum[tid]=0.f; ssq[tid]=0.f; }
    __syncthreads();
    int idx = blockIdx.x*256+tid;
    int b = idx>>8; int p = idx&255;
    float a[32];
    #pragma unroll
    for (int ci=0;ci<32;ci++){
        float v = r4[(size_t)b*8192 + (size_t)ci*256 + p]*sc[ci]+sh[ci];
        a[ci]=v>0.f?v:0.f;
    }
    float accs[16];
    #pragma unroll
    for (int oc=0;oc<16;oc++){
        float acc=wb[oc];
        #pragma unroll
        for (int ci=0;ci<32;ci++) acc += a[ci]*ws[oc*32+ci];
        out[(size_t)b*4096 + (size_t)oc*256 + p]=acc;
        accs[oc]=acc;
    }
    #pragma unroll
    for (int oc=0;oc<16;oc++){
        float s=wred(accs[oc]), q=wred(accs[oc]*accs[oc]);
        if ((tid&31)==0){ atomicAdd(&ssum[oc],s); atomicAdd(&ssq[oc],q); }
    }
    __syncthreads();
    if (tid<16){
        atomicAdd(&g_sumA[S5+tid], (double)ssum[tid]);
        atomicAdd(&g_sqA[S5+tid],  (double)ssq[tid]);
    }
}

// ---------------- tok = relu(bn(r5)) transposed to (B,L,D) ----------------
__global__ void k_tok(const float* __restrict__ r5, float* __restrict__ tok){
    __shared__ float sc[16], sh[16];
    int tid=threadIdx.x;
    if (tid<16) bn_scale(S5+tid, N5, sc[tid], sh[tid]);
    __syncthreads();
    int idx = blockIdx.x*256+tid;
    int d = idx&15; int l=(idx>>4)&255; int b=idx>>12;
    float v = r5[(size_t)b*4096 + (size_t)d*256 + l]*sc[d]+sh[d];
    tok[idx] = v>0.f?v:0.f;
}

// ---------------- mamba layer ----------------
#define O_WIN 0
#define O_CW  1024
#define O_CB  1152
#define O_XP  1184
#define O_DTW 2240
#define O_DTB 2272
#define O_AE  2304
#define O_DD  2816
#define O_OW  2848
#define O_LNG 3360
#define O_LNB 3376
#define O_XI  3392
#define O_ZZ  11584
#define O_XC  19776
#define O_DL  27968
#define O_BM  36160
#define O_CM  40256
#define O_YY  44352
#define SM_FLOATS 52544

__global__ void k_mamba(float* __restrict__ tok,
    const float* __restrict__ lng, const float* __restrict__ lnb,
    const float* __restrict__ inw, const float* __restrict__ cw, const float* __restrict__ cb,
    const float* __restrict__ xpw, const float* __restrict__ dtw, const float* __restrict__ dtb,
    const float* __restrict__ alog, const float* __restrict__ dvec, const float* __restrict__ ow)
{
    extern __shared__ float sm[];
    int t = threadIdx.x; int b = blockIdx.x;
    for (int i=t;i<1024;i+=512) sm[O_WIN+i]=inw[i];
    for (int i=t;i<128;i+=512)  sm[O_CW+i]=cw[i];
    for (int i=t;i<1056;i+=512) sm[O_XP+i]=xpw[i];
    for (int i=t;i<512;i+=512){ sm[O_AE+i]=-expf(alog[i]); sm[O_OW+i]=ow[i]; }
    if (t<32){ sm[O_CB+t]=cb[t]; sm[O_DTW+t]=dtw[t]; sm[O_DTB+t]=dtb[t]; sm[O_DD+t]=dvec[t]; }
    if (t<16){ sm[O_LNG+t]=lng[t]; sm[O_LNB+t]=lnb[t]; }
    __syncthreads();

    {
        int l = t & 255;
        int half = t >> 8;
        float v[16];
        const float* tp = tok + ((size_t)b*4096 + (size_t)l*16);
        float mean=0.f;
        #pragma unroll
        for (int d=0;d<16;d++){ v[d]=tp[d]; mean+=v[d]; }
        mean *= 0.0625f;
        float var=0.f;
        #pragma unroll
        for (int d=0;d<16;d++){ float dd=v[d]-mean; var+=dd*dd; }
        var *= 0.0625f;
        float inv = rsqrtf(var+1e-5f);
        #pragma unroll
        for (int d=0;d<16;d++) v[d]=(v[d]-mean)*inv*sm[O_LNG+d]+sm[O_LNB+d];
        int j0 = half*32;
        float* dst = (half==0) ? &sm[O_XI+l*32] : &sm[O_ZZ+l*32];
        for (int jj=0;jj<32;jj++){
            float a=0.f;
            #pragma unroll
            for (int d=0;d<16;d++) a += v[d]*sm[O_WIN+(j0+jj)*16+d];
            dst[jj]=a;
        }
    }
    __syncthreads();

    if (t < 256){
        int l=t;
        for (int d=0;d<32;d++){
            float a = sm[O_CB+d];
            #pragma unroll
            for (int k=0;k<4;k++){
                int ll=l-3+k;
                if (ll>=0) a += sm[O_CW+d*4+k]*sm[O_XI+ll*32+d];
            }
            sm[O_XC+l*32+d] = a*__fdividef(1.f, 1.f+__expf(-a));
        }
    }
    __syncthreads();

    {
        int l = t & 255;
        int half = t >> 8;
        float xcl[32];
        #pragma unroll
        for (int d=0;d<32;d++) xcl[d]=sm[O_XC+l*32+d];
        if (half==0){
            float dtv=0.f;
            #pragma unroll
            for (int d=0;d<32;d++) dtv += xcl[d]*sm[O_XP+d];
            for (int n=0;n<16;n++){
                float bb=0.f;
                #pragma unroll
                for (int d=0;d<32;d++) bb += xcl[d]*sm[O_XP+(1+n)*32+d];
                sm[O_BM+l*16+n]=bb;
            }
            for (int d=0;d<32;d++){
                float pre = dtv*sm[O_DTW+d]+sm[O_DTB+d];
                float sp = (pre>20.f)? pre : log1pf(__expf(pre));
                sm[O_DL+l*32+d]=sp;
            }
        } else {
            for (int n=0;n<16;n++){
                float cc=0.f;
                #pragma unroll
                for (int d=0;d<32;d++) cc += xcl[d]*sm[O_XP+(17+n)*32+d];
                sm[O_CM+l*16+n]=cc;
            }
        }
    }
    __syncthreads();

    {
        int d = t>>4, n = t&15;
        float A  = sm[O_AE+d*16+n];
        float Dv = sm[O_DD+d];
        float h=0.f;
        for (int l0=0;l0<256;l0+=8){
            float cbuf[8];
            #pragma unroll
            for (int j=0;j<8;j++){
                int l=l0+j;
                float dl  = sm[O_DL+l*32+d];
                float xcv = sm[O_XC+l*32+d];
                float dA  = __expf(dl*A);
                h = dA*h + dl*sm[O_BM+l*16+n]*xcv;
                cbuf[j] = h*sm[O_CM+l*16+n];
            }
            #pragma unroll
            for (int j=0;j<8;j++){
                float c=cbuf[j];
                c += __shfl_xor_sync(0xffffffffu, c, 1);
                c += __shfl_xor_sync(0xffffffffu, c, 2);
                c += __shfl_xor_sync(0xffffffffu, c, 4);
                c += __shfl_xor_sync(0xffffffffu, c, 8);
                cbuf[j]=c;
            }
            if (n==0){
                #pragma unroll
                for (int j=0;j<8;j++){
                    int l=l0+j;
                    sm[O_YY+l*32+d] = cbuf[j] + sm[O_XC+l*32+d]*Dv;
                }
            }
        }
    }
    __syncthreads();

    {
        int l = t & 255;
        int half = t >> 8;
        float yv[32];
        #pragma unroll
        for (int d=0;d<32;d++){
            float zv=sm[O_ZZ+l*32+d];
            yv[d]=sm[O_YY+l*32+d]*(zv*__fdividef(1.f,1.f+__expf(-zv)));
        }
        float* tp = tok + ((size_t)b*4096 + (size_t)l*16);
        int j0 = half*8;
        #pragma unroll
        for (int jj=0;jj<8;jj++){
            float a=0.f;
            #pragma unroll
            for (int d=0;d<32;d++) a += yv[d]*sm[O_OW+(j0+jj)*32+d];
            tp[j0+jj] += a;
        }
    }
}

// ---------------- head: mean-pool + linear + LN ----------------
__global__ void k_head(const float* __restrict__ tok, const float* __restrict__ pw,
                       const float* __restrict__ pb, const float* __restrict__ fg,
                       const float* __restrict__ fb, float* __restrict__ out){
    __shared__ float pooled[16];
    __shared__ float red[16];
    __shared__ float s_mean, s_inv;
    int t=threadIdx.x, b=blockIdx.x;
    if (t<16){
        float s=0.f;
        const float* tp = tok + (size_t)b*4096 + t;
        for (int l=0;l<256;l++) s += tp[l*16];
        pooled[t] = s*(1.f/256.f);
    }
    __syncthreads();
    float lg = pb[t];
    #pragma unroll
    for (int d=0;d<16;d++) lg += pooled[d]*pw[t*16+d];
    float s1v = wred(lg);
    float s2v = wred(lg*lg);
    int w = t>>5;
    if ((t&31)==0){ red[w]=s1v; red[8+w]=s2v; }
    __syncthreads();
    if (t==0){
        float a=0.f,q=0.f;
        for (int i=0;i<8;i++){a+=red[i]; q+=red[8+i];}
        float m=a*(1.f/256.f);
        float v=q*(1.f/256.f)-m*m;
        s_mean=m; s_inv=rsqrtf(v+1e-5f);
    }
    __syncthreads();
    out[b*256+t] = (lg-s_mean)*s_inv*fg[t]+fb[t];
}

// ---------------- launch ----------------
extern "C" void kernel_launch(void* const* d_in, const int* in_sizes, int n_in,
                              void* d_out, int out_size){
    const float* x    = (const float*)d_in[0];
    const float* c1w  = (const float*)d_in[1];
    const float* c1b  = (const float*)d_in[2];
    const float* caw1 = (const float*)d_in[3];
    const float* cab1 = (const float*)d_in[4];
    const float* caw2 = (const float*)d_in[5];
    const float* cab2 = (const float*)d_in[6];
    const float* sw1  = (const float*)d_in[7];
    const float* sw2  = (const float*)d_in[8];
    const float* c2w  = (const float*)d_in[9];
    const float* c2b  = (const float*)d_in[10];
    const float* c3w  = (const float*)d_in[11];
    const float* c3b  = (const float*)d_in[12];
    const float* c4w  = (const float*)d_in[13];
    const float* c4b  = (const float*)d_in[14];
    const float* c5w  = (const float*)d_in[15];
    const float* c5b  = (const float*)d_in[16];
    const float* mlng = (const float*)d_in[17];
    const float* mlnb = (const float*)d_in[18];
    const float* minw = (const float*)d_in[19];
    const float* mcw  = (const float*)d_in[20];
    const float* mcb  = (const float*)d_in[21];
    const float* mxp  = (const float*)d_in[22];
    const float* mdtw = (const float*)d_in[23];
    const float* mdtb = (const float*)d_in[24];
    const float* mal  = (const float*)d_in[25];
    const float* mD   = (const float*)d_in[26];
    const float* mow  = (const float*)d_in[27];
    const float* pw   = (const float*)d_in[28];
    const float* pb   = (const float*)d_in[29];
    const float* fg   = (const float*)d_in[30];
    const float* fb   = (const float*)d_in[31];
    float* out = (float*)d_out;

    float *h1, *s1, *s2, *p1, *r2, *p2, *r3, *p3, *r4, *r5, *tok;
    cudaGetSymbolAddress((void**)&h1, g_h1);
    cudaGetSymbolAddress((void**)&s1, g_s1);
    cudaGetSymbolAddress((void**)&s2, g_s2);
    cudaGetSymbolAddress((void**)&p1, g_p1);
    cudaGetSymbolAddress((void**)&r2, g_r2);
    cudaGetSymbolAddress((void**)&p2, g_p2);
    cudaGetSymbolAddress((void**)&r3, g_r3);
    cudaGetSymbolAddress((void**)&p3, g_p3);
    cudaGetSymbolAddress((void**)&r4, g_r4);
    cudaGetSymbolAddress((void**)&r5, g_r5);
    cudaGetSymbolAddress((void**)&tok, g_tok);

    size_t smem_mamba = SM_FLOATS * sizeof(float);
    cudaFuncSetAttribute(k_mamba, cudaFuncAttributeMaxDynamicSharedMemorySize, (int)smem_mamba);
    size_t smem_s1f = 2*4970*sizeof(float);   // 39760 B, two channel tiles
    cudaFuncSetAttribute(k_s1f, cudaFuncAttributeMaxDynamicSharedMemorySize, (int)smem_s1f);

    k_zero<<<1,128>>>();
    k_conv1<<<dim3(2,32,128), dim3(32,8)>>>(x, c1w, c1b, h1);
    k_s1f<<<dim3(4,4,128), 256, smem_s1f>>>(h1, sw1, caw1, cab1, caw2, cab2, s1);
    k_s2w<<<dim3(8,8,128), 256>>>(s1, sw2, s2);
    k_pool1v<<<4096,256>>>(h1, s2, caw1, cab1, caw2, cab2, p1);
    k_conv2<<<dim3(4,4,128), dim3(16,16)>>>(p1, c2w, c2b, r2);
    k_pool2<<<4096,256>>>(r2, p2);
    k_conv3<<<dim3(2,2,128), dim3(16,16)>>>(p2, c3w, c3b, r3);
    k_pool3<<<2048,256>>>(r3, p3);
    k_conv4<<<dim3(128,2), dim3(16,16)>>>(p3, c4w, c4b, r4);
    k_conv5<<<128,256>>>(r4, c5w, c5b, r5);
    k_tok<<<2048,256>>>(r5, tok);
    for (int layer=0; layer<2; layer++){
        k_mamba<<<128,512,smem_mamba>>>(tok,
            mlng+layer*16, mlnb+layer*16, minw+layer*1024,
            mcw+layer*128, mcb+layer*32, mxp+layer*1056,
            mdtw+layer*32, mdtb+layer*32, mal+layer*512,
            mD+layer*32, mow+layer*512);
    }
    k_head<<<128,256>>>(tok, pw, pb, fg, fb, out);
}

// round 7
// speedup vs baseline: 1.9690x; 1.0210x over previous
#include <cuda_runtime.h>
#include <cuda_bf16.h>
#include <math.h>

// ---------------- constants ----------------
#define N1  8388608.0
#define N2  524288.0
#define N3  131072.0
#define N4  32768.0
#define N5  32768.0

#define S1CH 0
#define SS1  8
#define SS2  12
#define S2CH 16
#define S3   24
#define S4   40
#define S5   72

// ---------------- scratch ----------------
__device__ float g_h1[33554432];
__device__ float g_s2[33554432];
__device__ float g_s1[8388608];
__device__ float g_p1[8388608];
__device__ float g_r2[4194304];
__device__ float g_p2[1048576];
__device__ float g_r3[2097152];
__device__ float g_p3[524288];
__device__ float g_r4[1048576];
__device__ float g_r5[524288];
__device__ double g_sumA[128];
__device__ double g_sqA[128];

// ---------------- helpers ----------------
__device__ __forceinline__ float wred(float v){
    #pragma unroll
    for (int o=16;o>0;o>>=1) v += __shfl_down_sync(0xffffffffu, v, o);
    return v;
}
__device__ __forceinline__ void bn_scale(int off, double N, float& sc, float& sh){
    double m = g_sumA[off]/N;
    double v = g_sqA[off]/N - m*m;
    double s = 1.0/sqrt(v+1e-5);
    sc = (float)s; sh = (float)(-m*s);
}
__device__ __forceinline__ float sigm(float x){
    return __fdividef(1.f, 1.f + __expf(-x));
}

__global__ void k_zero(){
    int t = threadIdx.x;
    if (t < 128){ g_sumA[t]=0.0; g_sqA[t]=0.0; }
}

// ---------------- conv1: 1->4, 5x5, s2, p2 ----------------
__global__ void __launch_bounds__(256) k_conv1(
                        const float* __restrict__ x, const float* __restrict__ w,
                        const float* __restrict__ bias, float* __restrict__ out){
    __shared__ float t[19][260];
    __shared__ float ws[100];
    __shared__ float wb[4];
    __shared__ float ssum[4], ssq[4];
    int tx = threadIdx.x, ty = threadIdx.y;
    int tid = ty*32 + tx;
    int b = blockIdx.z;
    if (tid < 100) ws[tid] = w[tid];
    if (tid < 4){ wb[tid] = bias[tid]; ssum[tid]=0.f; ssq[tid]=0.f; }
    int oy0 = blockIdx.y*8, ox0 = blockIdx.x*128;
    int iy0 = 2*oy0 - 2, ix0 = 2*ox0 - 2;
    const float* xb = x + (size_t)b*262144;
    for (int i = tid; i < 19*259; i += 256){
        int r = i/259, c = i%259;
        int iy = iy0 + r, ix = ix0 + c;
        float v = 0.f;
        if (iy>=0 && iy<512 && ix>=0 && ix<512) v = xb[iy*512+ix];
        t[r][c] = v;
    }
    __syncthreads();
    float acc[16];
    #pragma unroll
    for (int oc=0;oc<4;oc++)
        #pragma unroll
        for (int dx=0;dx<4;dx++) acc[oc*4+dx] = wb[oc];
    int colb = 8*tx;
    #pragma unroll
    for (int ky=0; ky<5; ky++){
        float rv[11];
        const float* row = &t[2*ty+ky][colb];
        float4 v0 = *(const float4*)row;
        float4 v1 = *(const float4*)(row+4);
        float2 v2 = *(const float2*)(row+8);
        rv[0]=v0.x; rv[1]=v0.y; rv[2]=v0.z; rv[3]=v0.w;
        rv[4]=v1.x; rv[5]=v1.y; rv[6]=v1.z; rv[7]=v1.w;
        rv[8]=v2.x; rv[9]=v2.y; rv[10]=row[10];
        #pragma unroll
        for (int oc=0;oc<4;oc++){
            #pragma unroll
            for (int kx=0;kx<5;kx++){
                float wv = ws[oc*25+ky*5+kx];
                #pragma unroll
                for (int dx=0;dx<4;dx++)
                    acc[oc*4+dx] += rv[2*dx+kx]*wv;
            }
        }
    }
    int oy = oy0 + ty, ox = ox0 + 4*tx;
    #pragma unroll
    for (int oc=0;oc<4;oc++){
        float4 v = make_float4(acc[oc*4],acc[oc*4+1],acc[oc*4+2],acc[oc*4+3]);
        *(float4*)&out[(size_t)b*262144 + (size_t)oc*65536 + (size_t)oy*256 + ox] = v;
        float s = v.x+v.y+v.z+v.w;
        float q = v.x*v.x+v.y*v.y+v.z*v.z+v.w*v.w;
        s = wred(s); q = wred(q);
        if ((tid&31)==0){ atomicAdd(&ssum[oc], s); atomicAdd(&ssq[oc], q); }
    }
    __syncthreads();
    if (tid < 4){
        atomicAdd(&g_sumA[S1CH+tid], (double)ssum[tid]);
        atomicAdd(&g_sqA[S1CH+tid],  (double)ssq[tid]);
    }
}

// ---------------- s1 fused: xg inline (2 ch/pass), conv7x7 4->1, stats -------
// tile stride 72 for vector LDS. dyn smem 2*70*72 floats.
__global__ void __launch_bounds__(256) k_s1f(
                      const float* __restrict__ h1, const float* __restrict__ w,
                      const float* __restrict__ caw1, const float* __restrict__ cab1,
                      const float* __restrict__ caw2, const float* __restrict__ cab2,
                      float* __restrict__ s1){
    extern __shared__ float xt[];   // 2 * 5040 floats
    __shared__ float wsm[196];
    __shared__ float sc[4], sh[4];
    __shared__ float a1w[4], a2w[4], a2b[4];
    __shared__ float a1b;
    __shared__ float ssum, ssq;
    int tid = threadIdx.x;
    int b = blockIdx.z;
    if (tid<196) wsm[tid]=w[tid];
    if (tid<4){ bn_scale(S1CH+tid, N1, sc[tid], sh[tid]);
                a1w[tid]=caw1[tid]; a2w[tid]=caw2[tid]; a2b[tid]=cab2[tid]; }
    if (tid==0){ a1b=cab1[0]; ssum=0.f; ssq=0.f; }
    __syncthreads();
    int y0 = blockIdx.y*64 - 3, x0 = blockIdx.x*64 - 3;
    const float* hb = h1 + (size_t)b*262144;
    int tyy=tid>>4, txx=tid&15;
    int r0=tyy*4, c0=txx*4;
    float acc[16];
    #pragma unroll
    for (int i=0;i<16;i++) acc[i]=0.f;
    #pragma unroll
    for (int pass=0; pass<2; pass++){
        if (pass) __syncthreads();
        int cA = 2*pass, cB = 2*pass+1;
        for (int i=tid; i<4900; i+=256){
            int r=i/70, cc=i%70;
            int sy=min(max(y0+r,0),255), sx=min(max(x0+cc,0),255);
            int off = sy*256+sx;
            float a0 = fmaxf(hb[off         ]*sc[0]+sh[0], 0.f);
            float a1 = fmaxf(hb[off+  65536 ]*sc[1]+sh[1], 0.f);
            float a2 = fmaxf(hb[off+ 131072 ]*sc[2]+sh[2], 0.f);
            float a3 = fmaxf(hb[off+ 196608 ]*sc[3]+sh[3], 0.f);
            float hid = fmaxf(a1b + a0*a1w[0]+a1*a1w[1]+a2*a1w[2]+a3*a1w[3], 0.f);
            float aA = (cA==0)?a0:a2;
            float aB = (cA==0)?a1:a3;
            int p = r*72+cc;
            xt[p       ] = aA*(hid*a2w[cA]+a2b[cA]);
            xt[p+5040  ] = aB*(hid*a2w[cB]+a2b[cB]);
        }
        __syncthreads();
        #pragma unroll
        for (int half=0; half<2; half++){
            int c = 2*pass + half;
            float wr[49];
            #pragma unroll
            for (int k=0;k<49;k++) wr[k]=wsm[c*49+k];
            const float* tb = &xt[half*5040];
            #pragma unroll
            for (int r=0;r<10;r++){
                float rv[10];
                const float* row = &tb[(r0+r)*72 + c0];
                float4 v0 = *(const float4*)row;
                float4 v1 = *(const float4*)(row+4);
                float2 v2 = *(const float2*)(row+8);
                rv[0]=v0.x; rv[1]=v0.y; rv[2]=v0.z; rv[3]=v0.w;
                rv[4]=v1.x; rv[5]=v1.y; rv[6]=v1.z; rv[7]=v1.w;
                rv[8]=v2.x; rv[9]=v2.y;
                #pragma unroll
                for (int dy=0;dy<4;dy++){
                    int ky=r-dy;
                    if (ky>=0 && ky<7){
                        #pragma unroll
                        for (int dx=0;dx<4;dx++){
                            float a=acc[dy*4+dx];
                            #pragma unroll
                            for (int kx=0;kx<7;kx++) a += rv[dx+kx]*wr[ky*7+kx];
                            acc[dy*4+dx]=a;
                        }
                    }
                }
            }
        }
    }
    int oy=blockIdx.y*64 + r0, ox=blockIdx.x*64 + c0;
    float s=0.f, q=0.f;
    #pragma unroll
    for (int dy=0;dy<4;dy++){
        float4 v = make_float4(acc[dy*4],acc[dy*4+1],acc[dy*4+2],acc[dy*4+3]);
        *(float4*)&s1[(size_t)b*65536 + (size_t)(oy+dy)*256 + ox] = v;
        s += v.x+v.y+v.z+v.w;
        q += v.x*v.x+v.y*v.y+v.z*v.z+v.w*v.w;
    }
    s=wred(s); q=wred(q);
    if ((tid&31)==0){ atomicAdd(&ssum,s); atomicAdd(&ssq,q); }
    __syncthreads();
    if (tid==0){ atomicAdd(&g_sumA[SS1],(double)ssum); atomicAdd(&g_sqA[SS1],(double)ssq); }
}

// ---------------- s2w: conv7x7 1->4, stats + write raw s2 (stride-40 tile) ---
__global__ void k_s2w(const float* __restrict__ s1, const float* __restrict__ w,
                      float* __restrict__ s2){
    __shared__ float t[38*40];
    __shared__ float wsm[196];
    __shared__ float sc1_, sh1_;
    __shared__ float ssum[4], ssq[4];
    int tid = threadIdx.x;
    int b = blockIdx.z;
    if (tid<196) wsm[tid]=w[tid];
    if (tid==0) bn_scale(SS1, N1, sc1_, sh1_);
    if (tid<4){ ssum[tid]=0.f; ssq[tid]=0.f; }
    __syncthreads();
    int y0 = blockIdx.y*32 - 3, x0 = blockIdx.x*32 - 3;
    const float* sb = s1 + (size_t)b*65536;
    for (int i=tid; i<1444; i+=256){
        int r=i/38, cc=i%38;
        int sy=min(max(y0+r,0),255), sx=min(max(x0+cc,0),255);
        t[r*40+cc] = fmaxf(sb[sy*256+sx]*sc1_+sh1_, 0.f);
    }
    __syncthreads();
    int oc = tid>>6, t64 = tid&63;
    int tyy = t64>>3, txx = t64&7;
    int r0=tyy*4, c0=txx*4;
    float wr[49];
    #pragma unroll
    for (int k=0;k<49;k++) wr[k]=wsm[oc*49+k];
    float acc[16];
    #pragma unroll
    for (int i=0;i<16;i++) acc[i]=0.f;
    #pragma unroll
    for (int r=0;r<10;r++){
        float rv[10];
        const float* row = &t[(r0+r)*40 + c0];
        float4 v0 = *(const float4*)row;
        float4 v1 = *(const float4*)(row+4);
        float2 v2 = *(const float2*)(row+8);
        rv[0]=v0.x; rv[1]=v0.y; rv[2]=v0.z; rv[3]=v0.w;
        rv[4]=v1.x; rv[5]=v1.y; rv[6]=v1.z; rv[7]=v1.w;
        rv[8]=v2.x; rv[9]=v2.y;
        #pragma unroll
        for (int dy=0;dy<4;dy++){
            int ky=r-dy;
            if (ky>=0 && ky<7){
                #pragma unroll
                for (int dx=0;dx<4;dx++){
                    float a=acc[dy*4+dx];
                    #pragma unroll
                    for (int kx=0;kx<7;kx++) a += rv[dx+kx]*wr[ky*7+kx];
                    acc[dy*4+dx]=a;
                }
            }
        }
    }
    int oy = blockIdx.y*32 + r0, ox = blockIdx.x*32 + c0;
    size_t base = (size_t)b*262144 + (size_t)oc*65536;
    float s=0.f,q=0.f;
    #pragma unroll
    for (int dy=0;dy<4;dy++){
        float4 v = make_float4(acc[dy*4],acc[dy*4+1],acc[dy*4+2],acc[dy*4+3]);
        *(float4*)&s2[base + (size_t)(oy+dy)*256 + ox] = v;
        s += v.x+v.y+v.z+v.w;
        q += v.x*v.x+v.y*v.y+v.z*v.z+v.w*v.w;
    }
    s=wred(s); q=wred(q);
    if ((tid&31)==0){ atomicAdd(&ssum[oc],s); atomicAdd(&ssq[oc],q); }
    __syncthreads();
    if (tid<4){
        atomicAdd(&g_sumA[SS2+tid],(double)ssum[tid]);
        atomicAdd(&g_sqA[SS2+tid], (double)ssq[tid]);
    }
}

// ---------------- pool1v ----------------
__global__ void k_pool1v(const float* __restrict__ h1, const float* __restrict__ s2,
                         const float* __restrict__ caw1, const float* __restrict__ cab1,
                         const float* __restrict__ caw2, const float* __restrict__ cab2,
                         float* __restrict__ p1){
    __shared__ float scA[4], shA[4], sc2[4], sh2[4];
    __shared__ float a1w[4], a2w[4], a2b[4];
    __shared__ float a1b;
    int tid = threadIdx.x;
    if (tid<4){
        bn_scale(S1CH+tid, N1, scA[tid], shA[tid]);
        bn_scale(SS2+tid,  N1, sc2[tid], sh2[tid]);
        a1w[tid]=caw1[tid]; a2w[tid]=caw2[tid]; a2b[tid]=cab2[tid];
    }
    if (tid==0) a1b=cab1[0];
    __syncthreads();
    int idx = blockIdx.x*256 + tid;
    int xp2 = idx & 63;
    int oy  = (idx>>6) & 127;
    int b   = idx>>13;
    size_t rowbase = (size_t)b*262144 + (size_t)(2*oy)*256 + 4*xp2;
    float m[4][2];
    #pragma unroll
    for (int c=0;c<4;c++){ m[c][0]=-1e30f; m[c][1]=-1e30f; }
    #pragma unroll
    for (int dy=0;dy<2;dy++){
        size_t ro = rowbase + (size_t)dy*256;
        float4 h[4], g[4];
        #pragma unroll
        for (int c=0;c<4;c++){
            h[c] = *(const float4*)&h1[ro + (size_t)c*65536];
            g[c] = *(const float4*)&s2[ro + (size_t)c*65536];
        }
        #pragma unroll
        for (int j=0;j<4;j++){
            float a[4], gv[4];
            #pragma unroll
            for (int c=0;c<4;c++){
                float hv = (j==0)?h[c].x:(j==1)?h[c].y:(j==2)?h[c].z:h[c].w;
                gv[c]    = (j==0)?g[c].x:(j==1)?g[c].y:(j==2)?g[c].z:g[c].w;
                a[c] = fmaxf(hv*scA[c]+shA[c], 0.f);
            }
            float hid = fmaxf(a1b + a[0]*a1w[0]+a[1]*a1w[1]+a[2]*a1w[2]+a[3]*a1w[3], 0.f);
            int half = j>>1;
            #pragma unroll
            for (int c=0;c<4;c++){
                float sv = sigm(gv[c]*sc2[c]+sh2[c]);
                float xv = a[c]*(hid*a2w[c]+a2b[c]);
                m[c][half] = fmaxf(m[c][half], xv*sv);
            }
        }
    }
    size_t ob = (size_t)b*65536 + (size_t)oy*128 + 2*xp2;
    #pragma unroll
    for (int c=0;c<4;c++)
        *(float2*)&p1[ob + (size_t)c*16384] = make_float2(m[c][0], m[c][1]);
}

// ---------------- conv2 ----------------
__global__ void k_conv2(const float* __restrict__ in, const float* __restrict__ w,
                        const float* __restrict__ bias, float* __restrict__ out){
    __shared__ float t[4][33][33];
    __shared__ float ws[288];
    __shared__ float wb[8];
    __shared__ float ssum[8], ssq[8];
    int tid = threadIdx.y*16+threadIdx.x;
    int b = blockIdx.z;
    for (int i=tid;i<288;i+=256) ws[i]=w[i];
    if (tid<8){ wb[tid]=bias[tid]; ssum[tid]=0.f; ssq[tid]=0.f; }
    int iy0 = blockIdx.y*32-1, ix0 = blockIdx.x*32-1;
    for (int i=tid; i<4*1089; i+=256){
        int c=i/1089; int r=(i%1089)/33; int cc=i%33;
        int iy=iy0+r, ix=ix0+cc;
        float v=0.f;
        if (iy>=0&&iy<128&&ix>=0&&ix<128)
            v = in[(size_t)b*65536 + (size_t)c*16384 + iy*128+ix];
        t[c][r][cc]=v;
    }
    __syncthreads();
    int ty=threadIdx.y, tx=threadIdx.x;
    float acc[8];
    #pragma unroll
    for (int oc=0;oc<8;oc++) acc[oc]=wb[oc];
    #pragma unroll
    for (int ci=0;ci<4;ci++)
        #pragma unroll
        for (int ky=0;ky<3;ky++)
            #pragma unroll
            for (int kx=0;kx<3;kx++){
                float v = t[ci][2*ty+ky][2*tx+kx];
                #pragma unroll
                for (int oc=0;oc<8;oc++) acc[oc]+=v*ws[oc*36+ci*9+ky*3+kx];
            }
    int oy = blockIdx.y*16+ty, ox = blockIdx.x*16+tx;
    #pragma unroll
    for (int oc=0;oc<8;oc++)
        out[(size_t)b*32768 + (size_t)oc*4096 + oy*64+ox] = acc[oc];
    #pragma unroll
    for (int oc=0;oc<8;oc++){
        float s=wred(acc[oc]), q=wred(acc[oc]*acc[oc]);
        if ((tid&31)==0){ atomicAdd(&ssum[oc],s); atomicAdd(&ssq[oc],q); }
    }
    __syncthreads();
    if (tid<8){
        atomicAdd(&g_sumA[S2CH+tid], (double)ssum[tid]);
        atomicAdd(&g_sqA[S2CH+tid],  (double)ssq[tid]);
    }
}

// ---------------- pool2 ----------------
__global__ void k_pool2(const float* __restrict__ r2, float* __restrict__ p2){
    __shared__ float sc[8], sh[8];
    int tid=threadIdx.x;
    if (tid<8) bn_scale(S2CH+tid, N2, sc[tid], sh[tid]);
    __syncthreads();
    int idx = blockIdx.x*256+tid;
    int ox=idx&31; int oy=(idx>>5)&31; int c=(idx>>10)&7; int b=idx>>13;
    size_t base = (size_t)b*32768 + (size_t)c*4096;
    float m=-1e30f;
    #pragma unroll
    for (int dy=0;dy<2;dy++)
        #pragma unroll
        for (int dx=0;dx<2;dx++){
            float v = r2[base + (size_t)(2*oy+dy)*64 + (2*ox+dx)]*sc[c]+sh[c];
            v = v>0.f?v:0.f;
            m = fmaxf(m,v);
        }
    p2[(size_t)b*8192 + (size_t)c*1024 + oy*32+ox] = m;
}

// ---------------- conv3 ----------------
__global__ void k_conv3(const float* __restrict__ in, const float* __restrict__ w,
                        const float* __restrict__ bias, float* __restrict__ out){
    __shared__ float t[8][18][18];
    __shared__ float ws[1152];
    __shared__ float wb[16];
    __shared__ float ssum[16], ssq[16];
    int tid = threadIdx.y*16+threadIdx.x;
    int b = blockIdx.z;
    for (int i=tid;i<1152;i+=256) ws[i]=w[i];
    if (tid<16){ wb[tid]=bias[tid]; ssum[tid]=0.f; ssq[tid]=0.f; }
    int iy0 = blockIdx.y*16-1, ix0 = blockIdx.x*16-1;
    for (int i=tid;i<8*324;i+=256){
        int c=i/324; int r=(i%324)/18; int cc=i%18;
        int iy=iy0+r, ix=ix0+cc;
        float v=0.f;
        if (iy>=0&&iy<32&&ix>=0&&ix<32)
            v = in[(size_t)b*8192 + (size_t)c*1024 + iy*32+ix];
        t[c][r][cc]=v;
    }
    __syncthreads();
    int ty=threadIdx.y, tx=threadIdx.x;
    float acc[16];
    #pragma unroll
    for (int oc=0;oc<16;oc++) acc[oc]=wb[oc];
    #pragma unroll
    for (int ci=0;ci<8;ci++)
        #pragma unroll
        for (int ky=0;ky<3;ky++)
            #pragma unroll
            for (int kx=0;kx<3;kx++){
                float v=t[ci][ty+ky][tx+kx];
                #pragma unroll
                for (int oc=0;oc<16;oc++) acc[oc]+=v*ws[oc*72+ci*9+ky*3+kx];
            }
    int oy=blockIdx.y*16+ty, ox=blockIdx.x*16+tx;
    #pragma unroll
    for (int oc=0;oc<16;oc++)
        out[(size_t)b*16384 + (size_t)oc*1024 + oy*32+ox]=acc[oc];
    #pragma unroll
    for (int oc=0;oc<16;oc++){
        float s=wred(acc[oc]), q=wred(acc[oc]*acc[oc]);
        if ((tid&31)==0){ atomicAdd(&ssum[oc],s); atomicAdd(&ssq[oc],q); }
    }
    __syncthreads();
    if (tid<16){
        atomicAdd(&g_sumA[S3+tid], (double)ssum[tid]);
        atomicAdd(&g_sqA[S3+tid],  (double)ssq[tid]);
    }
}

// ---------------- pool3 ----------------
__global__ void k_pool3(const float* __restrict__ r3, float* __restrict__ p3){
    __shared__ float sc[16], sh[16];
    int tid=threadIdx.x;
    if (tid<16) bn_scale(S3+tid, N3, sc[tid], sh[tid]);
    __syncthreads();
    int idx = blockIdx.x*256+tid;
    int ox=idx&15; int oy=(idx>>4)&15; int c=(idx>>8)&15; int b=idx>>12;
    size_t base=(size_t)b*16384 + (size_t)c*1024;
    float m=-1e30f;
    #pragma unroll
    for (int dy=0;dy<2;dy++)
        #pragma unroll
        for (int dx=0;dx<2;dx++){
            float v=r3[base + (size_t)(2*oy+dy)*32 + (2*ox+dx)]*sc[c]+sh[c];
            v=v>0.f?v:0.f;
            m=fmaxf(m,v);
        }
    p3[(size_t)b*4096 + (size_t)c*256 + oy*16+ox]=m;
}

// ---------------- conv4 (split 2 oc-halves) ----------------
__global__ void k_conv4(const float* __restrict__ in, const float* __restrict__ w,
                        const float* __restrict__ bias, float* __restrict__ out){
    __shared__ float t[16][18][18];
    __shared__ float ws[2304];
    __shared__ float wb[16];
    __shared__ float ssum[16], ssq[16];
    int tid = threadIdx.y*16+threadIdx.x;
    int b = blockIdx.x;
    int ocb = blockIdx.y*16;
    for (int i=tid;i<2304;i+=256) ws[i]=w[ocb*144+i];
    if (tid<16){ wb[tid]=bias[ocb+tid]; ssum[tid]=0.f; ssq[tid]=0.f; }
    for (int i=tid;i<16*324;i+=256){
        int c=i/324; int r=(i%324)/18; int cc=i%18;
        int iy=r-1, ix=cc-1;
        float v=0.f;
        if (iy>=0&&iy<16&&ix>=0&&ix<16)
            v = in[(size_t)b*4096 + (size_t)c*256 + iy*16+ix];
        t[c][r][cc]=v;
    }
    __syncthreads();
    int ty=threadIdx.y, tx=threadIdx.x;
    float acc[16];
    #pragma unroll
    for (int oc=0;oc<16;oc++) acc[oc]=wb[oc];
    #pragma unroll
    for (int ci=0;ci<16;ci++)
        #pragma unroll
        for (int ky=0;ky<3;ky++)
            #pragma unroll
            for (int kx=0;kx<3;kx++){
                float v=t[ci][ty+ky][tx+kx];
                #pragma unroll
                for (int oc=0;oc<16;oc++) acc[oc]+=v*ws[oc*144+ci*9+ky*3+kx];
            }
    #pragma unroll
    for (int oc=0;oc<16;oc++)
        out[(size_t)b*8192 + (size_t)(ocb+oc)*256 + ty*16+tx]=acc[oc];
    #pragma unroll
    for (int oc=0;oc<16;oc++){
        float s=wred(acc[oc]), q=wred(acc[oc]*acc[oc]);
        if ((tid&31)==0){ atomicAdd(&ssum[oc],s); atomicAdd(&ssq[oc],q); }
    }
    __syncthreads();
    if (tid<16){
        atomicAdd(&g_sumA[S4+ocb+tid], (double)ssum[tid]);
        atomicAdd(&g_sqA[S4+ocb+tid],  (double)ssq[tid]);
    }
}

// ---------------- conv5 ----------------
__global__ void k_conv5(const float* __restrict__ r4, const float* __restrict__ w,
                        const float* __restrict__ bias, float* __restrict__ out){
    __shared__ float sc[32], sh[32];
    __shared__ float ws[512];
    __shared__ float wb[16];
    __shared__ float ssum[16], ssq[16];
    int tid=threadIdx.x;
    if (tid<32) bn_scale(S4+tid, N4, sc[tid], sh[tid]);
    for (int i=tid;i<512;i+=256) ws[i]=w[i];
    if (tid<16){ wb[tid]=bias[tid]; ssum[tid]=0.f; ssq[tid]=0.f; }
    __syncthreads();
    int idx = blockIdx.x*256+tid;
    int b = idx>>8; int p = idx&255;
    float a[32];
    #pragma unroll
    for (int ci=0;ci<32;ci++){
        float v = r4[(size_t)b*8192 + (size_t)ci*256 + p]*sc[ci]+sh[ci];
        a[ci]=v>0.f?v:0.f;
    }
    float accs[16];
    #pragma unroll
    for (int oc=0;oc<16;oc++){
        float acc=wb[oc];
        #pragma unroll
        for (int ci=0;ci<32;ci++) acc += a[ci]*ws[oc*32+ci];
        out[(size_t)b*4096 + (size_t)oc*256 + p]=acc;
        accs[oc]=acc;
    }
    #pragma unroll
    for (int oc=0;oc<16;oc++){
        float s=wred(accs[oc]), q=wred(accs[oc]*accs[oc]);
        if ((tid&31)==0){ atomicAdd(&ssum[oc],s); atomicAdd(&ssq[oc],q); }
    }
    __syncthreads();
    if (tid<16){
        atomicAdd(&g_sumA[S5+tid], (double)ssum[tid]);
        atomicAdd(&g_sqA[S5+tid],  (double)ssq[tid]);
    }
}

// ---------------- fused: tok build + 2 mamba layers + head ----------------
#define O_WIN 0
#define O_CW  1024
#define O_CB  1152
#define O_XP  1184
#define O_DTW 2240
#define O_DTB 2272
#define O_AE  2304
#define O_DD  2816
#define O_OW  2848
#define O_LNG 3360
#define O_LNB 3376
#define O_XI  3392
#define O_ZZ  11584
#define O_XC  19776
#define O_DL  27968
#define O_BM  36160
#define O_CM  40256
#define O_YY  44352
#define O_TOK 52544
#define SM2_FLOATS 56640   // 226560 B

__global__ void k_mambah(const float* __restrict__ r5,
    const float* __restrict__ mlng, const float* __restrict__ mlnb,
    const float* __restrict__ minw, const float* __restrict__ mcw,
    const float* __restrict__ mcb,  const float* __restrict__ mxp,
    const float* __restrict__ mdtw, const float* __restrict__ mdtb,
    const float* __restrict__ mal,  const float* __restrict__ mD,
    const float* __restrict__ mow,
    const float* __restrict__ pw, const float* __restrict__ pb,
    const float* __restrict__ fg, const float* __restrict__ fb,
    float* __restrict__ out)
{
    extern __shared__ float sm[];
    __shared__ float sc5[16], sh5[16];
    __shared__ float pooled[16], red[16];
    __shared__ float s_mean, s_inv;
    int t = threadIdx.x; int b = blockIdx.x;

    // build tok in smem from r5 (BN + relu + transpose)
    if (t<16) bn_scale(S5+t, N5, sc5[t], sh5[t]);
    __syncthreads();
    if (t < 256){
        int l=t;
        #pragma unroll
        for (int d=0;d<16;d++){
            float v = r5[(size_t)b*4096 + (size_t)d*256 + l]*sc5[d]+sh5[d];
            sm[O_TOK + l*16 + d] = v>0.f?v:0.f;
        }
    }

    for (int layer=0; layer<2; layer++){
        const float* lng = mlng + layer*16;
        const float* lnb = mlnb + layer*16;
        const float* inw = minw + layer*1024;
        const float* cw  = mcw  + layer*128;
        const float* cb  = mcb  + layer*32;
        const float* xpw = mxp  + layer*1056;
        const float* dtw = mdtw + layer*32;
        const float* dtb = mdtb + layer*32;
        const float* alog= mal  + layer*512;
        const float* dvec= mD   + layer*32;
        const float* ow  = mow  + layer*512;
        __syncthreads();
        for (int i=t;i<1024;i+=512) sm[O_WIN+i]=inw[i];
        for (int i=t;i<128;i+=512)  sm[O_CW+i]=cw[i];
        for (int i=t;i<1056;i+=512) sm[O_XP+i]=xpw[i];
        for (int i=t;i<512;i+=512){ sm[O_AE+i]=-expf(alog[i]); sm[O_OW+i]=ow[i]; }
        if (t<32){ sm[O_CB+t]=cb[t]; sm[O_DTW+t]=dtw[t]; sm[O_DTB+t]=dtb[t]; sm[O_DD+t]=dvec[t]; }
        if (t<16){ sm[O_LNG+t]=lng[t]; sm[O_LNB+t]=lnb[t]; }
        __syncthreads();

        // step 1: LN + in_proj
        {
            int l = t & 255;
            int half = t >> 8;
            float v[16];
            float mean=0.f;
            #pragma unroll
            for (int d=0;d<16;d++){ v[d]=sm[O_TOK+l*16+d]; mean+=v[d]; }
            mean *= 0.0625f;
            float var=0.f;
            #pragma unroll
            for (int d=0;d<16;d++){ float dd=v[d]-mean; var+=dd*dd; }
            var *= 0.0625f;
            float inv = rsqrtf(var+1e-5f);
            #pragma unroll
            for (int d=0;d<16;d++) v[d]=(v[d]-mean)*inv*sm[O_LNG+d]+sm[O_LNB+d];
            int j0 = half*32;
            float* dst = (half==0) ? &sm[O_XI+l*32] : &sm[O_ZZ+l*32];
            for (int jj=0;jj<32;jj++){
                float a=0.f;
                #pragma unroll
                for (int d=0;d<16;d++) a += v[d]*sm[O_WIN+(j0+jj)*16+d];
                dst[jj]=a;
            }
        }
        __syncthreads();

        // step 2: depthwise causal conv + silu
        if (t < 256){
            int l=t;
            for (int d=0;d<32;d++){
                float a = sm[O_CB+d];
                #pragma unroll
                for (int k=0;k<4;k++){
                    int ll=l-3+k;
                    if (ll>=0) a += sm[O_CW+d*4+k]*sm[O_XI+ll*32+d];
                }
                sm[O_XC+l*32+d] = a*__fdividef(1.f, 1.f+__expf(-a));
            }
        }
        __syncthreads();

        // step 3: x_proj
        {
            int l = t & 255;
            int half = t >> 8;
            float xcl[32];
            #pragma unroll
            for (int d=0;d<32;d++) xcl[d]=sm[O_XC+l*32+d];
            if (half==0){
                float dtv=0.f;
                #pragma unroll
                for (int d=0;d<32;d++) dtv += xcl[d]*sm[O_XP+d];
                for (int n=0;n<16;n++){
                    float bb=0.f;
                    #pragma unroll
                    for (int d=0;d<32;d++) bb += xcl[d]*sm[O_XP+(1+n)*32+d];
                    sm[O_BM+l*16+n]=bb;
                }
                for (int d=0;d<32;d++){
                    float pre = dtv*sm[O_DTW+d]+sm[O_DTB+d];
                    float sp = (pre>20.f)? pre : log1pf(__expf(pre));
                    sm[O_DL+l*32+d]=sp;
                }
            } else {
                for (int n=0;n<16;n++){
                    float cc=0.f;
                    #pragma unroll
                    for (int d=0;d<32;d++) cc += xcl[d]*sm[O_XP+(17+n)*32+d];
                    sm[O_CM+l*16+n]=cc;
                }
            }
        }
        __syncthreads();

        // step 4: selective scan
        {
            int d = t>>4, n = t&15;
            float A  = sm[O_AE+d*16+n];
            float Dv = sm[O_DD+d];
            float h=0.f;
            for (int l0=0;l0<256;l0+=8){
                float cbuf[8];
                #pragma unroll
                for (int j=0;j<8;j++){
                    int l=l0+j;
                    float dl  = sm[O_DL+l*32+d];
                    float xcv = sm[O_XC+l*32+d];
                    float dA  = __expf(dl*A);
                    h = dA*h + dl*sm[O_BM+l*16+n]*xcv;
                    cbuf[j] = h*sm[O_CM+l*16+n];
                }
                #pragma unroll
                for (int j=0;j<8;j++){
                    float c=cbuf[j];
                    c += __shfl_xor_sync(0xffffffffu, c, 1);
                    c += __shfl_xor_sync(0xffffffffu, c, 2);
                    c += __shfl_xor_sync(0xffffffffu, c, 4);
                    c += __shfl_xor_sync(0xffffffffu, c, 8);
                    cbuf[j]=c;
                }
                if (n==0){
                    #pragma unroll
                    for (int j=0;j<8;j++){
                        int l=l0+j;
                        sm[O_YY+l*32+d] = cbuf[j] + sm[O_XC+l*32+d]*Dv;
                    }
                }
            }
        }
        __syncthreads();

        // step 5: gate + out_proj, residual into tok-smem
        {
            int l = t & 255;
            int half = t >> 8;
            float yv[32];
            #pragma unroll
            for (int d=0;d<32;d++){
                float zv=sm[O_ZZ+l*32+d];
                yv[d]=sm[O_YY+l*32+d]*(zv*__fdividef(1.f,1.f+__expf(-zv)));
            }
            int j0 = half*8;
            #pragma unroll
            for (int jj=0;jj<8;jj++){
                float a=0.f;
                #pragma unroll
                for (int d=0;d<32;d++) a += yv[d]*sm[O_OW+(j0+jj)*32+d];
                sm[O_TOK + l*16 + j0+jj] += a;
            }
        }
    }
    __syncthreads();

    // head: mean-pool + linear + LN
    if (t<16){
        float s=0.f;
        for (int l=0;l<256;l++) s += sm[O_TOK + l*16 + t];
        pooled[t] = s*(1.f/256.f);
    }
    __syncthreads();
    float lg = 0.f;
    if (t<256){
        lg = pb[t];
        #pragma unroll
        for (int d=0;d<16;d++) lg += pooled[d]*pw[t*16+d];
        float s1v = wred(lg);
        float s2v = wred(lg*lg);
        int w = t>>5;
        if ((t&31)==0){ red[w]=s1v; red[8+w]=s2v; }
    }
    __syncthreads();
    if (t==0){
        float a=0.f,q=0.f;
        for (int i=0;i<8;i++){a+=red[i]; q+=red[8+i];}
        float m=a*(1.f/256.f);
        float v=q*(1.f/256.f)-m*m;
        s_mean=m; s_inv=rsqrtf(v+1e-5f);
    }
    __syncthreads();
    if (t<256)
        out[b*256+t] = (lg-s_mean)*s_inv*fg[t]+fb[t];
}

// ---------------- launch ----------------
extern "C" void kernel_launch(void* const* d_in, const int* in_sizes, int n_in,
                              void* d_out, int out_size){
    const float* x    = (const float*)d_in[0];
    const float* c1w  = (const float*)d_in[1];
    const float* c1b  = (const float*)d_in[2];
    const float* caw1 = (const float*)d_in[3];
    const float* cab1 = (const float*)d_in[4];
    const float* caw2 = (const float*)d_in[5];
    const float* cab2 = (const float*)d_in[6];
    const float* sw1  = (const float*)d_in[7];
    const float* sw2  = (const float*)d_in[8];
    const float* c2w  = (const float*)d_in[9];
    const float* c2b  = (const float*)d_in[10];
    const float* c3w  = (const float*)d_in[11];
    const float* c3b  = (const float*)d_in[12];
    const float* c4w  = (const float*)d_in[13];
    const float* c4b  = (const float*)d_in[14];
    const float* c5w  = (const float*)d_in[15];
    const float* c5b  = (const float*)d_in[16];
    const float* mlng = (const float*)d_in[17];
    const float* mlnb = (const float*)d_in[18];
    const float* minw = (const float*)d_in[19];
    const float* mcw  = (const float*)d_in[20];
    const float* mcb  = (const float*)d_in[21];
    const float* mxp  = (const float*)d_in[22];
    const float* mdtw = (const float*)d_in[23];
    const float* mdtb = (const float*)d_in[24];
    const float* mal  = (const float*)d_in[25];
    const float* mD   = (const float*)d_in[26];
    const float* mow  = (const float*)d_in[27];
    const float* pw   = (const float*)d_in[28];
    const float* pb   = (const float*)d_in[29];
    const float* fg   = (const float*)d_in[30];
    const float* fb   = (const float*)d_in[31];
    float* out = (float*)d_out;

    float *h1, *s1, *s2, *p1, *r2, *p2, *r3, *p3, *r4, *r5;
    cudaGetSymbolAddress((void**)&h1, g_h1);
    cudaGetSymbolAddress((void**)&s1, g_s1);
    cudaGetSymbolAddress((void**)&s2, g_s2);
    cudaGetSymbolAddress((void**)&p1, g_p1);
    cudaGetSymbolAddress((void**)&r2, g_r2);
    cudaGetSymbolAddress((void**)&p2, g_p2);
    cudaGetSymbolAddress((void**)&r3, g_r3);
    cudaGetSymbolAddress((void**)&p3, g_p3);
    cudaGetSymbolAddress((void**)&r4, g_r4);
    cudaGetSymbolAddress((void**)&r5, g_r5);

    size_t smem_mh = SM2_FLOATS * sizeof(float);
    cudaFuncSetAttribute(k_mambah, cudaFuncAttributeMaxDynamicSharedMemorySize, (int)smem_mh);
    size_t smem_s1f = 2*5040*sizeof(float);   // 40320 B
    cudaFuncSetAttribute(k_s1f, cudaFuncAttributeMaxDynamicSharedMemorySize, (int)smem_s1f);

    k_zero<<<1,128>>>();
    k_conv1<<<dim3(2,32,128), dim3(32,8)>>>(x, c1w, c1b, h1);
    k_s1f<<<dim3(4,4,128), 256, smem_s1f>>>(h1, sw1, caw1, cab1, caw2, cab2, s1);
    k_s2w<<<dim3(8,8,128), 256>>>(s1, sw2, s2);
    k_pool1v<<<4096,256>>>(h1, s2, caw1, cab1, caw2, cab2, p1);
    k_conv2<<<dim3(4,4,128), dim3(16,16)>>>(p1, c2w, c2b, r2);
    k_pool2<<<4096,256>>>(r2, p2);
    k_conv3<<<dim3(2,2,128), dim3(16,16)>>>(p2, c3w, c3b, r3);
    k_pool3<<<2048,256>>>(r3, p3);
    k_conv4<<<dim3(128,2), dim3(16,16)>>>(p3, c4w, c4b, r4);
    k_conv5<<<128,256>>>(r4, c5w, c5b, r5);
    k_mambah<<<128,512,smem_mh>>>(r5, mlng, mlnb, minw, mcw, mcb, mxp,
                                  mdtw, mdtb, mal, mD, mow, pw, pb, fg, fb, out);
}